// round 3
// baseline (speedup 1.0000x reference)
#include <cuda_runtime.h>
#include <cstdint>

#define B_TOT 2048
#define N_WIN 64
#define C_DIM 192
#define KDIM 192
#define C3 576
#define HEADS 6
#define HDIM 32
#define SCALE_F 0.17677669529663687f

// scratch: QKV pre-conv t, conv output c, attention output a
__device__ float g_t[(size_t)B_TOT * N_WIN * C3];
__device__ float g_c[(size_t)B_TOT * N_WIN * C3];
__device__ float g_a[(size_t)B_TOT * N_WIN * C_DIM];

// ------------------------------- helpers ----------------------------------
__device__ __forceinline__ uint32_t f2tf32(float x) {
  uint32_t r;
  asm("cvt.rna.tf32.f32 %0, %1;" : "=r"(r) : "f"(x));
  return r;
}

typedef unsigned long long ull;

__device__ __forceinline__ ull pk(float x, float y) {
  ull r;
  asm("mov.b64 %0, {%1, %2};" : "=l"(r) : "f"(x), "f"(y));
  return r;
}
__device__ __forceinline__ float2 upk(ull v) {
  float2 r;
  asm("mov.b64 {%0, %1}, %2;" : "=f"(r.x), "=f"(r.y) : "l"(v));
  return r;
}
__device__ __forceinline__ void fma2(ull& d, ull a, ull b) {
  asm("fma.rn.f32x2 %0, %1, %2, %3;" : "=l"(d) : "l"(a), "l"(b), "l"(d));
}
__device__ __forceinline__ ull mul2(ull a, ull b) {
  ull d;
  asm("mul.rn.f32x2 %0, %1, %2;" : "=l"(d) : "l"(a), "l"(b));
  return d;
}
__device__ __forceinline__ ull add2(ull a, ull b) {
  ull d;
  asm("add.rn.f32x2 %0, %1, %2;" : "=l"(d) : "l"(a), "l"(b));
  return d;
}

__device__ __forceinline__ void mbar_init(uint32_t mbar, int cnt) {
  asm volatile("mbarrier.init.shared.b64 [%0], %1;" ::"r"(mbar), "r"(cnt)
               : "memory");
}
__device__ __forceinline__ void mbar_expect_tx(uint32_t mbar, uint32_t bytes) {
  asm volatile("mbarrier.arrive.expect_tx.shared.b64 _, [%0], %1;" ::"r"(mbar),
               "r"(bytes)
               : "memory");
}
__device__ __forceinline__ void bulk_g2s(uint32_t dst, const void* src,
                                         uint32_t bytes, uint32_t mbar) {
  asm volatile(
      "cp.async.bulk.shared::cta.global.mbarrier::complete_tx::bytes "
      "[%0], [%1], %2, [%3];" ::"r"(dst),
      "l"(src), "r"(bytes), "r"(mbar)
      : "memory");
}
__device__ __forceinline__ void mbar_wait0(uint32_t mbar) {
  asm volatile(
      "{\n\t.reg .pred P;\n"
      "W_%=:\n\t"
      "mbarrier.try_wait.parity.acquire.cta.shared::cta.b64 P, [%0], 0;\n\t"
      "@!P bra W_%=;\n\t}" ::"r"(mbar)
      : "memory");
}

// ---------------------------------------------------------------------------
// tf32 tensor-core GEMM: out[m, n] = sum_k A[m, k] * W[n, k] + bias[n]
//   M = 131072, K = 192, N in {576, 192}. BM=128, BN=64, BK=16,
//   256 threads = 8 warps (4m x 2n), each warp 32x32 via 2x4 m16n8k8 tiles.
// ---------------------------------------------------------------------------
#define GBM 128
#define GBN 64
#define GBK 16
#define APITCH 136
#define BPITCH 68

__global__ __launch_bounds__(256) void tf32_gemm_kernel(
    const float* __restrict__ A, const float* __restrict__ W,
    const float* __restrict__ bias, float* __restrict__ out, int Ncols) {
  __shared__ uint32_t As[GBK][APITCH];
  __shared__ uint32_t Bs[GBK][BPITCH];

  const int tid = threadIdx.x;
  const int m0 = blockIdx.y * GBM;
  const int n0 = blockIdx.x * GBN;
  const int wid = tid >> 5, lane = tid & 31;
  const int wm = (wid & 3) * 32;
  const int wn = (wid >> 2) * 32;
  const int g = lane >> 2, tg = lane & 3;

  float acc[2][4][4];
#pragma unroll
  for (int i = 0; i < 2; i++)
#pragma unroll
    for (int j = 0; j < 4; j++)
#pragma unroll
      for (int r = 0; r < 4; r++) acc[i][j][r] = 0.f;

  const int am = tid >> 1;
  const int ak = (tid & 1) * 8;
  const int bn = tid >> 2;
  const int bk = (tid & 3) * 4;

  const float* pa = A + (size_t)(m0 + am) * KDIM + ak;
  const float* pb = W + (size_t)(n0 + bn) * KDIM + bk;

  // prologue prefetch
  float4 a0 = *reinterpret_cast<const float4*>(pa);
  float4 a1 = *reinterpret_cast<const float4*>(pa + 4);
  float4 b0v = *reinterpret_cast<const float4*>(pb);

  for (int k0 = 0; k0 < KDIM; k0 += GBK) {
    As[ak + 0][am] = f2tf32(a0.x); As[ak + 1][am] = f2tf32(a0.y);
    As[ak + 2][am] = f2tf32(a0.z); As[ak + 3][am] = f2tf32(a0.w);
    As[ak + 4][am] = f2tf32(a1.x); As[ak + 5][am] = f2tf32(a1.y);
    As[ak + 6][am] = f2tf32(a1.z); As[ak + 7][am] = f2tf32(a1.w);
    Bs[bk + 0][bn] = f2tf32(b0v.x); Bs[bk + 1][bn] = f2tf32(b0v.y);
    Bs[bk + 2][bn] = f2tf32(b0v.z); Bs[bk + 3][bn] = f2tf32(b0v.w);
    __syncthreads();

    if (k0 + GBK < KDIM) {  // prefetch next tile; overlaps with MMAs below
      a0 = *reinterpret_cast<const float4*>(pa + k0 + GBK);
      a1 = *reinterpret_cast<const float4*>(pa + k0 + GBK + 4);
      b0v = *reinterpret_cast<const float4*>(pb + k0 + GBK);
    }

#pragma unroll
    for (int ks = 0; ks < GBK; ks += 8) {
      uint32_t af[2][4], bf[4][2];
#pragma unroll
      for (int mt = 0; mt < 2; mt++) {
        int m = wm + mt * 16 + g;
        af[mt][0] = As[ks + tg][m];
        af[mt][1] = As[ks + tg][m + 8];
        af[mt][2] = As[ks + tg + 4][m];
        af[mt][3] = As[ks + tg + 4][m + 8];
      }
#pragma unroll
      for (int nt = 0; nt < 4; nt++) {
        int nn = wn + nt * 8 + g;
        bf[nt][0] = Bs[ks + tg][nn];
        bf[nt][1] = Bs[ks + tg + 4][nn];
      }
#pragma unroll
      for (int mt = 0; mt < 2; mt++)
#pragma unroll
        for (int nt = 0; nt < 4; nt++) {
          asm volatile(
              "mma.sync.aligned.m16n8k8.row.col.f32.tf32.tf32.f32 "
              "{%0,%1,%2,%3}, {%4,%5,%6,%7}, {%8,%9}, {%0,%1,%2,%3};"
              : "+f"(acc[mt][nt][0]), "+f"(acc[mt][nt][1]),
                "+f"(acc[mt][nt][2]), "+f"(acc[mt][nt][3])
              : "r"(af[mt][0]), "r"(af[mt][1]), "r"(af[mt][2]),
                "r"(af[mt][3]), "r"(bf[nt][0]), "r"(bf[nt][1]));
        }
    }
    __syncthreads();
  }

#pragma unroll
  for (int mt = 0; mt < 2; mt++) {
#pragma unroll
    for (int nt = 0; nt < 4; nt++) {
      int row = m0 + wm + mt * 16 + g;
      int col = n0 + wn + nt * 8 + 2 * tg;
      float2 bv = *reinterpret_cast<const float2*>(bias + col);
      float2 v0, v1;
      v0.x = acc[mt][nt][0] + bv.x; v0.y = acc[mt][nt][1] + bv.y;
      v1.x = acc[mt][nt][2] + bv.x; v1.y = acc[mt][nt][3] + bv.y;
      *reinterpret_cast<float2*>(out + (size_t)row * Ncols + col) = v0;
      *reinterpret_cast<float2*>(out + (size_t)(row + 8) * Ncols + col) = v1;
    }
  }
}

// ---------------------------------------------------------------------------
// Depthwise 3x3 conv over the (2048, 64) grid, tiled in smem.
//   grid = (576/32, 2048/16) = (18, 128); 512 threads.
//   smem: s[18 windows][64 n][32 ch] = 147456 B (16 output windows + 2 halo)
// ---------------------------------------------------------------------------
#define CW 32
#define WB 16

__global__ __launch_bounds__(512, 1) void conv_kernel(
    const float* __restrict__ dw_w, const float* __restrict__ dw_b) {
  extern __shared__ float s[];
  const int tid = threadIdx.x;
  const int c0 = blockIdx.x * CW;
  const int b0 = blockIdx.y * WB;

  // -------- load 18 windows x 64 rows x 32 ch (float4, coalesced) ---------
  for (int i = tid; i < 18 * 64 * 8; i += 512) {
    int w = i >> 9;
    int n = (i & 511) >> 3;
    int f = i & 7;
    int gw = b0 - 1 + w;
    float4 v = make_float4(0.f, 0.f, 0.f, 0.f);
    if ((unsigned)gw < (unsigned)B_TOT)
      v = *reinterpret_cast<const float4*>(
          g_t + ((size_t)gw * 64 + n) * C3 + c0 + f * 4);
    *reinterpret_cast<float4*>(s + ((w * 64 + n) << 5) + f * 4) = v;
  }
  __syncthreads();

  // -------- compute: thread = (c-pair, out-window, n-half) ----------------
  const int cp = tid & 15;
  const int wo = (tid >> 4) & 15;
  const int nh = tid >> 8;
  const int nst = nh << 5;
  const int lw = wo + 1;
  const int gb = b0 + wo;
  const int c = c0 + 2 * cp;

  ull w2[9];
#pragma unroll
  for (int t = 0; t < 9; t++)
    w2[t] = pk(__ldg(dw_w + c * 9 + t), __ldg(dw_w + c * 9 + 9 + t));
  ull bia2 = pk(__ldg(dw_b + c), __ldg(dw_b + c + 1));

  const float* rowp[3];
#pragma unroll
  for (int r = 0; r < 3; r++) rowp[r] = s + (((lw - 1 + r) * 64) << 5) + 2 * cp;

  ull xm[3], x0[3];
#pragma unroll
  for (int r = 0; r < 3; r++) {
    xm[r] = (nst > 0)
                ? *reinterpret_cast<const ull*>(rowp[r] + ((nst - 1) << 5))
                : 0ull;
    x0[r] = *reinterpret_cast<const ull*>(rowp[r] + (nst << 5));
  }
  float* outp = g_c + ((size_t)gb * 64 + nst) * C3 + c;
#pragma unroll 4
  for (int n = nst; n < nst + 32; n++) {
    ull xp[3];
#pragma unroll
    for (int r = 0; r < 3; r++)
      xp[r] = (n + 1 < 64)
                  ? *reinterpret_cast<const ull*>(rowp[r] + ((n + 1) << 5))
                  : 0ull;
    ull s0 = mul2(xm[0], w2[0]);
    fma2(s0, x0[0], w2[1]); fma2(s0, xp[0], w2[2]);
    ull s1 = mul2(xm[1], w2[3]);
    fma2(s1, x0[1], w2[4]); fma2(s1, xp[1], w2[5]);
    ull s2 = mul2(xm[2], w2[6]);
    fma2(s2, x0[2], w2[7]); fma2(s2, xp[2], w2[8]);
    ull sv = add2(add2(s0, s1), add2(s2, bia2));
    *reinterpret_cast<float2*>(outp) = upk(sv);
    outp += C3;
#pragma unroll
    for (int r = 0; r < 3; r++) { xm[r] = x0[r]; x0[r] = xp[r]; }
  }
}

// ---------------------------------------------------------------------------
// Flash window attention. One block per window, 384 threads.
//   K/V/Q tile loaded via cp.async.bulk (TMA); smem 64 x 580 + mbar.
// ---------------------------------------------------------------------------
#define TPITCH 580
#define ATT_SMEM (64 * TPITCH * 4 + 16)

__global__ __launch_bounds__(384, 1) void attn_kernel(
    const float* __restrict__ mask, const float* __restrict__ rpb,
    const int* __restrict__ rel_idx, float* __restrict__ ga) {
  extern __shared__ float sm[];
  float* temp = sm;  // conv output (64 x 576, pitch 580)
  const int tid = threadIdx.x;
  const int b = blockIdx.x;

  uint32_t mbar =
      (uint32_t)__cvta_generic_to_shared(sm + 64 * TPITCH);

  if (tid == 0) mbar_init(mbar, 1);
  __syncthreads();
  if (tid == 0) {
    asm volatile("fence.proxy.async.shared::cta;" ::: "memory");
    mbar_expect_tx(mbar, 64 * C3 * 4);
    uint32_t dst = (uint32_t)__cvta_generic_to_shared(temp);
    const float* src = g_c + (size_t)b * 64 * C3;
#pragma unroll 4
    for (int n = 0; n < 64; n++)
      bulk_g2s(dst + n * (TPITCH * 4), src + (size_t)n * C3, C3 * 4, mbar);
  }
  mbar_wait0(mbar);

  // -------- attention: 12 warps = 6 heads x 2 query-halves ----------------
  const int w = tid >> 5, lane = tid & 31;
  const int h = w >> 1;
  const int n = ((w & 1) << 5) | lane;

  const float2* tq =
      reinterpret_cast<const float2*>(temp + n * TPITCH + h * HDIM);
  ull q2[16];
#pragma unroll
  for (int d = 0; d < 16; d++) {
    float2 v = tq[d];
    q2[d] = pk(v.x * SCALE_F, v.y * SCALE_F);
  }

  const int* ri = rel_idx + n * 64;
  const float* mrow = mask + (size_t)(b & 63) * 4096 + n * 64;

  float rmax = -1e30f, rsum = 0.f;
  ull acc2[16];
#pragma unroll
  for (int d = 0; d < 16; d++) acc2[d] = 0ull;

#pragma unroll
  for (int mt = 0; mt < 64; mt += 16) {
    float s[16];
#pragma unroll
    for (int j = 0; j < 16; j++) {
      const ulonglong2* tk = reinterpret_cast<const ulonglong2*>(
          temp + (mt + j) * TPITCH + 192 + h * HDIM);
      ull dp[4] = {0ull, 0ull, 0ull, 0ull};
#pragma unroll
      for (int d8 = 0; d8 < 8; d8++) {
        ulonglong2 kv = tk[d8];
        fma2(dp[(2 * d8) & 3], q2[2 * d8], kv.x);
        fma2(dp[(2 * d8 + 1) & 3], q2[2 * d8 + 1], kv.y);
      }
      float2 f = upk(add2(add2(dp[0], dp[1]), add2(dp[2], dp[3])));
      s[j] = f.x + f.y + __ldg(rpb + __ldg(ri + mt + j) * 6 + h) +
             __ldg(mrow + mt + j);
    }
    float tmax = rmax;
#pragma unroll
    for (int j = 0; j < 16; j++) tmax = fmaxf(tmax, s[j]);
    float corr = __expf(rmax - tmax);
    rsum *= corr;
    ull corr2 = pk(corr, corr);
#pragma unroll
    for (int d = 0; d < 16; d++) acc2[d] = mul2(acc2[d], corr2);
#pragma unroll
    for (int j = 0; j < 16; j++) {
      float p = __expf(s[j] - tmax);
      rsum += p;
      ull p2 = pk(p, p);
      const ulonglong2* tv = reinterpret_cast<const ulonglong2*>(
          temp + (mt + j) * TPITCH + 384 + h * HDIM);
#pragma unroll
      for (int d8 = 0; d8 < 8; d8++) {
        ulonglong2 vv = tv[d8];
        fma2(acc2[2 * d8], p2, vv.x);
        fma2(acc2[2 * d8 + 1], p2, vv.y);
      }
    }
    rmax = tmax;
  }
  float inv = 1.f / rsum;
  float2* po =
      reinterpret_cast<float2*>(ga + ((size_t)b * 64 + n) * C_DIM + h * HDIM);
#pragma unroll
  for (int d = 0; d < 16; d++) {
    float2 v = upk(acc2[d]);
    v.x *= inv; v.y *= inv;
    po[d] = v;
  }
}

// ---------------------------------------------------------------------------
extern "C" void kernel_launch(void* const* d_in, const int* in_sizes, int n_in,
                              void* d_out, int out_size) {
  const float* x      = (const float*)d_in[0];
  const float* mask   = (const float*)d_in[1];
  const float* qkv_w  = (const float*)d_in[2];
  const float* qkv_b  = (const float*)d_in[3];
  const float* dw_w   = (const float*)d_in[4];
  const float* dw_b   = (const float*)d_in[5];
  const float* rpb    = (const float*)d_in[6];
  const int*   rel    = (const int*)d_in[7];
  const float* proj_w = (const float*)d_in[8];
  const float* proj_b = (const float*)d_in[9];
  float* out = (float*)d_out;

  float* gt_ptr = nullptr;
  float* ga_ptr = nullptr;
  cudaGetSymbolAddress((void**)&gt_ptr, g_t);
  cudaGetSymbolAddress((void**)&ga_ptr, g_a);

  // 1) QKV GEMM (tf32): g_t = x @ qkv_w^T + qkv_b
  dim3 g1(C3 / GBN, (B_TOT * N_WIN) / GBM);  // (9, 1024)
  tf32_gemm_kernel<<<g1, 256>>>(x, qkv_w, qkv_b, gt_ptr, C3);

  // 2) depthwise conv: g_c = dwconv3x3(g_t)
  const int conv_smem = 18 * 64 * CW * 4;  // 147456
  cudaFuncSetAttribute(conv_kernel,
                       cudaFuncAttributeMaxDynamicSharedMemorySize, conv_smem);
  dim3 g2(C3 / CW, B_TOT / WB);  // (18, 128)
  conv_kernel<<<g2, 512, conv_smem>>>(dw_w, dw_b);

  // 3) window attention: g_a
  cudaFuncSetAttribute(attn_kernel,
                       cudaFuncAttributeMaxDynamicSharedMemorySize, ATT_SMEM);
  attn_kernel<<<B_TOT, 384, ATT_SMEM>>>(mask, rpb, rel, ga_ptr);

  // 4) projection GEMM (tf32): out = g_a @ proj_w^T + proj_b
  dim3 g3(C_DIM / GBN, (B_TOT * N_WIN) / GBM);  // (3, 1024)
  tf32_gemm_kernel<<<g3, 256>>>(ga_ptr, proj_w, proj_b, out, C_DIM);
}

// round 4
// speedup vs baseline: 1.0404x; 1.0404x over previous
#include <cuda_runtime.h>
#include <cstdint>

#define B_TOT 2048
#define N_WIN 64
#define C_DIM 192
#define KDIM 192
#define C3 576
#define HEADS 6
#define HDIM 32
#define SCALE_F 0.17677669529663687f

// scratch: QKV pre-conv t, conv output c, attention output a
__device__ float g_t[(size_t)B_TOT * N_WIN * C3];
__device__ float g_c[(size_t)B_TOT * N_WIN * C3];
__device__ float g_a[(size_t)B_TOT * N_WIN * C_DIM];

// ------------------------------- helpers ----------------------------------
__device__ __forceinline__ uint32_t f2tf32(float x) {
  uint32_t r;
  asm("cvt.rna.tf32.f32 %0, %1;" : "=r"(r) : "f"(x));
  return r;
}

typedef unsigned long long ull;

__device__ __forceinline__ ull pk(float x, float y) {
  ull r;
  asm("mov.b64 %0, {%1, %2};" : "=l"(r) : "f"(x), "f"(y));
  return r;
}
__device__ __forceinline__ float2 upk(ull v) {
  float2 r;
  asm("mov.b64 {%0, %1}, %2;" : "=f"(r.x), "=f"(r.y) : "l"(v));
  return r;
}
__device__ __forceinline__ void fma2(ull& d, ull a, ull b) {
  asm("fma.rn.f32x2 %0, %1, %2, %3;" : "=l"(d) : "l"(a), "l"(b), "l"(d));
}
__device__ __forceinline__ ull mul2(ull a, ull b) {
  ull d;
  asm("mul.rn.f32x2 %0, %1, %2;" : "=l"(d) : "l"(a), "l"(b));
  return d;
}
__device__ __forceinline__ ull add2(ull a, ull b) {
  ull d;
  asm("add.rn.f32x2 %0, %1, %2;" : "=l"(d) : "l"(a), "l"(b));
  return d;
}

// ---------------------------------------------------------------------------
// tf32 tensor-core GEMM: out[m, n] = sum_k A[m, k] * W[n, k] + bias[n]
//   M = 131072, K = 192, N in {576, 192}. BM=128, BN=64, BK=16, 256 thr,
//   8 warps (4m x 2n), warp 32x32 via 2x4 m16n8k8.
//   Double-buffered smem; paired layouts -> all fragment loads are LDS.64.
// ---------------------------------------------------------------------------
#define GBM 128
#define GBN 64
#define GBK 16
#define AP 136  // A k-row pitch (words); 136 % 32 == 8 -> conflict-free LDS.64
#define BP 136  // B pair-row pitch (words)

__device__ __forceinline__ void mma_step(const uint32_t* __restrict__ Asb,
                                         const uint32_t* __restrict__ Bsb,
                                         int wm, int wn, int g, int tg,
                                         float acc[2][4][4]) {
#pragma unroll
  for (int ks = 0; ks < GBK; ks += 8) {
    uint32_t af[2][4], bf[4][2];
#pragma unroll
    for (int mt = 0; mt < 2; mt++) {
      // A pair layout: word = k*AP + (m & ~15) + 2*(m&7) + ((m>>3)&1)
      const uint32_t* a0p = Asb + (ks + tg) * AP + wm + mt * 16 + 2 * g;
      const uint32_t* a1p = a0p + 4 * AP;
      ull v01 = *reinterpret_cast<const ull*>(a0p);
      ull v23 = *reinterpret_cast<const ull*>(a1p);
      af[mt][0] = (uint32_t)v01; af[mt][1] = (uint32_t)(v01 >> 32);
      af[mt][2] = (uint32_t)v23; af[mt][3] = (uint32_t)(v23 >> 32);
    }
#pragma unroll
    for (int nt = 0; nt < 4; nt++) {
      // B pair layout: word = ((k>>3)*4 + (k&3))*BP + 2*n + ((k>>2)&1)
      int nn = wn + nt * 8 + g;
      const uint32_t* bp = Bsb + ((ks >> 3) * 4 + tg) * BP + 2 * nn;
      ull v = *reinterpret_cast<const ull*>(bp);
      bf[nt][0] = (uint32_t)v; bf[nt][1] = (uint32_t)(v >> 32);
    }
#pragma unroll
    for (int mt = 0; mt < 2; mt++)
#pragma unroll
      for (int nt = 0; nt < 4; nt++) {
        asm volatile(
            "mma.sync.aligned.m16n8k8.row.col.f32.tf32.tf32.f32 "
            "{%0,%1,%2,%3}, {%4,%5,%6,%7}, {%8,%9}, {%0,%1,%2,%3};"
            : "+f"(acc[mt][nt][0]), "+f"(acc[mt][nt][1]),
              "+f"(acc[mt][nt][2]), "+f"(acc[mt][nt][3])
            : "r"(af[mt][0]), "r"(af[mt][1]), "r"(af[mt][2]),
              "r"(af[mt][3]), "r"(bf[nt][0]), "r"(bf[nt][1]));
      }
  }
}

__global__ __launch_bounds__(256) void tf32_gemm_kernel(
    const float* __restrict__ A, const float* __restrict__ W,
    const float* __restrict__ bias, float* __restrict__ out, int Ncols) {
  __shared__ uint32_t As[2][GBK * AP];
  __shared__ uint32_t Bs[2][8 * BP];

  const int tid = threadIdx.x;
  const int m0 = blockIdx.y * GBM;
  const int n0 = blockIdx.x * GBN;
  const int wid = tid >> 5, lane = tid & 31;
  const int wm = (wid & 3) * 32;
  const int wn = (wid >> 2) * 32;
  const int g = lane >> 2, tg = lane & 3;

  float acc[2][4][4];
#pragma unroll
  for (int i = 0; i < 2; i++)
#pragma unroll
    for (int j = 0; j < 4; j++)
#pragma unroll
      for (int r = 0; r < 4; r++) acc[i][j][r] = 0.f;

  const int am = tid >> 1;
  const int ak = (tid & 1) * 8;
  const int bn = tid >> 2;
  const int bk = (tid & 3) * 4;
  const int perm_am = (am & ~15) + ((am & 7) << 1) + ((am >> 3) & 1);
  const int bgrp = bk >> 3;
  const int bhalf = (bk >> 2) & 1;

  const float* pa = A + (size_t)(m0 + am) * KDIM + ak;
  const float* pb = W + (size_t)(n0 + bn) * KDIM + bk;

  // prologue: tile 0 -> stage 0
  {
    float4 a0 = *reinterpret_cast<const float4*>(pa);
    float4 a1 = *reinterpret_cast<const float4*>(pa + 4);
    float4 bv = *reinterpret_cast<const float4*>(pb);
    uint32_t* ap = &As[0][perm_am];
    ap[(ak + 0) * AP] = f2tf32(a0.x); ap[(ak + 1) * AP] = f2tf32(a0.y);
    ap[(ak + 2) * AP] = f2tf32(a0.z); ap[(ak + 3) * AP] = f2tf32(a0.w);
    ap[(ak + 4) * AP] = f2tf32(a1.x); ap[(ak + 5) * AP] = f2tf32(a1.y);
    ap[(ak + 6) * AP] = f2tf32(a1.z); ap[(ak + 7) * AP] = f2tf32(a1.w);
    uint32_t* bpp = &Bs[0][2 * bn + bhalf];
    bpp[(bgrp * 4 + 0) * BP] = f2tf32(bv.x);
    bpp[(bgrp * 4 + 1) * BP] = f2tf32(bv.y);
    bpp[(bgrp * 4 + 2) * BP] = f2tf32(bv.z);
    bpp[(bgrp * 4 + 3) * BP] = f2tf32(bv.w);
  }
  __syncthreads();

#pragma unroll
  for (int k0 = 0; k0 < KDIM; k0 += 32) {
    // ---- stage 0 holds tile k0; prefetch k0+16 (always valid) ----
    {
      float4 a0 = *reinterpret_cast<const float4*>(pa + k0 + 16);
      float4 a1 = *reinterpret_cast<const float4*>(pa + k0 + 20);
      float4 bv = *reinterpret_cast<const float4*>(pb + k0 + 16);
      mma_step(As[0], Bs[0], wm, wn, g, tg, acc);
      uint32_t* ap = &As[1][perm_am];
      ap[(ak + 0) * AP] = f2tf32(a0.x); ap[(ak + 1) * AP] = f2tf32(a0.y);
      ap[(ak + 2) * AP] = f2tf32(a0.z); ap[(ak + 3) * AP] = f2tf32(a0.w);
      ap[(ak + 4) * AP] = f2tf32(a1.x); ap[(ak + 5) * AP] = f2tf32(a1.y);
      ap[(ak + 6) * AP] = f2tf32(a1.z); ap[(ak + 7) * AP] = f2tf32(a1.w);
      uint32_t* bpp = &Bs[1][2 * bn + bhalf];
      bpp[(bgrp * 4 + 0) * BP] = f2tf32(bv.x);
      bpp[(bgrp * 4 + 1) * BP] = f2tf32(bv.y);
      bpp[(bgrp * 4 + 2) * BP] = f2tf32(bv.z);
      bpp[(bgrp * 4 + 3) * BP] = f2tf32(bv.w);
    }
    __syncthreads();
    // ---- stage 1 holds tile k0+16; prefetch k0+32 if any ----
    {
      float4 a0, a1, bv;
      bool more = (k0 + 32 < KDIM);
      if (more) {
        a0 = *reinterpret_cast<const float4*>(pa + k0 + 32);
        a1 = *reinterpret_cast<const float4*>(pa + k0 + 36);
        bv = *reinterpret_cast<const float4*>(pb + k0 + 32);
      }
      mma_step(As[1], Bs[1], wm, wn, g, tg, acc);
      if (more) {
        uint32_t* ap = &As[0][perm_am];
        ap[(ak + 0) * AP] = f2tf32(a0.x); ap[(ak + 1) * AP] = f2tf32(a0.y);
        ap[(ak + 2) * AP] = f2tf32(a0.z); ap[(ak + 3) * AP] = f2tf32(a0.w);
        ap[(ak + 4) * AP] = f2tf32(a1.x); ap[(ak + 5) * AP] = f2tf32(a1.y);
        ap[(ak + 6) * AP] = f2tf32(a1.z); ap[(ak + 7) * AP] = f2tf32(a1.w);
        uint32_t* bpp = &Bs[0][2 * bn + bhalf];
        bpp[(bgrp * 4 + 0) * BP] = f2tf32(bv.x);
        bpp[(bgrp * 4 + 1) * BP] = f2tf32(bv.y);
        bpp[(bgrp * 4 + 2) * BP] = f2tf32(bv.z);
        bpp[(bgrp * 4 + 3) * BP] = f2tf32(bv.w);
      }
    }
    __syncthreads();
  }

  // epilogue (+bias)
#pragma unroll
  for (int mt = 0; mt < 2; mt++) {
#pragma unroll
    for (int nt = 0; nt < 4; nt++) {
      int row = m0 + wm + mt * 16 + g;
      int col = n0 + wn + nt * 8 + 2 * tg;
      float2 bv = *reinterpret_cast<const float2*>(bias + col);
      float2 v0, v1;
      v0.x = acc[mt][nt][0] + bv.x; v0.y = acc[mt][nt][1] + bv.y;
      v1.x = acc[mt][nt][2] + bv.x; v1.y = acc[mt][nt][3] + bv.y;
      *reinterpret_cast<float2*>(out + (size_t)row * Ncols + col) = v0;
      *reinterpret_cast<float2*>(out + (size_t)(row + 8) * Ncols + col) = v1;
    }
  }
}

// ---------------------------------------------------------------------------
// Depthwise 3x3 conv over the (2048, 64) grid, tiled in smem.
//   grid = (576/32, 2048/8) = (18, 256); 512 threads; 2 CTAs/SM.
//   smem: s[10 windows][64 n][32 ch] = 81920 B (8 output windows + 2 halo)
// ---------------------------------------------------------------------------
#define CW 32
#define WB 8

__global__ __launch_bounds__(512, 2) void conv_kernel(
    const float* __restrict__ dw_w, const float* __restrict__ dw_b) {
  extern __shared__ float s[];
  const int tid = threadIdx.x;
  const int c0 = blockIdx.x * CW;
  const int b0 = blockIdx.y * WB;

  // load (WB+2) windows x 64 rows x 32 ch (float4, coalesced)
#pragma unroll
  for (int rep = 0; rep < 10; rep++) {
    int i = tid + rep * 512;          // 0..5119
    int w = i >> 9;
    int n = (i & 511) >> 3;
    int f = (i & 7) << 2;
    int gw = b0 - 1 + w;
    float4 v = make_float4(0.f, 0.f, 0.f, 0.f);
    if ((unsigned)gw < (unsigned)B_TOT)
      v = *reinterpret_cast<const float4*>(
          g_t + ((size_t)gw * 64 + n) * C3 + c0 + f);
    *reinterpret_cast<float4*>(s + ((w * 64 + n) << 5) + f) = v;
  }
  __syncthreads();

  // compute: thread = (c-pair, out-window, n-quarter)
  const int cp = tid & 15;
  const int wo = (tid >> 4) & 7;
  const int nh = tid >> 7;          // 0..3
  const int nst = nh << 4;
  const int gb = b0 + wo;
  const int c = c0 + 2 * cp;

  ull w2[9];
#pragma unroll
  for (int t = 0; t < 9; t++)
    w2[t] = pk(__ldg(dw_w + c * 9 + t), __ldg(dw_w + c * 9 + 9 + t));
  ull bia2 = pk(__ldg(dw_b + c), __ldg(dw_b + c + 1));

  const float* rowp[3];
#pragma unroll
  for (int r = 0; r < 3; r++) rowp[r] = s + (((wo + r) * 64) << 5) + 2 * cp;

  ull xm[3], x0[3];
#pragma unroll
  for (int r = 0; r < 3; r++) {
    xm[r] = (nst > 0)
                ? *reinterpret_cast<const ull*>(rowp[r] + ((nst - 1) << 5))
                : 0ull;
    x0[r] = *reinterpret_cast<const ull*>(rowp[r] + (nst << 5));
  }
  float* outp = g_c + ((size_t)gb * 64 + nst) * C3 + c;
#pragma unroll 4
  for (int n = nst; n < nst + 16; n++) {
    ull xp[3];
#pragma unroll
    for (int r = 0; r < 3; r++)
      xp[r] = (n + 1 < 64)
                  ? *reinterpret_cast<const ull*>(rowp[r] + ((n + 1) << 5))
                  : 0ull;
    ull s0 = mul2(xm[0], w2[0]);
    fma2(s0, x0[0], w2[1]); fma2(s0, xp[0], w2[2]);
    ull s1 = mul2(xm[1], w2[3]);
    fma2(s1, x0[1], w2[4]); fma2(s1, xp[1], w2[5]);
    ull s2 = mul2(xm[2], w2[6]);
    fma2(s2, x0[2], w2[7]); fma2(s2, xp[2], w2[8]);
    ull sv = add2(add2(s0, s1), add2(s2, bia2));
    *reinterpret_cast<float2*>(outp) = upk(sv);
    outp += C3;
#pragma unroll
    for (int r = 0; r < 3; r++) { xm[r] = x0[r]; x0[r] = xp[r]; }
  }
}

// ---------------------------------------------------------------------------
// Flash window attention. One block per window, 384 threads, 2 CTAs/SM.
//   smem holds only K/V (64 x 384, pitch 392 = 100352 B); Q read from L2.
// ---------------------------------------------------------------------------
#define KVP 392
#define ATT_SMEM (64 * KVP * 4)

__global__ __launch_bounds__(384, 2) void attn_kernel(
    const float* __restrict__ mask, const float* __restrict__ rpb,
    const int* __restrict__ rel_idx, float* __restrict__ ga) {
  extern __shared__ float kv[];  // row n: K at [0..191], V at [192..383]
  const int tid = threadIdx.x;
  const int b = blockIdx.x;

  // cooperative K/V load: 64 rows x 96 float4
  {
    const float* src = g_c + (size_t)b * 64 * C3 + 192;
#pragma unroll
    for (int rep = 0; rep < 16; rep++) {
      int i = tid + rep * 384;   // 0..6143
      int n = i / 96;
      int f = (i - n * 96) << 2;
      *reinterpret_cast<float4*>(kv + n * KVP + f) =
          *reinterpret_cast<const float4*>(src + (size_t)n * C3 + f);
    }
  }
  __syncthreads();

  // 12 warps = 6 heads x 2 query-halves
  const int w = tid >> 5, lane = tid & 31;
  const int h = w >> 1;
  const int n = ((w & 1) << 5) | lane;

  // Q from global (L2-hot)
  ull q2[16];
  {
    const float2* qp = reinterpret_cast<const float2*>(
        g_c + ((size_t)b * 64 + n) * C3 + h * HDIM);
#pragma unroll
    for (int d = 0; d < 16; d++) {
      float2 v = qp[d];
      q2[d] = pk(v.x * SCALE_F, v.y * SCALE_F);
    }
  }

  const int* ri = rel_idx + n * 64;
  const float* mrow = mask + (size_t)(b & 63) * 4096 + n * 64;

  float rmax = -1e30f, rsum = 0.f;
  ull acc2[16];
#pragma unroll
  for (int d = 0; d < 16; d++) acc2[d] = 0ull;

#pragma unroll 2
  for (int mt = 0; mt < 64; mt += 8) {
    float s[8];
#pragma unroll
    for (int j = 0; j < 8; j++) {
      const ulonglong2* tk = reinterpret_cast<const ulonglong2*>(
          kv + (mt + j) * KVP + h * HDIM);
      ull dp[4] = {0ull, 0ull, 0ull, 0ull};
#pragma unroll
      for (int d8 = 0; d8 < 8; d8++) {
        ulonglong2 kvv = tk[d8];
        fma2(dp[(2 * d8) & 3], q2[2 * d8], kvv.x);
        fma2(dp[(2 * d8 + 1) & 3], q2[2 * d8 + 1], kvv.y);
      }
      float2 f = upk(add2(add2(dp[0], dp[1]), add2(dp[2], dp[3])));
      s[j] = f.x + f.y + __ldg(rpb + __ldg(ri + mt + j) * 6 + h) +
             __ldg(mrow + mt + j);
    }
    float tmax = rmax;
#pragma unroll
    for (int j = 0; j < 8; j++) tmax = fmaxf(tmax, s[j]);
    float corr = __expf(rmax - tmax);
    rsum *= corr;
    ull corr2 = pk(corr, corr);
#pragma unroll
    for (int d = 0; d < 16; d++) acc2[d] = mul2(acc2[d], corr2);
#pragma unroll
    for (int j = 0; j < 8; j++) {
      float p = __expf(s[j] - tmax);
      rsum += p;
      ull p2 = pk(p, p);
      const ulonglong2* tv = reinterpret_cast<const ulonglong2*>(
          kv + (mt + j) * KVP + 192 + h * HDIM);
#pragma unroll
      for (int d8 = 0; d8 < 8; d8++) {
        ulonglong2 vv = tv[d8];
        fma2(acc2[2 * d8], p2, vv.x);
        fma2(acc2[2 * d8 + 1], p2, vv.y);
      }
    }
    rmax = tmax;
  }
  float inv = 1.f / rsum;
  float2* po =
      reinterpret_cast<float2*>(ga + ((size_t)b * 64 + n) * C_DIM + h * HDIM);
#pragma unroll
  for (int d = 0; d < 16; d++) {
    float2 v = upk(acc2[d]);
    v.x *= inv; v.y *= inv;
    po[d] = v;
  }
}

// ---------------------------------------------------------------------------
extern "C" void kernel_launch(void* const* d_in, const int* in_sizes, int n_in,
                              void* d_out, int out_size) {
  const float* x      = (const float*)d_in[0];
  const float* mask   = (const float*)d_in[1];
  const float* qkv_w  = (const float*)d_in[2];
  const float* qkv_b  = (const float*)d_in[3];
  const float* dw_w   = (const float*)d_in[4];
  const float* dw_b   = (const float*)d_in[5];
  const float* rpb    = (const float*)d_in[6];
  const int*   rel    = (const int*)d_in[7];
  const float* proj_w = (const float*)d_in[8];
  const float* proj_b = (const float*)d_in[9];
  float* out = (float*)d_out;

  float* gt_ptr = nullptr;
  float* ga_ptr = nullptr;
  cudaGetSymbolAddress((void**)&gt_ptr, g_t);
  cudaGetSymbolAddress((void**)&ga_ptr, g_a);

  // 1) QKV GEMM (tf32): g_t = x @ qkv_w^T + qkv_b
  dim3 g1(C3 / GBN, (B_TOT * N_WIN) / GBM);  // (9, 1024)
  tf32_gemm_kernel<<<g1, 256>>>(x, qkv_w, qkv_b, gt_ptr, C3);

  // 2) depthwise conv: g_c = dwconv3x3(g_t)
  const int conv_smem = 10 * 64 * CW * 4;  // 81920
  cudaFuncSetAttribute(conv_kernel,
                       cudaFuncAttributeMaxDynamicSharedMemorySize, conv_smem);
  dim3 g2(C3 / CW, B_TOT / WB);  // (18, 256)
  conv_kernel<<<g2, 512, conv_smem>>>(dw_w, dw_b);

  // 3) window attention: g_a
  cudaFuncSetAttribute(attn_kernel,
                       cudaFuncAttributeMaxDynamicSharedMemorySize, ATT_SMEM);
  attn_kernel<<<B_TOT, 384, ATT_SMEM>>>(mask, rpb, rel, ga_ptr);

  // 4) projection GEMM (tf32): out = g_a @ proj_w^T + proj_b
  dim3 g3(C_DIM / GBN, (B_TOT * N_WIN) / GBM);  // (3, 1024)
  tf32_gemm_kernel<<<g3, 256>>>(ga_ptr, proj_w, proj_b, out, C_DIM);
}

// round 5
// speedup vs baseline: 1.1882x; 1.1421x over previous
#include <cuda_runtime.h>
#include <cstdint>

#define B_TOT 2048
#define N_WIN 64
#define C_DIM 192
#define KDIM 192
#define C3 576
#define HEADS 6
#define HDIM 32
#define SCALE_F 0.17677669529663687f

// scratch: QKV pre-conv t, conv output c, attention output a
__device__ float g_t[(size_t)B_TOT * N_WIN * C3];
__device__ float g_c[(size_t)B_TOT * N_WIN * C3];
__device__ float g_a[(size_t)B_TOT * N_WIN * C_DIM];

// ------------------------------- helpers ----------------------------------
__device__ __forceinline__ uint32_t f2tf32(float x) {
  uint32_t r;
  asm("cvt.rna.tf32.f32 %0, %1;" : "=r"(r) : "f"(x));
  return r;
}

typedef unsigned long long ull;

__device__ __forceinline__ ull pk(float x, float y) {
  ull r;
  asm("mov.b64 %0, {%1, %2};" : "=l"(r) : "f"(x), "f"(y));
  return r;
}
__device__ __forceinline__ float2 upk(ull v) {
  float2 r;
  asm("mov.b64 {%0, %1}, %2;" : "=f"(r.x), "=f"(r.y) : "l"(v));
  return r;
}
__device__ __forceinline__ void fma2(ull& d, ull a, ull b) {
  asm("fma.rn.f32x2 %0, %1, %2, %3;" : "=l"(d) : "l"(a), "l"(b), "l"(d));
}
__device__ __forceinline__ ull mul2(ull a, ull b) {
  ull d;
  asm("mul.rn.f32x2 %0, %1, %2;" : "=l"(d) : "l"(a), "l"(b));
  return d;
}
__device__ __forceinline__ ull add2(ull a, ull b) {
  ull d;
  asm("add.rn.f32x2 %0, %1, %2;" : "=l"(d) : "l"(a), "l"(b));
  return d;
}

// ---------------------------------------------------------------------------
// tf32 tensor-core GEMM: out[m, n] = sum_k A[m, k] * W[n, k] + bias[n]
//   (unchanged from round 4)
// ---------------------------------------------------------------------------
#define GBM 128
#define GBN 64
#define GBK 16
#define AP 136
#define BP 136

__device__ __forceinline__ void mma_step(const uint32_t* __restrict__ Asb,
                                         const uint32_t* __restrict__ Bsb,
                                         int wm, int wn, int g, int tg,
                                         float acc[2][4][4]) {
#pragma unroll
  for (int ks = 0; ks < GBK; ks += 8) {
    uint32_t af[2][4], bf[4][2];
#pragma unroll
    for (int mt = 0; mt < 2; mt++) {
      const uint32_t* a0p = Asb + (ks + tg) * AP + wm + mt * 16 + 2 * g;
      const uint32_t* a1p = a0p + 4 * AP;
      ull v01 = *reinterpret_cast<const ull*>(a0p);
      ull v23 = *reinterpret_cast<const ull*>(a1p);
      af[mt][0] = (uint32_t)v01; af[mt][1] = (uint32_t)(v01 >> 32);
      af[mt][2] = (uint32_t)v23; af[mt][3] = (uint32_t)(v23 >> 32);
    }
#pragma unroll
    for (int nt = 0; nt < 4; nt++) {
      int nn = wn + nt * 8 + g;
      const uint32_t* bp = Bsb + ((ks >> 3) * 4 + tg) * BP + 2 * nn;
      ull v = *reinterpret_cast<const ull*>(bp);
      bf[nt][0] = (uint32_t)v; bf[nt][1] = (uint32_t)(v >> 32);
    }
#pragma unroll
    for (int mt = 0; mt < 2; mt++)
#pragma unroll
      for (int nt = 0; nt < 4; nt++) {
        asm volatile(
            "mma.sync.aligned.m16n8k8.row.col.f32.tf32.tf32.f32 "
            "{%0,%1,%2,%3}, {%4,%5,%6,%7}, {%8,%9}, {%0,%1,%2,%3};"
            : "+f"(acc[mt][nt][0]), "+f"(acc[mt][nt][1]),
              "+f"(acc[mt][nt][2]), "+f"(acc[mt][nt][3])
            : "r"(af[mt][0]), "r"(af[mt][1]), "r"(af[mt][2]),
              "r"(af[mt][3]), "r"(bf[nt][0]), "r"(bf[nt][1]));
      }
  }
}

__global__ __launch_bounds__(256) void tf32_gemm_kernel(
    const float* __restrict__ A, const float* __restrict__ W,
    const float* __restrict__ bias, float* __restrict__ out, int Ncols) {
  __shared__ uint32_t As[2][GBK * AP];
  __shared__ uint32_t Bs[2][8 * BP];

  const int tid = threadIdx.x;
  const int m0 = blockIdx.y * GBM;
  const int n0 = blockIdx.x * GBN;
  const int wid = tid >> 5, lane = tid & 31;
  const int wm = (wid & 3) * 32;
  const int wn = (wid >> 2) * 32;
  const int g = lane >> 2, tg = lane & 3;

  float acc[2][4][4];
#pragma unroll
  for (int i = 0; i < 2; i++)
#pragma unroll
    for (int j = 0; j < 4; j++)
#pragma unroll
      for (int r = 0; r < 4; r++) acc[i][j][r] = 0.f;

  const int am = tid >> 1;
  const int ak = (tid & 1) * 8;
  const int bn = tid >> 2;
  const int bk = (tid & 3) * 4;
  const int perm_am = (am & ~15) + ((am & 7) << 1) + ((am >> 3) & 1);
  const int bgrp = bk >> 3;
  const int bhalf = (bk >> 2) & 1;

  const float* pa = A + (size_t)(m0 + am) * KDIM + ak;
  const float* pb = W + (size_t)(n0 + bn) * KDIM + bk;

  {
    float4 a0 = *reinterpret_cast<const float4*>(pa);
    float4 a1 = *reinterpret_cast<const float4*>(pa + 4);
    float4 bv = *reinterpret_cast<const float4*>(pb);
    uint32_t* ap = &As[0][perm_am];
    ap[(ak + 0) * AP] = f2tf32(a0.x); ap[(ak + 1) * AP] = f2tf32(a0.y);
    ap[(ak + 2) * AP] = f2tf32(a0.z); ap[(ak + 3) * AP] = f2tf32(a0.w);
    ap[(ak + 4) * AP] = f2tf32(a1.x); ap[(ak + 5) * AP] = f2tf32(a1.y);
    ap[(ak + 6) * AP] = f2tf32(a1.z); ap[(ak + 7) * AP] = f2tf32(a1.w);
    uint32_t* bpp = &Bs[0][2 * bn + bhalf];
    bpp[(bgrp * 4 + 0) * BP] = f2tf32(bv.x);
    bpp[(bgrp * 4 + 1) * BP] = f2tf32(bv.y);
    bpp[(bgrp * 4 + 2) * BP] = f2tf32(bv.z);
    bpp[(bgrp * 4 + 3) * BP] = f2tf32(bv.w);
  }
  __syncthreads();

#pragma unroll
  for (int k0 = 0; k0 < KDIM; k0 += 32) {
    {
      float4 a0 = *reinterpret_cast<const float4*>(pa + k0 + 16);
      float4 a1 = *reinterpret_cast<const float4*>(pa + k0 + 20);
      float4 bv = *reinterpret_cast<const float4*>(pb + k0 + 16);
      mma_step(As[0], Bs[0], wm, wn, g, tg, acc);
      uint32_t* ap = &As[1][perm_am];
      ap[(ak + 0) * AP] = f2tf32(a0.x); ap[(ak + 1) * AP] = f2tf32(a0.y);
      ap[(ak + 2) * AP] = f2tf32(a0.z); ap[(ak + 3) * AP] = f2tf32(a0.w);
      ap[(ak + 4) * AP] = f2tf32(a1.x); ap[(ak + 5) * AP] = f2tf32(a1.y);
      ap[(ak + 6) * AP] = f2tf32(a1.z); ap[(ak + 7) * AP] = f2tf32(a1.w);
      uint32_t* bpp = &Bs[1][2 * bn + bhalf];
      bpp[(bgrp * 4 + 0) * BP] = f2tf32(bv.x);
      bpp[(bgrp * 4 + 1) * BP] = f2tf32(bv.y);
      bpp[(bgrp * 4 + 2) * BP] = f2tf32(bv.z);
      bpp[(bgrp * 4 + 3) * BP] = f2tf32(bv.w);
    }
    __syncthreads();
    {
      float4 a0, a1, bv;
      bool more = (k0 + 32 < KDIM);
      if (more) {
        a0 = *reinterpret_cast<const float4*>(pa + k0 + 32);
        a1 = *reinterpret_cast<const float4*>(pa + k0 + 36);
        bv = *reinterpret_cast<const float4*>(pb + k0 + 32);
      }
      mma_step(As[1], Bs[1], wm, wn, g, tg, acc);
      if (more) {
        uint32_t* ap = &As[0][perm_am];
        ap[(ak + 0) * AP] = f2tf32(a0.x); ap[(ak + 1) * AP] = f2tf32(a0.y);
        ap[(ak + 2) * AP] = f2tf32(a0.z); ap[(ak + 3) * AP] = f2tf32(a0.w);
        ap[(ak + 4) * AP] = f2tf32(a1.x); ap[(ak + 5) * AP] = f2tf32(a1.y);
        ap[(ak + 6) * AP] = f2tf32(a1.z); ap[(ak + 7) * AP] = f2tf32(a1.w);
        uint32_t* bpp = &Bs[0][2 * bn + bhalf];
        bpp[(bgrp * 4 + 0) * BP] = f2tf32(bv.x);
        bpp[(bgrp * 4 + 1) * BP] = f2tf32(bv.y);
        bpp[(bgrp * 4 + 2) * BP] = f2tf32(bv.z);
        bpp[(bgrp * 4 + 3) * BP] = f2tf32(bv.w);
      }
    }
    __syncthreads();
  }

#pragma unroll
  for (int mt = 0; mt < 2; mt++) {
#pragma unroll
    for (int nt = 0; nt < 4; nt++) {
      int row = m0 + wm + mt * 16 + g;
      int col = n0 + wn + nt * 8 + 2 * tg;
      float2 bv = *reinterpret_cast<const float2*>(bias + col);
      float2 v0, v1;
      v0.x = acc[mt][nt][0] + bv.x; v0.y = acc[mt][nt][1] + bv.y;
      v1.x = acc[mt][nt][2] + bv.x; v1.y = acc[mt][nt][3] + bv.y;
      *reinterpret_cast<float2*>(out + (size_t)row * Ncols + col) = v0;
      *reinterpret_cast<float2*>(out + (size_t)(row + 8) * Ncols + col) = v1;
    }
  }
}

// ---------------------------------------------------------------------------
// Depthwise 3x3 conv (unchanged from round 4)
// ---------------------------------------------------------------------------
#define CW 32
#define WB 8

__global__ __launch_bounds__(512, 2) void conv_kernel(
    const float* __restrict__ dw_w, const float* __restrict__ dw_b) {
  extern __shared__ float s[];
  const int tid = threadIdx.x;
  const int c0 = blockIdx.x * CW;
  const int b0 = blockIdx.y * WB;

#pragma unroll
  for (int rep = 0; rep < 10; rep++) {
    int i = tid + rep * 512;
    int w = i >> 9;
    int n = (i & 511) >> 3;
    int f = (i & 7) << 2;
    int gw = b0 - 1 + w;
    float4 v = make_float4(0.f, 0.f, 0.f, 0.f);
    if ((unsigned)gw < (unsigned)B_TOT)
      v = *reinterpret_cast<const float4*>(
          g_t + ((size_t)gw * 64 + n) * C3 + c0 + f);
    *reinterpret_cast<float4*>(s + ((w * 64 + n) << 5) + f) = v;
  }
  __syncthreads();

  const int cp = tid & 15;
  const int wo = (tid >> 4) & 7;
  const int nh = tid >> 7;
  const int nst = nh << 4;
  const int gb = b0 + wo;
  const int c = c0 + 2 * cp;

  ull w2[9];
#pragma unroll
  for (int t = 0; t < 9; t++)
    w2[t] = pk(__ldg(dw_w + c * 9 + t), __ldg(dw_w + c * 9 + 9 + t));
  ull bia2 = pk(__ldg(dw_b + c), __ldg(dw_b + c + 1));

  const float* rowp[3];
#pragma unroll
  for (int r = 0; r < 3; r++) rowp[r] = s + (((wo + r) * 64) << 5) + 2 * cp;

  ull xm[3], x0[3];
#pragma unroll
  for (int r = 0; r < 3; r++) {
    xm[r] = (nst > 0)
                ? *reinterpret_cast<const ull*>(rowp[r] + ((nst - 1) << 5))
                : 0ull;
    x0[r] = *reinterpret_cast<const ull*>(rowp[r] + (nst << 5));
  }
  float* outp = g_c + ((size_t)gb * 64 + nst) * C3 + c;
#pragma unroll 4
  for (int n = nst; n < nst + 16; n++) {
    ull xp[3];
#pragma unroll
    for (int r = 0; r < 3; r++)
      xp[r] = (n + 1 < 64)
                  ? *reinterpret_cast<const ull*>(rowp[r] + ((n + 1) << 5))
                  : 0ull;
    ull s0 = mul2(xm[0], w2[0]);
    fma2(s0, x0[0], w2[1]); fma2(s0, xp[0], w2[2]);
    ull s1 = mul2(xm[1], w2[3]);
    fma2(s1, x0[1], w2[4]); fma2(s1, xp[1], w2[5]);
    ull s2 = mul2(xm[2], w2[6]);
    fma2(s2, x0[2], w2[7]); fma2(s2, xp[2], w2[8]);
    ull sv = add2(add2(s0, s1), add2(s2, bia2));
    *reinterpret_cast<float2*>(outp) = upk(sv);
    outp += C3;
#pragma unroll
    for (int r = 0; r < 3; r++) { xm[r] = x0[r]; x0[r] = xp[r]; }
  }
}

// ---------------------------------------------------------------------------
// Flash window attention. One block per window, 768 threads, 1 CTA/SM.
//   thread = (head, query, dim-half): q/acc are 8 ull each -> no reg spills.
//   QK dot completed via shfl_xor(1) with the partner lane (other 16 dims).
//   smem holds K/V (64 x 384, pitch 392 = 100352 B).
// ---------------------------------------------------------------------------
#define KVP 392
#define ATT_SMEM (64 * KVP * 4)

__global__ __launch_bounds__(768, 1) void attn_kernel(
    const float* __restrict__ mask, const float* __restrict__ rpb,
    const int* __restrict__ rel_idx, float* __restrict__ ga) {
  extern __shared__ float kv[];  // row n: K at [0..191], V at [192..383]
  const int tid = threadIdx.x;
  const int b = blockIdx.x;

  // cooperative K/V load: 64 rows x 96 float4
  {
    const float* src = g_c + (size_t)b * 64 * C3 + 192;
#pragma unroll
    for (int rep = 0; rep < 8; rep++) {
      int i = tid + rep * 768;   // 0..6143
      int n = i / 96;
      int f = (i - n * 96) << 2;
      *reinterpret_cast<float4*>(kv + n * KVP + f) =
          *reinterpret_cast<const float4*>(src + (size_t)n * C3 + f);
    }
  }
  __syncthreads();

  // 24 warps = 6 heads x 4 query-quarters; lane pair = (query, dim-half)
  const int w = tid >> 5, lane = tid & 31;
  const int h = w >> 2;                       // 0..5
  const int n = ((w & 3) << 4) | (lane >> 1); // 0..63
  const int dh = lane & 1;                    // dim half
  const int dof = h * HDIM + dh * 16;

  // Q half (16 dims) from global (L2-hot)
  ull q2[8];
  {
    const float2* qp = reinterpret_cast<const float2*>(
        g_c + ((size_t)b * 64 + n) * C3 + dof);
#pragma unroll
    for (int d = 0; d < 8; d++) {
      float2 v = qp[d];
      q2[d] = pk(v.x * SCALE_F, v.y * SCALE_F);
    }
  }

  const int* ri = rel_idx + n * 64;
  const float* mrow = mask + (size_t)(b & 63) * 4096 + n * 64;

  float rmax = -1e30f, rsum = 0.f;
  ull acc2[8];
#pragma unroll
  for (int d = 0; d < 8; d++) acc2[d] = 0ull;

#pragma unroll
  for (int mt = 0; mt < 64; mt += 16) {
    float s[16];
#pragma unroll
    for (int j = 0; j < 16; j++) {
      const ulonglong2* tk =
          reinterpret_cast<const ulonglong2*>(kv + (mt + j) * KVP + dof);
      ull dp[4] = {0ull, 0ull, 0ull, 0ull};
#pragma unroll
      for (int d4 = 0; d4 < 4; d4++) {
        ulonglong2 kvv = tk[d4];
        fma2(dp[(2 * d4) & 3], q2[2 * d4], kvv.x);
        fma2(dp[(2 * d4 + 1) & 3], q2[2 * d4 + 1], kvv.y);
      }
      float2 f = upk(add2(add2(dp[0], dp[1]), add2(dp[2], dp[3])));
      float half = f.x + f.y;
      half += __shfl_xor_sync(0xffffffffu, half, 1);
      s[j] = half + __ldg(rpb + __ldg(ri + mt + j) * 6 + h) +
             __ldg(mrow + mt + j);
    }
    float tmax = rmax;
#pragma unroll
    for (int j = 0; j < 16; j++) tmax = fmaxf(tmax, s[j]);
    float corr = __expf(rmax - tmax);
    rsum *= corr;
    ull corr2 = pk(corr, corr);
#pragma unroll
    for (int d = 0; d < 8; d++) acc2[d] = mul2(acc2[d], corr2);
#pragma unroll
    for (int j = 0; j < 16; j++) {
      float p = __expf(s[j] - tmax);
      rsum += p;
      ull p2 = pk(p, p);
      const ulonglong2* tv = reinterpret_cast<const ulonglong2*>(
          kv + (mt + j) * KVP + 192 + dof);
#pragma unroll
      for (int d4 = 0; d4 < 4; d4++) {
        ulonglong2 vv = tv[d4];
        fma2(acc2[2 * d4], p2, vv.x);
        fma2(acc2[2 * d4 + 1], p2, vv.y);
      }
    }
    rmax = tmax;
  }
  float inv = 1.f / rsum;
  float2* po =
      reinterpret_cast<float2*>(ga + ((size_t)b * 64 + n) * C_DIM + dof);
#pragma unroll
  for (int d = 0; d < 8; d++) {
    float2 v = upk(acc2[d]);
    v.x *= inv; v.y *= inv;
    po[d] = v;
  }
}

// ---------------------------------------------------------------------------
extern "C" void kernel_launch(void* const* d_in, const int* in_sizes, int n_in,
                              void* d_out, int out_size) {
  const float* x      = (const float*)d_in[0];
  const float* mask   = (const float*)d_in[1];
  const float* qkv_w  = (const float*)d_in[2];
  const float* qkv_b  = (const float*)d_in[3];
  const float* dw_w   = (const float*)d_in[4];
  const float* dw_b   = (const float*)d_in[5];
  const float* rpb    = (const float*)d_in[6];
  const int*   rel    = (const int*)d_in[7];
  const float* proj_w = (const float*)d_in[8];
  const float* proj_b = (const float*)d_in[9];
  float* out = (float*)d_out;

  float* gt_ptr = nullptr;
  float* ga_ptr = nullptr;
  cudaGetSymbolAddress((void**)&gt_ptr, g_t);
  cudaGetSymbolAddress((void**)&ga_ptr, g_a);

  // 1) QKV GEMM (tf32): g_t = x @ qkv_w^T + qkv_b
  dim3 g1(C3 / GBN, (B_TOT * N_WIN) / GBM);  // (9, 1024)
  tf32_gemm_kernel<<<g1, 256>>>(x, qkv_w, qkv_b, gt_ptr, C3);

  // 2) depthwise conv: g_c = dwconv3x3(g_t)
  const int conv_smem = 10 * 64 * CW * 4;  // 81920
  cudaFuncSetAttribute(conv_kernel,
                       cudaFuncAttributeMaxDynamicSharedMemorySize, conv_smem);
  dim3 g2(C3 / CW, B_TOT / WB);  // (18, 256)
  conv_kernel<<<g2, 512, conv_smem>>>(dw_w, dw_b);

  // 3) window attention: g_a
  cudaFuncSetAttribute(attn_kernel,
                       cudaFuncAttributeMaxDynamicSharedMemorySize, ATT_SMEM);
  attn_kernel<<<B_TOT, 768, ATT_SMEM>>>(mask, rpb, rel, ga_ptr);

  // 4) projection GEMM (tf32): out = g_a @ proj_w^T + proj_b
  dim3 g3(C_DIM / GBN, (B_TOT * N_WIN) / GBM);  // (3, 1024)
  tf32_gemm_kernel<<<g3, 256>>>(ga_ptr, proj_w, proj_b, out, C_DIM);
}

// round 6
// speedup vs baseline: 1.6706x; 1.4060x over previous
#include <cuda_runtime.h>
#include <cstdint>

#define B_TOT 2048
#define N_WIN 64
#define C_DIM 192
#define KDIM 192
#define C3 576
#define HEADS 6
#define HDIM 32
#define SCALE_F 0.17677669529663687f

// scratch: QKV pre-conv t, conv output c, attention output a
__device__ float g_t[(size_t)B_TOT * N_WIN * C3];
__device__ float g_c[(size_t)B_TOT * N_WIN * C3];
__device__ float g_a[(size_t)B_TOT * N_WIN * C_DIM];

// ------------------------------- helpers ----------------------------------
__device__ __forceinline__ uint32_t f2tf32(float x) {
  uint32_t r;
  asm("cvt.rna.tf32.f32 %0, %1;" : "=r"(r) : "f"(x));
  return r;
}

typedef unsigned long long ull;

__device__ __forceinline__ ull pk(float x, float y) {
  ull r;
  asm("mov.b64 %0, {%1, %2};" : "=l"(r) : "f"(x), "f"(y));
  return r;
}
__device__ __forceinline__ float2 upk(ull v) {
  float2 r;
  asm("mov.b64 {%0, %1}, %2;" : "=f"(r.x), "=f"(r.y) : "l"(v));
  return r;
}
__device__ __forceinline__ void fma2(ull& d, ull a, ull b) {
  asm("fma.rn.f32x2 %0, %1, %2, %3;" : "=l"(d) : "l"(a), "l"(b), "l"(d));
}
__device__ __forceinline__ ull mul2(ull a, ull b) {
  ull d;
  asm("mul.rn.f32x2 %0, %1, %2;" : "=l"(d) : "l"(a), "l"(b));
  return d;
}
__device__ __forceinline__ ull add2(ull a, ull b) {
  ull d;
  asm("add.rn.f32x2 %0, %1, %2;" : "=l"(d) : "l"(a), "l"(b));
  return d;
}

// ---------------------------------------------------------------------------
// tf32 tensor-core GEMM (unchanged from round 5)
// ---------------------------------------------------------------------------
#define GBM 128
#define GBN 64
#define GBK 16
#define AP 136
#define BP 136

__device__ __forceinline__ void mma_step(const uint32_t* __restrict__ Asb,
                                         const uint32_t* __restrict__ Bsb,
                                         int wm, int wn, int g, int tg,
                                         float acc[2][4][4]) {
#pragma unroll
  for (int ks = 0; ks < GBK; ks += 8) {
    uint32_t af[2][4], bf[4][2];
#pragma unroll
    for (int mt = 0; mt < 2; mt++) {
      const uint32_t* a0p = Asb + (ks + tg) * AP + wm + mt * 16 + 2 * g;
      const uint32_t* a1p = a0p + 4 * AP;
      ull v01 = *reinterpret_cast<const ull*>(a0p);
      ull v23 = *reinterpret_cast<const ull*>(a1p);
      af[mt][0] = (uint32_t)v01; af[mt][1] = (uint32_t)(v01 >> 32);
      af[mt][2] = (uint32_t)v23; af[mt][3] = (uint32_t)(v23 >> 32);
    }
#pragma unroll
    for (int nt = 0; nt < 4; nt++) {
      int nn = wn + nt * 8 + g;
      const uint32_t* bp = Bsb + ((ks >> 3) * 4 + tg) * BP + 2 * nn;
      ull v = *reinterpret_cast<const ull*>(bp);
      bf[nt][0] = (uint32_t)v; bf[nt][1] = (uint32_t)(v >> 32);
    }
#pragma unroll
    for (int mt = 0; mt < 2; mt++)
#pragma unroll
      for (int nt = 0; nt < 4; nt++) {
        asm volatile(
            "mma.sync.aligned.m16n8k8.row.col.f32.tf32.tf32.f32 "
            "{%0,%1,%2,%3}, {%4,%5,%6,%7}, {%8,%9}, {%0,%1,%2,%3};"
            : "+f"(acc[mt][nt][0]), "+f"(acc[mt][nt][1]),
              "+f"(acc[mt][nt][2]), "+f"(acc[mt][nt][3])
            : "r"(af[mt][0]), "r"(af[mt][1]), "r"(af[mt][2]),
              "r"(af[mt][3]), "r"(bf[nt][0]), "r"(bf[nt][1]));
      }
  }
}

__global__ __launch_bounds__(256) void tf32_gemm_kernel(
    const float* __restrict__ A, const float* __restrict__ W,
    const float* __restrict__ bias, float* __restrict__ out, int Ncols) {
  __shared__ uint32_t As[2][GBK * AP];
  __shared__ uint32_t Bs[2][8 * BP];

  const int tid = threadIdx.x;
  const int m0 = blockIdx.y * GBM;
  const int n0 = blockIdx.x * GBN;
  const int wid = tid >> 5, lane = tid & 31;
  const int wm = (wid & 3) * 32;
  const int wn = (wid >> 2) * 32;
  const int g = lane >> 2, tg = lane & 3;

  float acc[2][4][4];
#pragma unroll
  for (int i = 0; i < 2; i++)
#pragma unroll
    for (int j = 0; j < 4; j++)
#pragma unroll
      for (int r = 0; r < 4; r++) acc[i][j][r] = 0.f;

  const int am = tid >> 1;
  const int ak = (tid & 1) * 8;
  const int bn = tid >> 2;
  const int bk = (tid & 3) * 4;
  const int perm_am = (am & ~15) + ((am & 7) << 1) + ((am >> 3) & 1);
  const int bgrp = bk >> 3;
  const int bhalf = (bk >> 2) & 1;

  const float* pa = A + (size_t)(m0 + am) * KDIM + ak;
  const float* pb = W + (size_t)(n0 + bn) * KDIM + bk;

  {
    float4 a0 = *reinterpret_cast<const float4*>(pa);
    float4 a1 = *reinterpret_cast<const float4*>(pa + 4);
    float4 bv = *reinterpret_cast<const float4*>(pb);
    uint32_t* ap = &As[0][perm_am];
    ap[(ak + 0) * AP] = f2tf32(a0.x); ap[(ak + 1) * AP] = f2tf32(a0.y);
    ap[(ak + 2) * AP] = f2tf32(a0.z); ap[(ak + 3) * AP] = f2tf32(a0.w);
    ap[(ak + 4) * AP] = f2tf32(a1.x); ap[(ak + 5) * AP] = f2tf32(a1.y);
    ap[(ak + 6) * AP] = f2tf32(a1.z); ap[(ak + 7) * AP] = f2tf32(a1.w);
    uint32_t* bpp = &Bs[0][2 * bn + bhalf];
    bpp[(bgrp * 4 + 0) * BP] = f2tf32(bv.x);
    bpp[(bgrp * 4 + 1) * BP] = f2tf32(bv.y);
    bpp[(bgrp * 4 + 2) * BP] = f2tf32(bv.z);
    bpp[(bgrp * 4 + 3) * BP] = f2tf32(bv.w);
  }
  __syncthreads();

#pragma unroll
  for (int k0 = 0; k0 < KDIM; k0 += 32) {
    {
      float4 a0 = *reinterpret_cast<const float4*>(pa + k0 + 16);
      float4 a1 = *reinterpret_cast<const float4*>(pa + k0 + 20);
      float4 bv = *reinterpret_cast<const float4*>(pb + k0 + 16);
      mma_step(As[0], Bs[0], wm, wn, g, tg, acc);
      uint32_t* ap = &As[1][perm_am];
      ap[(ak + 0) * AP] = f2tf32(a0.x); ap[(ak + 1) * AP] = f2tf32(a0.y);
      ap[(ak + 2) * AP] = f2tf32(a0.z); ap[(ak + 3) * AP] = f2tf32(a0.w);
      ap[(ak + 4) * AP] = f2tf32(a1.x); ap[(ak + 5) * AP] = f2tf32(a1.y);
      ap[(ak + 6) * AP] = f2tf32(a1.z); ap[(ak + 7) * AP] = f2tf32(a1.w);
      uint32_t* bpp = &Bs[1][2 * bn + bhalf];
      bpp[(bgrp * 4 + 0) * BP] = f2tf32(bv.x);
      bpp[(bgrp * 4 + 1) * BP] = f2tf32(bv.y);
      bpp[(bgrp * 4 + 2) * BP] = f2tf32(bv.z);
      bpp[(bgrp * 4 + 3) * BP] = f2tf32(bv.w);
    }
    __syncthreads();
    {
      float4 a0, a1, bv;
      bool more = (k0 + 32 < KDIM);
      if (more) {
        a0 = *reinterpret_cast<const float4*>(pa + k0 + 32);
        a1 = *reinterpret_cast<const float4*>(pa + k0 + 36);
        bv = *reinterpret_cast<const float4*>(pb + k0 + 32);
      }
      mma_step(As[1], Bs[1], wm, wn, g, tg, acc);
      if (more) {
        uint32_t* ap = &As[0][perm_am];
        ap[(ak + 0) * AP] = f2tf32(a0.x); ap[(ak + 1) * AP] = f2tf32(a0.y);
        ap[(ak + 2) * AP] = f2tf32(a0.z); ap[(ak + 3) * AP] = f2tf32(a0.w);
        ap[(ak + 4) * AP] = f2tf32(a1.x); ap[(ak + 5) * AP] = f2tf32(a1.y);
        ap[(ak + 6) * AP] = f2tf32(a1.z); ap[(ak + 7) * AP] = f2tf32(a1.w);
        uint32_t* bpp = &Bs[0][2 * bn + bhalf];
        bpp[(bgrp * 4 + 0) * BP] = f2tf32(bv.x);
        bpp[(bgrp * 4 + 1) * BP] = f2tf32(bv.y);
        bpp[(bgrp * 4 + 2) * BP] = f2tf32(bv.z);
        bpp[(bgrp * 4 + 3) * BP] = f2tf32(bv.w);
      }
    }
    __syncthreads();
  }

#pragma unroll
  for (int mt = 0; mt < 2; mt++) {
#pragma unroll
    for (int nt = 0; nt < 4; nt++) {
      int row = m0 + wm + mt * 16 + g;
      int col = n0 + wn + nt * 8 + 2 * tg;
      float2 bv = *reinterpret_cast<const float2*>(bias + col);
      float2 v0, v1;
      v0.x = acc[mt][nt][0] + bv.x; v0.y = acc[mt][nt][1] + bv.y;
      v1.x = acc[mt][nt][2] + bv.x; v1.y = acc[mt][nt][3] + bv.y;
      *reinterpret_cast<float2*>(out + (size_t)row * Ncols + col) = v0;
      *reinterpret_cast<float2*>(out + (size_t)(row + 8) * Ncols + col) = v1;
    }
  }
}

// ---------------------------------------------------------------------------
// Depthwise 3x3 conv (unchanged from round 4)
// ---------------------------------------------------------------------------
#define CW 32
#define WB 8

__global__ __launch_bounds__(512, 2) void conv_kernel(
    const float* __restrict__ dw_w, const float* __restrict__ dw_b) {
  extern __shared__ float s[];
  const int tid = threadIdx.x;
  const int c0 = blockIdx.x * CW;
  const int b0 = blockIdx.y * WB;

#pragma unroll
  for (int rep = 0; rep < 10; rep++) {
    int i = tid + rep * 512;
    int w = i >> 9;
    int n = (i & 511) >> 3;
    int f = (i & 7) << 2;
    int gw = b0 - 1 + w;
    float4 v = make_float4(0.f, 0.f, 0.f, 0.f);
    if ((unsigned)gw < (unsigned)B_TOT)
      v = *reinterpret_cast<const float4*>(
          g_t + ((size_t)gw * 64 + n) * C3 + c0 + f);
    *reinterpret_cast<float4*>(s + ((w * 64 + n) << 5) + f) = v;
  }
  __syncthreads();

  const int cp = tid & 15;
  const int wo = (tid >> 4) & 7;
  const int nh = tid >> 7;
  const int nst = nh << 4;
  const int gb = b0 + wo;
  const int c = c0 + 2 * cp;

  ull w2[9];
#pragma unroll
  for (int t = 0; t < 9; t++)
    w2[t] = pk(__ldg(dw_w + c * 9 + t), __ldg(dw_w + c * 9 + 9 + t));
  ull bia2 = pk(__ldg(dw_b + c), __ldg(dw_b + c + 1));

  const float* rowp[3];
#pragma unroll
  for (int r = 0; r < 3; r++) rowp[r] = s + (((wo + r) * 64) << 5) + 2 * cp;

  ull xm[3], x0[3];
#pragma unroll
  for (int r = 0; r < 3; r++) {
    xm[r] = (nst > 0)
                ? *reinterpret_cast<const ull*>(rowp[r] + ((nst - 1) << 5))
                : 0ull;
    x0[r] = *reinterpret_cast<const ull*>(rowp[r] + (nst << 5));
  }
  float* outp = g_c + ((size_t)gb * 64 + nst) * C3 + c;
#pragma unroll 4
  for (int n = nst; n < nst + 16; n++) {
    ull xp[3];
#pragma unroll
    for (int r = 0; r < 3; r++)
      xp[r] = (n + 1 < 64)
                  ? *reinterpret_cast<const ull*>(rowp[r] + ((n + 1) << 5))
                  : 0ull;
    ull s0 = mul2(xm[0], w2[0]);
    fma2(s0, x0[0], w2[1]); fma2(s0, xp[0], w2[2]);
    ull s1 = mul2(xm[1], w2[3]);
    fma2(s1, x0[1], w2[4]); fma2(s1, xp[1], w2[5]);
    ull s2 = mul2(xm[2], w2[6]);
    fma2(s2, x0[2], w2[7]); fma2(s2, xp[2], w2[8]);
    ull sv = add2(add2(s0, s1), add2(s2, bia2));
    *reinterpret_cast<float2*>(outp) = upk(sv);
    outp += C3;
#pragma unroll
    for (int r = 0; r < 3; r++) { xm[r] = x0[r]; x0[r] = xp[r]; }
  }
}

// ---------------------------------------------------------------------------
// Window attention: tensor-core S = QK^T + bias + mask, then scalar
// softmax + PV. One block per window, 768 threads, 1 CTA/SM.
//   smem: sQ/sV 64x196 (tf32 Q, later fp32 V), sK 64x196 (tf32),
//         sS 6x64x68 fp32. Total 204800 B.
// ---------------------------------------------------------------------------
#define QKP 196
#define SSP 68
#define SK_OFF (64 * QKP)
#define SS_OFF (2 * 64 * QKP)
#define ATT_SMEM ((2 * 64 * QKP + HEADS * 64 * SSP) * 4)

__global__ __launch_bounds__(768, 1) void attn_kernel(
    const float* __restrict__ mask, const float* __restrict__ rpb,
    const int* __restrict__ rel_idx, float* __restrict__ ga) {
  extern __shared__ float sm[];
  uint32_t* sQ = reinterpret_cast<uint32_t*>(sm);        // tf32, Q*scale
  uint32_t* sK = reinterpret_cast<uint32_t*>(sm + SK_OFF);  // tf32
  float* sS = sm + SS_OFF;  // S+bias+mask, [h][n][m] pitch 68
  float* sV = sm;           // V overwrites Q after phase 1

  const int tid = threadIdx.x;
  const int b = blockIdx.x;
  const float* win = g_c + (size_t)b * 64 * C3;

  // ---- phase 0: stage Q (scaled) and K as tf32 ----------------------------
#pragma unroll
  for (int rep = 0; rep < 4; rep++) {
    int i = tid + rep * 768;          // 0..3071
    int row = i / 48, f4 = (i % 48) << 2;
    float4 q = *reinterpret_cast<const float4*>(win + (size_t)row * C3 + f4);
    uint32_t* dq = sQ + row * QKP + f4;
    dq[0] = f2tf32(q.x * SCALE_F); dq[1] = f2tf32(q.y * SCALE_F);
    dq[2] = f2tf32(q.z * SCALE_F); dq[3] = f2tf32(q.w * SCALE_F);
    float4 k =
        *reinterpret_cast<const float4*>(win + (size_t)row * C3 + 192 + f4);
    uint32_t* dk = sK + row * QKP + f4;
    dk[0] = f2tf32(k.x); dk[1] = f2tf32(k.y);
    dk[2] = f2tf32(k.z); dk[3] = f2tf32(k.w);
  }
  __syncthreads();

  // ---- phase 1: S = QK^T + bias + mask (warp = (head, m-tile)) -----------
  {
    const int w = tid >> 5, lane = tid & 31;
    const int h = w >> 2, R = (w & 3) << 4;
    const int g = lane >> 2, tg = lane & 3;

    float acc[8][4];
#pragma unroll
    for (int nt = 0; nt < 8; nt++)
#pragma unroll
      for (int r = 0; r < 4; r++) acc[nt][r] = 0.f;

    const uint32_t* qb = sQ + (R + g) * QKP + h * HDIM + tg;
#pragma unroll
    for (int kt = 0; kt < 4; kt++) {
      uint32_t a0 = qb[kt * 8];
      uint32_t a1 = qb[kt * 8 + 8 * QKP];
      uint32_t a2 = qb[kt * 8 + 4];
      uint32_t a3 = qb[kt * 8 + 8 * QKP + 4];
#pragma unroll
      for (int nt = 0; nt < 8; nt++) {
        const uint32_t* kb = sK + (nt * 8 + g) * QKP + h * HDIM + kt * 8 + tg;
        uint32_t b0 = kb[0], b1 = kb[4];
        asm volatile(
            "mma.sync.aligned.m16n8k8.row.col.f32.tf32.tf32.f32 "
            "{%0,%1,%2,%3}, {%4,%5,%6,%7}, {%8,%9}, {%0,%1,%2,%3};"
            : "+f"(acc[nt][0]), "+f"(acc[nt][1]), "+f"(acc[nt][2]),
              "+f"(acc[nt][3])
            : "r"(a0), "r"(a1), "r"(a2), "r"(a3), "r"(b0), "r"(b1));
      }
    }

    // epilogue: + rpb[rel_idx] + mask, store to sS
    const int n0 = R + g, n1 = n0 + 8;
    const float* mbase = mask + (size_t)(b & 63) * 4096;
#pragma unroll
    for (int nt = 0; nt < 8; nt++) {
      int m0 = nt * 8 + 2 * tg;
      int2 r0 = *reinterpret_cast<const int2*>(rel_idx + n0 * 64 + m0);
      int2 r1 = *reinterpret_cast<const int2*>(rel_idx + n1 * 64 + m0);
      float2 k0 = *reinterpret_cast<const float2*>(mbase + n0 * 64 + m0);
      float2 k1 = *reinterpret_cast<const float2*>(mbase + n1 * 64 + m0);
      float2 o0, o1;
      o0.x = acc[nt][0] + __ldg(rpb + r0.x * 6 + h) + k0.x;
      o0.y = acc[nt][1] + __ldg(rpb + r0.y * 6 + h) + k0.y;
      o1.x = acc[nt][2] + __ldg(rpb + r1.x * 6 + h) + k1.x;
      o1.y = acc[nt][3] + __ldg(rpb + r1.y * 6 + h) + k1.y;
      *reinterpret_cast<float2*>(sS + (h * 64 + n0) * SSP + m0) = o0;
      *reinterpret_cast<float2*>(sS + (h * 64 + n1) * SSP + m0) = o1;
    }
  }
  __syncthreads();

  // ---- load V into sV (Q region is dead) ----------------------------------
#pragma unroll
  for (int rep = 0; rep < 4; rep++) {
    int i = tid + rep * 768;
    int row = i / 48, f4 = (i % 48) << 2;
    *reinterpret_cast<float4*>(sV + row * QKP + f4) =
        *reinterpret_cast<const float4*>(win + (size_t)row * C3 + 384 + f4);
  }
  __syncthreads();

  // ---- phase 2: softmax + PV (thread = (head, query, dim-half)) ----------
  const int w = tid >> 5, lane = tid & 31;
  const int h = w >> 2;
  const int n = ((w & 3) << 4) | (lane >> 1);
  const int dh = lane & 1;
  const int dof = h * HDIM + dh * 16;

  const float* srow = sS + (h * 64 + n) * SSP;

  float rmax = -1e30f, rsum = 0.f;
  ull acc2[8];
#pragma unroll
  for (int d = 0; d < 8; d++) acc2[d] = 0ull;

#pragma unroll
  for (int mt = 0; mt < 64; mt += 16) {
    float s[16];
#pragma unroll
    for (int jj = 0; jj < 4; jj++) {
      float4 v = *reinterpret_cast<const float4*>(srow + mt + jj * 4);
      s[jj * 4 + 0] = v.x; s[jj * 4 + 1] = v.y;
      s[jj * 4 + 2] = v.z; s[jj * 4 + 3] = v.w;
    }
    float tmax = rmax;
#pragma unroll
    for (int j = 0; j < 16; j++) tmax = fmaxf(tmax, s[j]);
    float corr = __expf(rmax - tmax);
    rsum *= corr;
    ull corr2 = pk(corr, corr);
#pragma unroll
    for (int d = 0; d < 8; d++) acc2[d] = mul2(acc2[d], corr2);
#pragma unroll
    for (int j = 0; j < 16; j++) {
      float p = __expf(s[j] - tmax);
      rsum += p;
      ull p2 = pk(p, p);
      const ulonglong2* tv = reinterpret_cast<const ulonglong2*>(
          sV + (mt + j) * QKP + dof);
#pragma unroll
      for (int d4 = 0; d4 < 4; d4++) {
        ulonglong2 vv = tv[d4];
        fma2(acc2[2 * d4], p2, vv.x);
        fma2(acc2[2 * d4 + 1], p2, vv.y);
      }
    }
    rmax = tmax;
  }
  float inv = 1.f / rsum;
  float2* po =
      reinterpret_cast<float2*>(ga + ((size_t)b * 64 + n) * C_DIM + dof);
#pragma unroll
  for (int d = 0; d < 8; d++) {
    float2 v = upk(acc2[d]);
    v.x *= inv; v.y *= inv;
    po[d] = v;
  }
}

// ---------------------------------------------------------------------------
extern "C" void kernel_launch(void* const* d_in, const int* in_sizes, int n_in,
                              void* d_out, int out_size) {
  const float* x      = (const float*)d_in[0];
  const float* mask   = (const float*)d_in[1];
  const float* qkv_w  = (const float*)d_in[2];
  const float* qkv_b  = (const float*)d_in[3];
  const float* dw_w   = (const float*)d_in[4];
  const float* dw_b   = (const float*)d_in[5];
  const float* rpb    = (const float*)d_in[6];
  const int*   rel    = (const int*)d_in[7];
  const float* proj_w = (const float*)d_in[8];
  const float* proj_b = (const float*)d_in[9];
  float* out = (float*)d_out;

  float* gt_ptr = nullptr;
  float* ga_ptr = nullptr;
  cudaGetSymbolAddress((void**)&gt_ptr, g_t);
  cudaGetSymbolAddress((void**)&ga_ptr, g_a);

  // 1) QKV GEMM (tf32): g_t = x @ qkv_w^T + qkv_b
  dim3 g1(C3 / GBN, (B_TOT * N_WIN) / GBM);  // (9, 1024)
  tf32_gemm_kernel<<<g1, 256>>>(x, qkv_w, qkv_b, gt_ptr, C3);

  // 2) depthwise conv: g_c = dwconv3x3(g_t)
  const int conv_smem = 10 * 64 * CW * 4;  // 81920
  cudaFuncSetAttribute(conv_kernel,
                       cudaFuncAttributeMaxDynamicSharedMemorySize, conv_smem);
  dim3 g2(C3 / CW, B_TOT / WB);  // (18, 256)
  conv_kernel<<<g2, 512, conv_smem>>>(dw_w, dw_b);

  // 3) window attention: g_a
  cudaFuncSetAttribute(attn_kernel,
                       cudaFuncAttributeMaxDynamicSharedMemorySize, ATT_SMEM);
  attn_kernel<<<B_TOT, 768, ATT_SMEM>>>(mask, rpb, rel, ga_ptr);

  // 4) projection GEMM (tf32): out = g_a @ proj_w^T + proj_b
  dim3 g3(C_DIM / GBN, (B_TOT * N_WIN) / GBM);  // (3, 1024)
  tf32_gemm_kernel<<<g3, 256>>>(ga_ptr, proj_w, proj_b, out, C_DIM);
}

// round 7
// speedup vs baseline: 2.1941x; 1.3134x over previous
#include <cuda_runtime.h>
#include <cstdint>

#define B_TOT 2048
#define N_WIN 64
#define C_DIM 192
#define KDIM 192
#define C3 576
#define HEADS 6
#define HDIM 32
#define SCALE_F 0.17677669529663687f

// GEMM tile geometry
#define AP 136                 // A k-row pitch (words); 136 % 32 == 8 -> conflict-free
#define BP 392                 // B pair-row pitch (words); 392 % 32 == 8
#define AT_WORDS (16 * AP)     // 2176 words per A k-tile (128 rows x 16 k)
#define BT_WORDS (8 * BP)      // 3136 words per B k-tile (192 rows x 16 k)
#define NKT 12                 // K = 192 = 12 x 16

// scratch
__device__ float g_t[(size_t)B_TOT * N_WIN * C3];           // QKV pre-conv
__device__ float g_c[(size_t)B_TOT * N_WIN * C3];           // conv output
__device__ __align__(16) float g_ax[(size_t)1024 * NKT * AT_WORDS];  // x, tiled tf32
__device__ __align__(16) float g_ap[(size_t)1024 * NKT * AT_WORDS];  // attn out, tiled tf32
__device__ __align__(16) float g_bq[3 * NKT * BT_WORDS];    // qkv_w tiled tf32
__device__ __align__(16) float g_bp[1 * NKT * BT_WORDS];    // proj_w tiled tf32

// ------------------------------- helpers ----------------------------------
__device__ __forceinline__ uint32_t f2tf32(float x) {
  uint32_t r;
  asm("cvt.rna.tf32.f32 %0, %1;" : "=r"(r) : "f"(x));
  return r;
}

typedef unsigned long long ull;

__device__ __forceinline__ ull pk(float x, float y) {
  ull r;
  asm("mov.b64 %0, {%1, %2};" : "=l"(r) : "f"(x), "f"(y));
  return r;
}
__device__ __forceinline__ float2 upk(ull v) {
  float2 r;
  asm("mov.b64 {%0, %1}, %2;" : "=f"(r.x), "=f"(r.y) : "l"(v));
  return r;
}
__device__ __forceinline__ void fma2(ull& d, ull a, ull b) {
  asm("fma.rn.f32x2 %0, %1, %2, %3;" : "=l"(d) : "l"(a), "l"(b), "l"(d));
}
__device__ __forceinline__ ull mul2(ull a, ull b) {
  ull d;
  asm("mul.rn.f32x2 %0, %1, %2;" : "=l"(d) : "l"(a), "l"(b));
  return d;
}
__device__ __forceinline__ ull add2(ull a, ull b) {
  ull d;
  asm("add.rn.f32x2 %0, %1, %2;" : "=l"(d) : "l"(a), "l"(b));
  return d;
}
__device__ __forceinline__ void cp16(uint32_t s, const void* g) {
  asm volatile("cp.async.cg.shared.global [%0], [%1], 16;" ::"r"(s), "l"(g));
}
__device__ __forceinline__ void cp_commit() {
  asm volatile("cp.async.commit_group;");
}
template <int N>
__device__ __forceinline__ void cp_wait() {
  asm volatile("cp.async.wait_group %0;" ::"n"(N));
}

// ---------------------------------------------------------------------------
// Prep kernels: convert fp32 -> tf32 and permute into GEMM-native tile layout
// A layout: [mtile][ktile][k 0..15][perm(m) 0..135]
//   perm(m) = (m & ~15) + 2*(m & 7) + ((m >> 3) & 1)
// B layout: [ntile][ktile][prow 0..7][2n + khalf], prow=(k>>3)*4+(k&3),
//   khalf=(k>>2)&1
// ---------------------------------------------------------------------------
__global__ __launch_bounds__(128) void prep_a_kernel(
    const float* __restrict__ src, float* __restrict__ dst) {
  const int m = threadIdx.x;
  const int mtile = blockIdx.y;
  const int k0 = blockIdx.x * 4;  // 0..188
  float4 v = *reinterpret_cast<const float4*>(
      src + ((size_t)mtile * 128 + m) * KDIM + k0);
  const int ktile = k0 >> 4, kk = k0 & 15;
  const int perm = (m & ~15) + 2 * (m & 7) + ((m >> 3) & 1);
  uint32_t* d = reinterpret_cast<uint32_t*>(dst) +
                ((size_t)(mtile * NKT + ktile) * 16 + kk) * AP + perm;
  d[0] = f2tf32(v.x);
  d[AP] = f2tf32(v.y);
  d[2 * AP] = f2tf32(v.z);
  d[3 * AP] = f2tf32(v.w);
}

__global__ __launch_bounds__(192) void prep_w_kernel(
    const float* __restrict__ src, float* __restrict__ dst) {
  const int nl = threadIdx.x;  // 0..191
  const int ntile = blockIdx.y;
  const int k0 = blockIdx.x * 4;
  float4 v = *reinterpret_cast<const float4*>(
      src + ((size_t)ntile * 192 + nl) * KDIM + k0);
  const int ktile = k0 >> 4, kk = k0 & 15;
  const int pr0 = (kk >> 3) * 4;
  const int khalf = (kk >> 2) & 1;
  uint32_t* d = reinterpret_cast<uint32_t*>(dst) +
                ((size_t)(ntile * NKT + ktile) * 8 + pr0) * BP + 2 * nl + khalf;
  d[0] = f2tf32(v.x);
  d[BP] = f2tf32(v.y);
  d[2 * BP] = f2tf32(v.z);
  d[3 * BP] = f2tf32(v.w);
}

// ---------------------------------------------------------------------------
// tf32 GEMM v2: out[m, n] = sum_k A[m,k] W[n,k] + bias[n]
//   Operands pre-tiled tf32. Block 128x192, 192 thr, 6 warps of 64x64.
//   cp.async double-buffered; no cvt/STS in the hot loop.
// ---------------------------------------------------------------------------
__global__ __launch_bounds__(192) void tf32_gemm2(
    const float* __restrict__ At, const float* __restrict__ Bt,
    const float* __restrict__ bias, float* __restrict__ out, int Ncols) {
  __shared__ __align__(16) uint32_t Ab[2][AT_WORDS];
  __shared__ __align__(16) uint32_t Bb[2][BT_WORDS];

  const int tid = threadIdx.x;
  const int wid = tid >> 5, lane = tid & 31;
  const int wm = (wid & 1) * 64;
  const int wn = (wid >> 1) * 64;
  const int g = lane >> 2, tg = lane & 3;
  const int m0 = blockIdx.y * 128;
  const int n0 = blockIdx.x * 192;

  const uint32_t* gA =
      reinterpret_cast<const uint32_t*>(At) + (size_t)blockIdx.y * NKT * AT_WORDS;
  const uint32_t* gB =
      reinterpret_cast<const uint32_t*>(Bt) + (size_t)blockIdx.x * NKT * BT_WORDS;

  float acc[4][8][4];
#pragma unroll
  for (int mt = 0; mt < 4; mt++)
#pragma unroll
    for (int nt = 0; nt < 8; nt++)
#pragma unroll
      for (int r = 0; r < 4; r++) acc[mt][nt][r] = 0.f;

  auto copy_tile = [&](int kt, int buf) {
    const uint32_t* a = gA + (size_t)kt * AT_WORDS;
    const uint32_t* bsrc = gB + (size_t)kt * BT_WORDS;
    uint32_t sa = (uint32_t)__cvta_generic_to_shared(&Ab[buf][0]);
    uint32_t sb = (uint32_t)__cvta_generic_to_shared(&Bb[buf][0]);
    for (int i = tid * 4; i < AT_WORDS; i += 192 * 4) cp16(sa + i * 4, a + i);
    for (int i = tid * 4; i < BT_WORDS; i += 192 * 4) cp16(sb + i * 4, bsrc + i);
  };

  auto mma_tile = [&](int buf) {
    const uint32_t* Asb = Ab[buf];
    const uint32_t* Bsb = Bb[buf];
#pragma unroll
    for (int ks = 0; ks < 16; ks += 8) {
      uint32_t af[4][4], bf[8][2];
#pragma unroll
      for (int mt = 0; mt < 4; mt++) {
        const uint32_t* ap = Asb + (ks + tg) * AP + wm + mt * 16 + 2 * g;
        ull v01 = *reinterpret_cast<const ull*>(ap);
        ull v23 = *reinterpret_cast<const ull*>(ap + 4 * AP);
        af[mt][0] = (uint32_t)v01; af[mt][1] = (uint32_t)(v01 >> 32);
        af[mt][2] = (uint32_t)v23; af[mt][3] = (uint32_t)(v23 >> 32);
      }
#pragma unroll
      for (int nt = 0; nt < 8; nt++) {
        const uint32_t* bp =
            Bsb + ((ks >> 3) * 4 + tg) * BP + 2 * (wn + nt * 8 + g);
        ull v = *reinterpret_cast<const ull*>(bp);
        bf[nt][0] = (uint32_t)v; bf[nt][1] = (uint32_t)(v >> 32);
      }
#pragma unroll
      for (int mt = 0; mt < 4; mt++)
#pragma unroll
        for (int nt = 0; nt < 8; nt++) {
          asm volatile(
              "mma.sync.aligned.m16n8k8.row.col.f32.tf32.tf32.f32 "
              "{%0,%1,%2,%3}, {%4,%5,%6,%7}, {%8,%9}, {%0,%1,%2,%3};"
              : "+f"(acc[mt][nt][0]), "+f"(acc[mt][nt][1]),
                "+f"(acc[mt][nt][2]), "+f"(acc[mt][nt][3])
              : "r"(af[mt][0]), "r"(af[mt][1]), "r"(af[mt][2]),
                "r"(af[mt][3]), "r"(bf[nt][0]), "r"(bf[nt][1]));
        }
    }
  };

  copy_tile(0, 0);
  cp_commit();

#pragma unroll 1
  for (int kt = 0; kt < NKT; kt += 2) {
    copy_tile(kt + 1, 1);
    cp_commit();
    cp_wait<1>();
    __syncthreads();
    mma_tile(0);
    __syncthreads();
    if (kt + 2 < NKT) {
      copy_tile(kt + 2, 0);
      cp_commit();
      cp_wait<1>();
    } else {
      cp_wait<0>();
    }
    __syncthreads();
    mma_tile(1);
    __syncthreads();
  }

  // epilogue (+bias)
#pragma unroll
  for (int mt = 0; mt < 4; mt++) {
#pragma unroll
    for (int nt = 0; nt < 8; nt++) {
      int row = m0 + wm + mt * 16 + g;
      int col = n0 + wn + nt * 8 + 2 * tg;
      float2 bv = *reinterpret_cast<const float2*>(bias + col);
      float2 v0, v1;
      v0.x = acc[mt][nt][0] + bv.x; v0.y = acc[mt][nt][1] + bv.y;
      v1.x = acc[mt][nt][2] + bv.x; v1.y = acc[mt][nt][3] + bv.y;
      *reinterpret_cast<float2*>(out + (size_t)row * Ncols + col) = v0;
      *reinterpret_cast<float2*>(out + (size_t)(row + 8) * Ncols + col) = v1;
    }
  }
}

// ---------------------------------------------------------------------------
// Depthwise 3x3 conv (unchanged)
// ---------------------------------------------------------------------------
#define CW 32
#define WB 8

__global__ __launch_bounds__(512, 2) void conv_kernel(
    const float* __restrict__ dw_w, const float* __restrict__ dw_b) {
  extern __shared__ float s[];
  const int tid = threadIdx.x;
  const int c0 = blockIdx.x * CW;
  const int b0 = blockIdx.y * WB;

#pragma unroll
  for (int rep = 0; rep < 10; rep++) {
    int i = tid + rep * 512;
    int w = i >> 9;
    int n = (i & 511) >> 3;
    int f = (i & 7) << 2;
    int gw = b0 - 1 + w;
    float4 v = make_float4(0.f, 0.f, 0.f, 0.f);
    if ((unsigned)gw < (unsigned)B_TOT)
      v = *reinterpret_cast<const float4*>(
          g_t + ((size_t)gw * 64 + n) * C3 + c0 + f);
    *reinterpret_cast<float4*>(s + ((w * 64 + n) << 5) + f) = v;
  }
  __syncthreads();

  const int cp = tid & 15;
  const int wo = (tid >> 4) & 7;
  const int nh = tid >> 7;
  const int nst = nh << 4;
  const int gb = b0 + wo;
  const int c = c0 + 2 * cp;

  ull w2[9];
#pragma unroll
  for (int t = 0; t < 9; t++)
    w2[t] = pk(__ldg(dw_w + c * 9 + t), __ldg(dw_w + c * 9 + 9 + t));
  ull bia2 = pk(__ldg(dw_b + c), __ldg(dw_b + c + 1));

  const float* rowp[3];
#pragma unroll
  for (int r = 0; r < 3; r++) rowp[r] = s + (((wo + r) * 64) << 5) + 2 * cp;

  ull xm[3], x0[3];
#pragma unroll
  for (int r = 0; r < 3; r++) {
    xm[r] = (nst > 0)
                ? *reinterpret_cast<const ull*>(rowp[r] + ((nst - 1) << 5))
                : 0ull;
    x0[r] = *reinterpret_cast<const ull*>(rowp[r] + (nst << 5));
  }
  float* outp = g_c + ((size_t)gb * 64 + nst) * C3 + c;
#pragma unroll 4
  for (int n = nst; n < nst + 16; n++) {
    ull xp[3];
#pragma unroll
    for (int r = 0; r < 3; r++)
      xp[r] = (n + 1 < 64)
                  ? *reinterpret_cast<const ull*>(rowp[r] + ((n + 1) << 5))
                  : 0ull;
    ull s0 = mul2(xm[0], w2[0]);
    fma2(s0, x0[0], w2[1]); fma2(s0, xp[0], w2[2]);
    ull s1 = mul2(xm[1], w2[3]);
    fma2(s1, x0[1], w2[4]); fma2(s1, xp[1], w2[5]);
    ull s2 = mul2(xm[2], w2[6]);
    fma2(s2, x0[2], w2[7]); fma2(s2, xp[2], w2[8]);
    ull sv = add2(add2(s0, s1), add2(s2, bia2));
    *reinterpret_cast<float2*>(outp) = upk(sv);
    outp += C3;
#pragma unroll
    for (int r = 0; r < 3; r++) { xm[r] = x0[r]; x0[r] = xp[r]; }
  }
}

// ---------------------------------------------------------------------------
// Window attention (round-6 structure; epilogue writes tiled tf32 for proj)
// ---------------------------------------------------------------------------
#define QKP 196
#define SSP 68
#define SK_OFF (64 * QKP)
#define SS_OFF (2 * 64 * QKP)
#define ATT_SMEM ((2 * 64 * QKP + HEADS * 64 * SSP) * 4)

__global__ __launch_bounds__(768, 1) void attn_kernel(
    const float* __restrict__ mask, const float* __restrict__ rpb,
    const int* __restrict__ rel_idx) {
  extern __shared__ float sm[];
  uint32_t* sQ = reinterpret_cast<uint32_t*>(sm);
  uint32_t* sK = reinterpret_cast<uint32_t*>(sm + SK_OFF);
  float* sS = sm + SS_OFF;
  float* sV = sm;

  const int tid = threadIdx.x;
  const int b = blockIdx.x;
  const float* win = g_c + (size_t)b * 64 * C3;

  // stage Q (scaled) and K as tf32
#pragma unroll
  for (int rep = 0; rep < 4; rep++) {
    int i = tid + rep * 768;
    int row = i / 48, f4 = (i % 48) << 2;
    float4 q = *reinterpret_cast<const float4*>(win + (size_t)row * C3 + f4);
    uint32_t* dq = sQ + row * QKP + f4;
    dq[0] = f2tf32(q.x * SCALE_F); dq[1] = f2tf32(q.y * SCALE_F);
    dq[2] = f2tf32(q.z * SCALE_F); dq[3] = f2tf32(q.w * SCALE_F);
    float4 k =
        *reinterpret_cast<const float4*>(win + (size_t)row * C3 + 192 + f4);
    uint32_t* dk = sK + row * QKP + f4;
    dk[0] = f2tf32(k.x); dk[1] = f2tf32(k.y);
    dk[2] = f2tf32(k.z); dk[3] = f2tf32(k.w);
  }
  __syncthreads();

  // S = QK^T + bias + mask
  {
    const int w = tid >> 5, lane = tid & 31;
    const int h = w >> 2, R = (w & 3) << 4;
    const int g = lane >> 2, tg = lane & 3;

    float acc[8][4];
#pragma unroll
    for (int nt = 0; nt < 8; nt++)
#pragma unroll
      for (int r = 0; r < 4; r++) acc[nt][r] = 0.f;

    const uint32_t* qb = sQ + (R + g) * QKP + h * HDIM + tg;
#pragma unroll
    for (int kt = 0; kt < 4; kt++) {
      uint32_t a0 = qb[kt * 8];
      uint32_t a1 = qb[kt * 8 + 8 * QKP];
      uint32_t a2 = qb[kt * 8 + 4];
      uint32_t a3 = qb[kt * 8 + 8 * QKP + 4];
#pragma unroll
      for (int nt = 0; nt < 8; nt++) {
        const uint32_t* kb = sK + (nt * 8 + g) * QKP + h * HDIM + kt * 8 + tg;
        uint32_t b0 = kb[0], b1 = kb[4];
        asm volatile(
            "mma.sync.aligned.m16n8k8.row.col.f32.tf32.tf32.f32 "
            "{%0,%1,%2,%3}, {%4,%5,%6,%7}, {%8,%9}, {%0,%1,%2,%3};"
            : "+f"(acc[nt][0]), "+f"(acc[nt][1]), "+f"(acc[nt][2]),
              "+f"(acc[nt][3])
            : "r"(a0), "r"(a1), "r"(a2), "r"(a3), "r"(b0), "r"(b1));
      }
    }

    const int n0 = R + g, n1 = n0 + 8;
    const float* mbase = mask + (size_t)(b & 63) * 4096;
#pragma unroll
    for (int nt = 0; nt < 8; nt++) {
      int m0 = nt * 8 + 2 * tg;
      int2 r0 = *reinterpret_cast<const int2*>(rel_idx + n0 * 64 + m0);
      int2 r1 = *reinterpret_cast<const int2*>(rel_idx + n1 * 64 + m0);
      float2 k0 = *reinterpret_cast<const float2*>(mbase + n0 * 64 + m0);
      float2 k1 = *reinterpret_cast<const float2*>(mbase + n1 * 64 + m0);
      float2 o0, o1;
      o0.x = acc[nt][0] + __ldg(rpb + r0.x * 6 + h) + k0.x;
      o0.y = acc[nt][1] + __ldg(rpb + r0.y * 6 + h) + k0.y;
      o1.x = acc[nt][2] + __ldg(rpb + r1.x * 6 + h) + k1.x;
      o1.y = acc[nt][3] + __ldg(rpb + r1.y * 6 + h) + k1.y;
      *reinterpret_cast<float2*>(sS + (h * 64 + n0) * SSP + m0) = o0;
      *reinterpret_cast<float2*>(sS + (h * 64 + n1) * SSP + m0) = o1;
    }
  }
  __syncthreads();

  // V into sV (Q region dead)
#pragma unroll
  for (int rep = 0; rep < 4; rep++) {
    int i = tid + rep * 768;
    int row = i / 48, f4 = (i % 48) << 2;
    *reinterpret_cast<float4*>(sV + row * QKP + f4) =
        *reinterpret_cast<const float4*>(win + (size_t)row * C3 + 384 + f4);
  }
  __syncthreads();

  // softmax + PV
  const int w = tid >> 5, lane = tid & 31;
  const int h = w >> 2;
  const int n = ((w & 3) << 4) | (lane >> 1);
  const int dh = lane & 1;
  const int dof = h * HDIM + dh * 16;

  const float* srow = sS + (h * 64 + n) * SSP;

  float rmax = -1e30f, rsum = 0.f;
  ull acc2[8];
#pragma unroll
  for (int d = 0; d < 8; d++) acc2[d] = 0ull;

#pragma unroll
  for (int mt = 0; mt < 64; mt += 16) {
    float s[16];
#pragma unroll
    for (int jj = 0; jj < 4; jj++) {
      float4 v = *reinterpret_cast<const float4*>(srow + mt + jj * 4);
      s[jj * 4 + 0] = v.x; s[jj * 4 + 1] = v.y;
      s[jj * 4 + 2] = v.z; s[jj * 4 + 3] = v.w;
    }
    float tmax = rmax;
#pragma unroll
    for (int j = 0; j < 16; j++) tmax = fmaxf(tmax, s[j]);
    float corr = __expf(rmax - tmax);
    rsum *= corr;
    ull corr2 = pk(corr, corr);
#pragma unroll
    for (int d = 0; d < 8; d++) acc2[d] = mul2(acc2[d], corr2);
#pragma unroll
    for (int j = 0; j < 16; j++) {
      float p = __expf(s[j] - tmax);
      rsum += p;
      ull p2 = pk(p, p);
      const ulonglong2* tv =
          reinterpret_cast<const ulonglong2*>(sV + (mt + j) * QKP + dof);
#pragma unroll
      for (int d4 = 0; d4 < 4; d4++) {
        ulonglong2 vv = tv[d4];
        fma2(acc2[2 * d4], p2, vv.x);
        fma2(acc2[2 * d4 + 1], p2, vv.y);
      }
    }
    rmax = tmax;
  }
  float inv = 1.f / rsum;

  // write output directly in the tiled tf32 A-layout for the proj GEMM
  const int n_global = b * 64 + n;
  const int mtile = n_global >> 7, mrow = n_global & 127;
  const int perm = (mrow & ~15) + 2 * (mrow & 7) + ((mrow >> 3) & 1);
  const int ktile = dof >> 4;
  uint32_t* dst = reinterpret_cast<uint32_t*>(g_ap) +
                  ((size_t)(mtile * NKT + ktile) * 16) * AP + perm;
#pragma unroll
  for (int d = 0; d < 8; d++) {
    float2 v = upk(acc2[d]);
    dst[(2 * d) * AP] = f2tf32(v.x * inv);
    dst[(2 * d + 1) * AP] = f2tf32(v.y * inv);
  }
}

// ---------------------------------------------------------------------------
extern "C" void kernel_launch(void* const* d_in, const int* in_sizes, int n_in,
                              void* d_out, int out_size) {
  const float* x      = (const float*)d_in[0];
  const float* mask   = (const float*)d_in[1];
  const float* qkv_w  = (const float*)d_in[2];
  const float* qkv_b  = (const float*)d_in[3];
  const float* dw_w   = (const float*)d_in[4];
  const float* dw_b   = (const float*)d_in[5];
  const float* rpb    = (const float*)d_in[6];
  const int*   rel    = (const int*)d_in[7];
  const float* proj_w = (const float*)d_in[8];
  const float* proj_b = (const float*)d_in[9];
  float* out = (float*)d_out;

  float *gt_ptr, *gax, *gap, *gbq, *gbp;
  cudaGetSymbolAddress((void**)&gt_ptr, g_t);
  cudaGetSymbolAddress((void**)&gax, g_ax);
  cudaGetSymbolAddress((void**)&gap, g_ap);
  cudaGetSymbolAddress((void**)&gbq, g_bq);
  cudaGetSymbolAddress((void**)&gbp, g_bp);

  // 0) operand prep (tf32 + tile permute)
  prep_a_kernel<<<dim3(48, 1024), 128>>>(x, gax);
  prep_w_kernel<<<dim3(48, 3), 192>>>(qkv_w, gbq);
  prep_w_kernel<<<dim3(48, 1), 192>>>(proj_w, gbp);

  // 1) QKV GEMM: g_t = x @ qkv_w^T + qkv_b
  tf32_gemm2<<<dim3(3, 1024), 192>>>(gax, gbq, qkv_b, gt_ptr, C3);

  // 2) depthwise conv: g_c
  const int conv_smem = 10 * 64 * CW * 4;
  cudaFuncSetAttribute(conv_kernel,
                       cudaFuncAttributeMaxDynamicSharedMemorySize, conv_smem);
  dim3 g2(C3 / CW, B_TOT / WB);
  conv_kernel<<<g2, 512, conv_smem>>>(dw_w, dw_b);

  // 3) window attention -> g_ap (tiled tf32)
  cudaFuncSetAttribute(attn_kernel,
                       cudaFuncAttributeMaxDynamicSharedMemorySize, ATT_SMEM);
  attn_kernel<<<B_TOT, 768, ATT_SMEM>>>(mask, rpb, rel);

  // 4) projection GEMM: out = attn_out @ proj_w^T + proj_b
  tf32_gemm2<<<dim3(1, 1024), 192>>>(gap, gbp, proj_b, out, C_DIM);
}

// round 8
// speedup vs baseline: 2.4438x; 1.1138x over previous
#include <cuda_runtime.h>
#include <cuda_fp16.h>
#include <cstdint>

#define B_TOT 2048
#define N_WIN 64
#define C_DIM 192
#define KDIM 192
#define C3 576
#define HEADS 6
#define HDIM 32
#define SCALE_F 0.17677669529663687f

// GEMM tile geometry
#define AP 136
#define BP 392
#define AT_WORDS (16 * AP)
#define BT_WORDS (8 * BP)
#define NKT 12

// scratch (fp16 intermediates)
__device__ __align__(16) __half g_t[(size_t)B_TOT * N_WIN * C3];
__device__ __align__(16) __half g_c[(size_t)B_TOT * N_WIN * C3];
__device__ __align__(16) float g_ax[(size_t)1024 * NKT * AT_WORDS];
__device__ __align__(16) float g_ap[(size_t)1024 * NKT * AT_WORDS];
__device__ __align__(16) float g_bq[3 * NKT * BT_WORDS];
__device__ __align__(16) float g_bp[1 * NKT * BT_WORDS];

// ------------------------------- helpers ----------------------------------
__device__ __forceinline__ uint32_t f2tf32(float x) {
  uint32_t r;
  asm("cvt.rna.tf32.f32 %0, %1;" : "=r"(r) : "f"(x));
  return r;
}

typedef unsigned long long ull;

__device__ __forceinline__ ull pk(float x, float y) {
  ull r;
  asm("mov.b64 %0, {%1, %2};" : "=l"(r) : "f"(x), "f"(y));
  return r;
}
__device__ __forceinline__ float2 upk(ull v) {
  float2 r;
  asm("mov.b64 {%0, %1}, %2;" : "=f"(r.x), "=f"(r.y) : "l"(v));
  return r;
}
__device__ __forceinline__ void fma2(ull& d, ull a, ull b) {
  asm("fma.rn.f32x2 %0, %1, %2, %3;" : "=l"(d) : "l"(a), "l"(b), "l"(d));
}
__device__ __forceinline__ ull mul2(ull a, ull b) {
  ull d;
  asm("mul.rn.f32x2 %0, %1, %2;" : "=l"(d) : "l"(a), "l"(b));
  return d;
}
__device__ __forceinline__ ull add2(ull a, ull b) {
  ull d;
  asm("add.rn.f32x2 %0, %1, %2;" : "=l"(d) : "l"(a), "l"(b));
  return d;
}
__device__ __forceinline__ ull ld2h(const __half* p) {
  __half2 h = *reinterpret_cast<const __half2*>(p);
  float2 f = __half22float2(h);
  return pk(f.x, f.y);
}
__device__ __forceinline__ void cp16(uint32_t s, const void* g) {
  asm volatile("cp.async.cg.shared.global [%0], [%1], 16;" ::"r"(s), "l"(g));
}
__device__ __forceinline__ void cp_commit() {
  asm volatile("cp.async.commit_group;");
}
template <int N>
__device__ __forceinline__ void cp_wait() {
  asm volatile("cp.async.wait_group %0;" ::"n"(N));
}

// ---------------------------------------------------------------------------
// Prep kernels (unchanged layouts)
// ---------------------------------------------------------------------------
__global__ __launch_bounds__(128) void prep_a_kernel(
    const float* __restrict__ src, float* __restrict__ dst) {
  const int m = threadIdx.x;
  const int mtile = blockIdx.y;
  const int k0 = blockIdx.x * 4;
  float4 v = *reinterpret_cast<const float4*>(
      src + ((size_t)mtile * 128 + m) * KDIM + k0);
  const int ktile = k0 >> 4, kk = k0 & 15;
  const int perm = (m & ~15) + 2 * (m & 7) + ((m >> 3) & 1);
  uint32_t* d = reinterpret_cast<uint32_t*>(dst) +
                ((size_t)(mtile * NKT + ktile) * 16 + kk) * AP + perm;
  d[0] = f2tf32(v.x);
  d[AP] = f2tf32(v.y);
  d[2 * AP] = f2tf32(v.z);
  d[3 * AP] = f2tf32(v.w);
}

__global__ __launch_bounds__(192) void prep_w_kernel(
    const float* __restrict__ src, float* __restrict__ dst) {
  const int nl = threadIdx.x;
  const int ntile = blockIdx.y;
  const int k0 = blockIdx.x * 4;
  float4 v = *reinterpret_cast<const float4*>(
      src + ((size_t)ntile * 192 + nl) * KDIM + k0);
  const int ktile = k0 >> 4, kk = k0 & 15;
  const int pr0 = (kk >> 3) * 4;
  const int khalf = (kk >> 2) & 1;
  uint32_t* d = reinterpret_cast<uint32_t*>(dst) +
                ((size_t)(ntile * NKT + ktile) * 8 + pr0) * BP + 2 * nl + khalf;
  d[0] = f2tf32(v.x);
  d[BP] = f2tf32(v.y);
  d[2 * BP] = f2tf32(v.z);
  d[3 * BP] = f2tf32(v.w);
}

// ---------------------------------------------------------------------------
// tf32 GEMM v2 (templated output type: fp16 for QKV, fp32 for proj)
// ---------------------------------------------------------------------------
template <typename OutT>
__global__ __launch_bounds__(192) void tf32_gemm2(
    const float* __restrict__ At, const float* __restrict__ Bt,
    const float* __restrict__ bias, OutT* __restrict__ out, int Ncols) {
  __shared__ __align__(16) uint32_t Ab[2][AT_WORDS];
  __shared__ __align__(16) uint32_t Bb[2][BT_WORDS];

  const int tid = threadIdx.x;
  const int wid = tid >> 5, lane = tid & 31;
  const int wm = (wid & 1) * 64;
  const int wn = (wid >> 1) * 64;
  const int g = lane >> 2, tg = lane & 3;
  const int m0 = blockIdx.y * 128;
  const int n0 = blockIdx.x * 192;

  const uint32_t* gA =
      reinterpret_cast<const uint32_t*>(At) + (size_t)blockIdx.y * NKT * AT_WORDS;
  const uint32_t* gB =
      reinterpret_cast<const uint32_t*>(Bt) + (size_t)blockIdx.x * NKT * BT_WORDS;

  float acc[4][8][4];
#pragma unroll
  for (int mt = 0; mt < 4; mt++)
#pragma unroll
    for (int nt = 0; nt < 8; nt++)
#pragma unroll
      for (int r = 0; r < 4; r++) acc[mt][nt][r] = 0.f;

  auto copy_tile = [&](int kt, int buf) {
    const uint32_t* a = gA + (size_t)kt * AT_WORDS;
    const uint32_t* bsrc = gB + (size_t)kt * BT_WORDS;
    uint32_t sa = (uint32_t)__cvta_generic_to_shared(&Ab[buf][0]);
    uint32_t sb = (uint32_t)__cvta_generic_to_shared(&Bb[buf][0]);
    for (int i = tid * 4; i < AT_WORDS; i += 192 * 4) cp16(sa + i * 4, a + i);
    for (int i = tid * 4; i < BT_WORDS; i += 192 * 4) cp16(sb + i * 4, bsrc + i);
  };

  auto mma_tile = [&](int buf) {
    const uint32_t* Asb = Ab[buf];
    const uint32_t* Bsb = Bb[buf];
#pragma unroll
    for (int ks = 0; ks < 16; ks += 8) {
      uint32_t af[4][4], bf[8][2];
#pragma unroll
      for (int mt = 0; mt < 4; mt++) {
        const uint32_t* ap = Asb + (ks + tg) * AP + wm + mt * 16 + 2 * g;
        ull v01 = *reinterpret_cast<const ull*>(ap);
        ull v23 = *reinterpret_cast<const ull*>(ap + 4 * AP);
        af[mt][0] = (uint32_t)v01; af[mt][1] = (uint32_t)(v01 >> 32);
        af[mt][2] = (uint32_t)v23; af[mt][3] = (uint32_t)(v23 >> 32);
      }
#pragma unroll
      for (int nt = 0; nt < 8; nt++) {
        const uint32_t* bp =
            Bsb + ((ks >> 3) * 4 + tg) * BP + 2 * (wn + nt * 8 + g);
        ull v = *reinterpret_cast<const ull*>(bp);
        bf[nt][0] = (uint32_t)v; bf[nt][1] = (uint32_t)(v >> 32);
      }
#pragma unroll
      for (int mt = 0; mt < 4; mt++)
#pragma unroll
        for (int nt = 0; nt < 8; nt++) {
          asm volatile(
              "mma.sync.aligned.m16n8k8.row.col.f32.tf32.tf32.f32 "
              "{%0,%1,%2,%3}, {%4,%5,%6,%7}, {%8,%9}, {%0,%1,%2,%3};"
              : "+f"(acc[mt][nt][0]), "+f"(acc[mt][nt][1]),
                "+f"(acc[mt][nt][2]), "+f"(acc[mt][nt][3])
              : "r"(af[mt][0]), "r"(af[mt][1]), "r"(af[mt][2]),
                "r"(af[mt][3]), "r"(bf[nt][0]), "r"(bf[nt][1]));
        }
    }
  };

  copy_tile(0, 0);
  cp_commit();

#pragma unroll 1
  for (int kt = 0; kt < NKT; kt += 2) {
    copy_tile(kt + 1, 1);
    cp_commit();
    cp_wait<1>();
    __syncthreads();
    mma_tile(0);
    __syncthreads();
    if (kt + 2 < NKT) {
      copy_tile(kt + 2, 0);
      cp_commit();
      cp_wait<1>();
    } else {
      cp_wait<0>();
    }
    __syncthreads();
    mma_tile(1);
    __syncthreads();
  }

#pragma unroll
  for (int mt = 0; mt < 4; mt++) {
#pragma unroll
    for (int nt = 0; nt < 8; nt++) {
      int row = m0 + wm + mt * 16 + g;
      int col = n0 + wn + nt * 8 + 2 * tg;
      float2 bv = *reinterpret_cast<const float2*>(bias + col);
      float x0 = acc[mt][nt][0] + bv.x, y0 = acc[mt][nt][1] + bv.y;
      float x1 = acc[mt][nt][2] + bv.x, y1 = acc[mt][nt][3] + bv.y;
      if constexpr (sizeof(OutT) == 2) {
        *reinterpret_cast<__half2*>(out + (size_t)row * Ncols + col) =
            __floats2half2_rn(x0, y0);
        *reinterpret_cast<__half2*>(out + (size_t)(row + 8) * Ncols + col) =
            __floats2half2_rn(x1, y1);
      } else {
        *reinterpret_cast<float2*>(out + (size_t)row * Ncols + col) =
            make_float2(x0, y0);
        *reinterpret_cast<float2*>(out + (size_t)(row + 8) * Ncols + col) =
            make_float2(x1, y1);
      }
    }
  }
}

// ---------------------------------------------------------------------------
// Depthwise 3x3 conv: fp16 in/out, f32x2 math. smem 40 KB.
// ---------------------------------------------------------------------------
#define CW 32
#define WB 8

__global__ __launch_bounds__(512, 2) void conv_kernel(
    const float* __restrict__ dw_w, const float* __restrict__ dw_b) {
  extern __shared__ __half sh[];
  const int tid = threadIdx.x;
  const int c0 = blockIdx.x * CW;
  const int b0 = blockIdx.y * WB;

  // load (WB+2) windows x 64 rows x 32 ch fp16 (16B chunks)
#pragma unroll
  for (int rep = 0; rep < 5; rep++) {
    int i = tid + rep * 512;          // 0..2559
    int w = i >> 8;
    int n = (i >> 2) & 63;
    int f = i & 3;
    int gw = b0 - 1 + w;
    uint4 v = make_uint4(0, 0, 0, 0);
    if ((unsigned)gw < (unsigned)B_TOT)
      v = *reinterpret_cast<const uint4*>(
          g_t + ((size_t)gw * 64 + n) * C3 + c0 + f * 8);
    *reinterpret_cast<uint4*>(sh + (w * 64 + n) * 32 + f * 8) = v;
  }
  __syncthreads();

  const int cp = tid & 15;
  const int wo = (tid >> 4) & 7;
  const int nh = tid >> 7;
  const int nst = nh << 4;
  const int gb = b0 + wo;
  const int c = c0 + 2 * cp;

  ull w2[9];
#pragma unroll
  for (int t = 0; t < 9; t++)
    w2[t] = pk(__ldg(dw_w + c * 9 + t), __ldg(dw_w + c * 9 + 9 + t));
  ull bia2 = pk(__ldg(dw_b + c), __ldg(dw_b + c + 1));

  const __half* rowp[3];
#pragma unroll
  for (int r = 0; r < 3; r++) rowp[r] = sh + ((wo + r) * 64) * 32 + 2 * cp;

  ull xm[3], x0[3];
#pragma unroll
  for (int r = 0; r < 3; r++) {
    xm[r] = (nst > 0) ? ld2h(rowp[r] + ((nst - 1) << 5)) : 0ull;
    x0[r] = ld2h(rowp[r] + (nst << 5));
  }
  __half* outp = g_c + ((size_t)gb * 64 + nst) * C3 + c;
#pragma unroll 4
  for (int n = nst; n < nst + 16; n++) {
    ull xp[3];
#pragma unroll
    for (int r = 0; r < 3; r++)
      xp[r] = (n + 1 < 64) ? ld2h(rowp[r] + ((n + 1) << 5)) : 0ull;
    ull s0 = mul2(xm[0], w2[0]);
    fma2(s0, x0[0], w2[1]); fma2(s0, xp[0], w2[2]);
    ull s1 = mul2(xm[1], w2[3]);
    fma2(s1, x0[1], w2[4]); fma2(s1, xp[1], w2[5]);
    ull s2 = mul2(xm[2], w2[6]);
    fma2(s2, x0[2], w2[7]); fma2(s2, xp[2], w2[8]);
    float2 sv = upk(add2(add2(s0, s1), add2(s2, bia2)));
    *reinterpret_cast<__half2*>(outp) = __floats2half2_rn(sv.x, sv.y);
    outp += C3;
#pragma unroll
    for (int r = 0; r < 3; r++) { xm[r] = x0[r]; x0[r] = xp[r]; }
  }
}

// ---------------------------------------------------------------------------
// Window attention, split by head-pair: grid (2048, 3), 256 threads.
//   smem: sQ 2x64x36 tf32 (reused as sV 64x72 f32), sK 2x64x36 tf32,
//         sS 2x64x68 f32. Total 71680 B -> 3 CTAs/SM.
// ---------------------------------------------------------------------------
#define QP 36
#define VP 72
#define SSP 68
#define SK_OFF (2 * 64 * QP)
#define SS_OFF (2 * SK_OFF)
#define ATT_SMEM ((2 * 2 * 64 * QP + 2 * 64 * SSP) * 4)

__global__ __launch_bounds__(256, 3) void attn_kernel(
    const float* __restrict__ mask, const float* __restrict__ rpb,
    const int* __restrict__ rel_idx) {
  extern __shared__ float sm[];
  uint32_t* sQ = reinterpret_cast<uint32_t*>(sm);
  uint32_t* sK = reinterpret_cast<uint32_t*>(sm + SK_OFF);
  float* sS = sm + SS_OFF;
  float* sV = sm;  // overwrites sQ after phase 1

  const int tid = threadIdx.x;
  const int b = blockIdx.x;
  const int h2 = blockIdx.y;           // head-pair: heads 2*h2, 2*h2+1
  const __half* win = g_c + (size_t)b * 64 * C3 + h2 * 64;

  // ---- phase 0: load Q, K (fp16) -> tf32 smem -----------------------------
#pragma unroll
  for (int rep = 0; rep < 4; rep++) {
    int i = tid + rep * 256;           // 0..1023
    int row = i >> 4;
    int c16 = i & 15;
    int qk = c16 >> 3;                 // 0 = Q, 1 = K
    int f = c16 & 7;                   // 16B chunk (8 halves)
    const __half* src = win + (size_t)row * C3 + qk * 192 + f * 8;
    uint32_t* dst = (qk ? sK : sQ) + ((f >> 2) * 64 + row) * QP + (f & 3) * 8;
#pragma unroll
    for (int e = 0; e < 4; e++) {
      __half2 h = *reinterpret_cast<const __half2*>(src + 2 * e);
      float2 fv = __half22float2(h);
      dst[2 * e] = f2tf32(fv.x);
      dst[2 * e + 1] = f2tf32(fv.y);
    }
  }
  __syncthreads();

  // ---- phase 1: S = (QK^T)*scale + bias + mask ----------------------------
  {
    const int w = tid >> 5, lane = tid & 31;
    const int h = w >> 2, R = (w & 3) << 4;
    const int g = lane >> 2, tg = lane & 3;

    float acc[8][4];
#pragma unroll
    for (int nt = 0; nt < 8; nt++)
#pragma unroll
      for (int r = 0; r < 4; r++) acc[nt][r] = 0.f;

    const uint32_t* qb = sQ + (h * 64 + R + g) * QP + tg;
#pragma unroll
    for (int kt = 0; kt < 4; kt++) {
      uint32_t a0 = qb[kt * 8];
      uint32_t a1 = qb[kt * 8 + 8 * QP];
      uint32_t a2 = qb[kt * 8 + 4];
      uint32_t a3 = qb[kt * 8 + 8 * QP + 4];
#pragma unroll
      for (int nt = 0; nt < 8; nt++) {
        const uint32_t* kb = sK + (h * 64 + nt * 8 + g) * QP + kt * 8 + tg;
        uint32_t b0 = kb[0], b1 = kb[4];
        asm volatile(
            "mma.sync.aligned.m16n8k8.row.col.f32.tf32.tf32.f32 "
            "{%0,%1,%2,%3}, {%4,%5,%6,%7}, {%8,%9}, {%0,%1,%2,%3};"
            : "+f"(acc[nt][0]), "+f"(acc[nt][1]), "+f"(acc[nt][2]),
              "+f"(acc[nt][3])
            : "r"(a0), "r"(a1), "r"(a2), "r"(a3), "r"(b0), "r"(b1));
      }
    }

    const int n0 = R + g, n1 = n0 + 8;
    const int gh = 2 * h2 + h;
    const float* mbase = mask + (size_t)(b & 63) * 4096;
#pragma unroll
    for (int nt = 0; nt < 8; nt++) {
      int m0 = nt * 8 + 2 * tg;
      int2 r0 = *reinterpret_cast<const int2*>(rel_idx + n0 * 64 + m0);
      int2 r1 = *reinterpret_cast<const int2*>(rel_idx + n1 * 64 + m0);
      float2 k0 = *reinterpret_cast<const float2*>(mbase + n0 * 64 + m0);
      float2 k1 = *reinterpret_cast<const float2*>(mbase + n1 * 64 + m0);
      float2 o0, o1;
      o0.x = fmaf(acc[nt][0], SCALE_F, __ldg(rpb + r0.x * 6 + gh) + k0.x);
      o0.y = fmaf(acc[nt][1], SCALE_F, __ldg(rpb + r0.y * 6 + gh) + k0.y);
      o1.x = fmaf(acc[nt][2], SCALE_F, __ldg(rpb + r1.x * 6 + gh) + k1.x);
      o1.y = fmaf(acc[nt][3], SCALE_F, __ldg(rpb + r1.y * 6 + gh) + k1.y);
      *reinterpret_cast<float2*>(sS + (h * 64 + n0) * SSP + m0) = o0;
      *reinterpret_cast<float2*>(sS + (h * 64 + n1) * SSP + m0) = o1;
    }
  }
  __syncthreads();

  // ---- load V (fp16) -> f32 smem (sQ region is dead) ----------------------
#pragma unroll
  for (int rep = 0; rep < 2; rep++) {
    int i = tid + rep * 256;           // 0..511
    int row = i >> 3;
    int f = i & 7;
    const __half* src = win + (size_t)row * C3 + 384 + f * 8;
    float* dst = sV + row * VP + f * 8;
#pragma unroll
    for (int e = 0; e < 4; e++) {
      __half2 h = *reinterpret_cast<const __half2*>(src + 2 * e);
      float2 fv = __half22float2(h);
      dst[2 * e] = fv.x;
      dst[2 * e + 1] = fv.y;
    }
  }
  __syncthreads();

  // ---- phase 2: softmax + PV ----------------------------------------------
  const int h = tid >> 7;
  const int n = (tid >> 1) & 63;
  const int dh = tid & 1;
  const int dof = h * 32 + dh * 16;    // into sV row (64 cols)

  const float* srow = sS + (h * 64 + n) * SSP;

  float rmax = -1e30f, rsum = 0.f;
  ull acc2[8];
#pragma unroll
  for (int d = 0; d < 8; d++) acc2[d] = 0ull;

#pragma unroll
  for (int mt = 0; mt < 64; mt += 16) {
    float s[16];
#pragma unroll
    for (int jj = 0; jj < 4; jj++) {
      float4 v = *reinterpret_cast<const float4*>(srow + mt + jj * 4);
      s[jj * 4 + 0] = v.x; s[jj * 4 + 1] = v.y;
      s[jj * 4 + 2] = v.z; s[jj * 4 + 3] = v.w;
    }
    float tmax = rmax;
#pragma unroll
    for (int j = 0; j < 16; j++) tmax = fmaxf(tmax, s[j]);
    float corr = __expf(rmax - tmax);
    rsum *= corr;
    ull corr2 = pk(corr, corr);
#pragma unroll
    for (int d = 0; d < 8; d++) acc2[d] = mul2(acc2[d], corr2);
#pragma unroll
    for (int j = 0; j < 16; j++) {
      float p = __expf(s[j] - tmax);
      rsum += p;
      ull p2 = pk(p, p);
      const ulonglong2* tv =
          reinterpret_cast<const ulonglong2*>(sV + (mt + j) * VP + dof);
#pragma unroll
      for (int d4 = 0; d4 < 4; d4++) {
        ulonglong2 vv = tv[d4];
        fma2(acc2[2 * d4], p2, vv.x);
        fma2(acc2[2 * d4 + 1], p2, vv.y);
      }
    }
    rmax = tmax;
  }
  float inv = 1.f / rsum;

  // write tiled tf32 A-layout for proj GEMM
  const int n_global = b * 64 + n;
  const int mtile = n_global >> 7, mrow = n_global & 127;
  const int perm = (mrow & ~15) + 2 * (mrow & 7) + ((mrow >> 3) & 1);
  const int ktile = (h2 * 64 + dof) >> 4;
  uint32_t* dst = reinterpret_cast<uint32_t*>(g_ap) +
                  ((size_t)(mtile * NKT + ktile) * 16) * AP + perm;
#pragma unroll
  for (int d = 0; d < 8; d++) {
    float2 v = upk(acc2[d]);
    dst[(2 * d) * AP] = f2tf32(v.x * inv);
    dst[(2 * d + 1) * AP] = f2tf32(v.y * inv);
  }
}

// ---------------------------------------------------------------------------
extern "C" void kernel_launch(void* const* d_in, const int* in_sizes, int n_in,
                              void* d_out, int out_size) {
  const float* x      = (const float*)d_in[0];
  const float* mask   = (const float*)d_in[1];
  const float* qkv_w  = (const float*)d_in[2];
  const float* qkv_b  = (const float*)d_in[3];
  const float* dw_w   = (const float*)d_in[4];
  const float* dw_b   = (const float*)d_in[5];
  const float* rpb    = (const float*)d_in[6];
  const int*   rel    = (const int*)d_in[7];
  const float* proj_w = (const float*)d_in[8];
  const float* proj_b = (const float*)d_in[9];
  float* out = (float*)d_out;

  __half* gt_ptr;
  float *gax, *gap, *gbq, *gbp;
  cudaGetSymbolAddress((void**)&gt_ptr, g_t);
  cudaGetSymbolAddress((void**)&gax, g_ax);
  cudaGetSymbolAddress((void**)&gap, g_ap);
  cudaGetSymbolAddress((void**)&gbq, g_bq);
  cudaGetSymbolAddress((void**)&gbp, g_bp);

  // 0) operand prep
  prep_a_kernel<<<dim3(48, 1024), 128>>>(x, gax);
  prep_w_kernel<<<dim3(48, 3), 192>>>(qkv_w, gbq);
  prep_w_kernel<<<dim3(48, 1), 192>>>(proj_w, gbp);

  // 1) QKV GEMM -> fp16 g_t
  tf32_gemm2<__half><<<dim3(3, 1024), 192>>>(gax, gbq, qkv_b, gt_ptr, C3);

  // 2) depthwise conv (fp16 in/out)
  const int conv_smem = 10 * 64 * CW * 2;  // 40960
  cudaFuncSetAttribute(conv_kernel,
                       cudaFuncAttributeMaxDynamicSharedMemorySize, conv_smem);
  dim3 g2(C3 / CW, B_TOT / WB);
  conv_kernel<<<g2, 512, conv_smem>>>(dw_w, dw_b);

  // 3) window attention (per head-pair) -> g_ap tiled tf32
  cudaFuncSetAttribute(attn_kernel,
                       cudaFuncAttributeMaxDynamicSharedMemorySize, ATT_SMEM);
  attn_kernel<<<dim3(B_TOT, 3), 256, ATT_SMEM>>>(mask, rpb, rel);

  // 4) projection GEMM -> fp32 out
  tf32_gemm2<float><<<dim3(1, 1024), 192>>>(gap, gbp, proj_b, out, C_DIM);
}

// round 9
// speedup vs baseline: 2.9185x; 1.1943x over previous
#include <cuda_runtime.h>
#include <cuda_fp16.h>
#include <cstdint>

#define B_TOT 2048
#define N_WIN 64
#define C_DIM 192
#define KDIM 192
#define C3 576
#define HEADS 6
#define HDIM 32
#define SCALE_F 0.17677669529663687f

// fp16 GEMM tile geometry (each 32-bit word packs a k-pair of halves)
#define AP2 136                 // A p-row pitch (words); 136 % 32 == 8
#define BP2 392                 // B pgrp-row pitch (words); 392 % 32 == 8
#define AT2_WORDS (8 * AP2)     // 1088 words per A k-tile (128 m x 16 k fp16)
#define BT2_WORDS (4 * BP2)     // 1568 words per B k-tile (192 n x 16 k fp16)
#define NKT 12                  // K = 192 = 12 x 16

// scratch
__device__ __align__(16) __half g_t[(size_t)B_TOT * N_WIN * C3];
__device__ __align__(16) __half g_c[(size_t)B_TOT * N_WIN * C3];
__device__ __align__(16) uint32_t g_ax[(size_t)1024 * NKT * AT2_WORDS];
__device__ __align__(16) uint32_t g_ap[(size_t)1024 * NKT * AT2_WORDS];
__device__ __align__(16) uint32_t g_bq[3 * NKT * BT2_WORDS];
__device__ __align__(16) uint32_t g_bp[1 * NKT * BT2_WORDS];

// ------------------------------- helpers ----------------------------------
typedef unsigned long long ull;

__device__ __forceinline__ uint32_t pkh(float x, float y) {
  __half2 h = __floats2half2_rn(x, y);
  return *reinterpret_cast<uint32_t*>(&h);
}
__device__ __forceinline__ ull pk(float x, float y) {
  ull r;
  asm("mov.b64 %0, {%1, %2};" : "=l"(r) : "f"(x), "f"(y));
  return r;
}
__device__ __forceinline__ float2 upk(ull v) {
  float2 r;
  asm("mov.b64 {%0, %1}, %2;" : "=f"(r.x), "=f"(r.y) : "l"(v));
  return r;
}
__device__ __forceinline__ void fma2(ull& d, ull a, ull b) {
  asm("fma.rn.f32x2 %0, %1, %2, %3;" : "=l"(d) : "l"(a), "l"(b), "l"(d));
}
__device__ __forceinline__ ull mul2(ull a, ull b) {
  ull d;
  asm("mul.rn.f32x2 %0, %1, %2;" : "=l"(d) : "l"(a), "l"(b));
  return d;
}
__device__ __forceinline__ ull add2(ull a, ull b) {
  ull d;
  asm("add.rn.f32x2 %0, %1, %2;" : "=l"(d) : "l"(a), "l"(b));
  return d;
}
__device__ __forceinline__ ull ld2h(const __half* p) {
  __half2 h = *reinterpret_cast<const __half2*>(p);
  float2 f = __half22float2(h);
  return pk(f.x, f.y);
}
__device__ __forceinline__ void cp16(uint32_t s, const void* g) {
  asm volatile("cp.async.cg.shared.global [%0], [%1], 16;" ::"r"(s), "l"(g));
}
__device__ __forceinline__ void cp_commit() {
  asm volatile("cp.async.commit_group;");
}
template <int N>
__device__ __forceinline__ void cp_wait() {
  asm volatile("cp.async.wait_group %0;" ::"n"(N));
}
#define MMA16(d, a, b)                                                       \
  asm volatile(                                                              \
      "mma.sync.aligned.m16n8k16.row.col.f32.f16.f16.f32 "                   \
      "{%0,%1,%2,%3}, {%4,%5,%6,%7}, {%8,%9}, {%0,%1,%2,%3};"                \
      : "+f"(d[0]), "+f"(d[1]), "+f"(d[2]), "+f"(d[3])                       \
      : "r"(a[0]), "r"(a[1]), "r"(a[2]), "r"(a[3]), "r"(b[0]), "r"(b[1]))

// ---------------------------------------------------------------------------
// Prep kernels: fp32 -> packed fp16, GEMM-native tile layouts.
// A: word[(mtile*NKT+kt)*8 + p][perm(m)], p = (k within tile)/2,
//    perm(m) = (m&~15) + 2*(m&7) + ((m>>3)&1), word = {A[m][2p],A[m][2p+1]}
// B: word[(ntile*NKT+kt)*4 + (p&3)][2n + (p>>2)]
// ---------------------------------------------------------------------------
__global__ __launch_bounds__(128) void prep_a_kernel(
    const float* __restrict__ src, uint32_t* __restrict__ dst) {
  const int m = threadIdx.x;
  const int mtile = blockIdx.y;
  const int k0 = blockIdx.x * 4;
  float4 v = *reinterpret_cast<const float4*>(
      src + ((size_t)mtile * 128 + m) * KDIM + k0);
  const int ktile = k0 >> 4;
  const int pl = (k0 >> 1) & 7;  // 0,2,4,6
  const int perm = (m & ~15) + 2 * (m & 7) + ((m >> 3) & 1);
  uint32_t* d = dst + ((size_t)(mtile * NKT + ktile) * 8 + pl) * AP2 + perm;
  d[0] = pkh(v.x, v.y);
  d[AP2] = pkh(v.z, v.w);
}

__global__ __launch_bounds__(192) void prep_w_kernel(
    const float* __restrict__ src, uint32_t* __restrict__ dst) {
  const int nl = threadIdx.x;
  const int ntile = blockIdx.y;
  const int k0 = blockIdx.x * 4;
  float4 v = *reinterpret_cast<const float4*>(
      src + ((size_t)ntile * 192 + nl) * KDIM + k0);
  const int ktile = k0 >> 4;
  const int pl = (k0 >> 1) & 7;  // 0,2,4,6
  const int pgrp = pl & 3, sel = pl >> 2;
  uint32_t* d = dst + ((size_t)(ntile * NKT + ktile) * 4 + pgrp) * BP2 +
                2 * nl + sel;
  d[0] = pkh(v.x, v.y);
  d[BP2] = pkh(v.z, v.w);
}

// ---------------------------------------------------------------------------
// fp16 GEMM: out[m,n] = sum_k A[m,k] W[n,k] + bias[n]. Block 128x192,
// 192 thr, 6 warps of 64x64, m16n8k16, cp.async double-buffered.
// ---------------------------------------------------------------------------
template <typename OutT>
__global__ __launch_bounds__(192) void hgemm(
    const uint32_t* __restrict__ At, const uint32_t* __restrict__ Bt,
    const float* __restrict__ bias, OutT* __restrict__ out, int Ncols) {
  __shared__ __align__(16) uint32_t Ab[2][AT2_WORDS];
  __shared__ __align__(16) uint32_t Bb[2][BT2_WORDS];

  const int tid = threadIdx.x;
  const int wid = tid >> 5, lane = tid & 31;
  const int wm = (wid & 1) * 64;
  const int wn = (wid >> 1) * 64;
  const int g = lane >> 2, tg = lane & 3;
  const int m0 = blockIdx.y * 128;
  const int n0 = blockIdx.x * 192;

  const uint32_t* gA = At + (size_t)blockIdx.y * NKT * AT2_WORDS;
  const uint32_t* gB = Bt + (size_t)blockIdx.x * NKT * BT2_WORDS;

  float acc[4][8][4];
#pragma unroll
  for (int mt = 0; mt < 4; mt++)
#pragma unroll
    for (int nt = 0; nt < 8; nt++)
#pragma unroll
      for (int r = 0; r < 4; r++) acc[mt][nt][r] = 0.f;

  auto copy_tile = [&](int kt, int buf) {
    const uint32_t* a = gA + (size_t)kt * AT2_WORDS;
    const uint32_t* bsrc = gB + (size_t)kt * BT2_WORDS;
    uint32_t sa = (uint32_t)__cvta_generic_to_shared(&Ab[buf][0]);
    uint32_t sb = (uint32_t)__cvta_generic_to_shared(&Bb[buf][0]);
    for (int i = tid * 4; i < AT2_WORDS; i += 192 * 4) cp16(sa + i * 4, a + i);
    for (int i = tid * 4; i < BT2_WORDS; i += 192 * 4) cp16(sb + i * 4, bsrc + i);
  };

  auto mma_tile = [&](int buf) {
    const uint32_t* Asb = Ab[buf];
    const uint32_t* Bsb = Bb[buf];
    uint32_t af[4][4], bf[8][2];
#pragma unroll
    for (int mt = 0; mt < 4; mt++) {
      const uint32_t* ap = Asb + tg * AP2 + wm + mt * 16 + 2 * g;
      ull v01 = *reinterpret_cast<const ull*>(ap);
      ull v23 = *reinterpret_cast<const ull*>(ap + 4 * AP2);
      af[mt][0] = (uint32_t)v01; af[mt][1] = (uint32_t)(v01 >> 32);
      af[mt][2] = (uint32_t)v23; af[mt][3] = (uint32_t)(v23 >> 32);
    }
#pragma unroll
    for (int nt = 0; nt < 8; nt++) {
      const uint32_t* bp = Bsb + tg * BP2 + 2 * (wn + nt * 8 + g);
      ull v = *reinterpret_cast<const ull*>(bp);
      bf[nt][0] = (uint32_t)v; bf[nt][1] = (uint32_t)(v >> 32);
    }
#pragma unroll
    for (int mt = 0; mt < 4; mt++)
#pragma unroll
      for (int nt = 0; nt < 8; nt++) MMA16(acc[mt][nt], af[mt], bf[nt]);
  };

  copy_tile(0, 0);
  cp_commit();

#pragma unroll 1
  for (int kt = 0; kt < NKT; kt += 2) {
    copy_tile(kt + 1, 1);
    cp_commit();
    cp_wait<1>();
    __syncthreads();
    mma_tile(0);
    __syncthreads();
    if (kt + 2 < NKT) {
      copy_tile(kt + 2, 0);
      cp_commit();
      cp_wait<1>();
    } else {
      cp_wait<0>();
    }
    __syncthreads();
    mma_tile(1);
    __syncthreads();
  }

#pragma unroll
  for (int mt = 0; mt < 4; mt++) {
#pragma unroll
    for (int nt = 0; nt < 8; nt++) {
      int row = m0 + wm + mt * 16 + g;
      int col = n0 + wn + nt * 8 + 2 * tg;
      float2 bv = *reinterpret_cast<const float2*>(bias + col);
      float x0 = acc[mt][nt][0] + bv.x, y0 = acc[mt][nt][1] + bv.y;
      float x1 = acc[mt][nt][2] + bv.x, y1 = acc[mt][nt][3] + bv.y;
      if constexpr (sizeof(OutT) == 2) {
        *reinterpret_cast<__half2*>(out + (size_t)row * Ncols + col) =
            __floats2half2_rn(x0, y0);
        *reinterpret_cast<__half2*>(out + (size_t)(row + 8) * Ncols + col) =
            __floats2half2_rn(x1, y1);
      } else {
        *reinterpret_cast<float2*>(out + (size_t)row * Ncols + col) =
            make_float2(x0, y0);
        *reinterpret_cast<float2*>(out + (size_t)(row + 8) * Ncols + col) =
            make_float2(x1, y1);
      }
    }
  }
}

// ---------------------------------------------------------------------------
// Depthwise 3x3 conv (unchanged from round 8)
// ---------------------------------------------------------------------------
#define CW 32
#define WB 8

__global__ __launch_bounds__(512, 2) void conv_kernel(
    const float* __restrict__ dw_w, const float* __restrict__ dw_b) {
  extern __shared__ __half sh[];
  const int tid = threadIdx.x;
  const int c0 = blockIdx.x * CW;
  const int b0 = blockIdx.y * WB;

#pragma unroll
  for (int rep = 0; rep < 5; rep++) {
    int i = tid + rep * 512;
    int w = i >> 8;
    int n = (i >> 2) & 63;
    int f = i & 3;
    int gw = b0 - 1 + w;
    uint4 v = make_uint4(0, 0, 0, 0);
    if ((unsigned)gw < (unsigned)B_TOT)
      v = *reinterpret_cast<const uint4*>(
          g_t + ((size_t)gw * 64 + n) * C3 + c0 + f * 8);
    *reinterpret_cast<uint4*>(sh + (w * 64 + n) * 32 + f * 8) = v;
  }
  __syncthreads();

  const int cp = tid & 15;
  const int wo = (tid >> 4) & 7;
  const int nh = tid >> 7;
  const int nst = nh << 4;
  const int gb = b0 + wo;
  const int c = c0 + 2 * cp;

  ull w2[9];
#pragma unroll
  for (int t = 0; t < 9; t++)
    w2[t] = pk(__ldg(dw_w + c * 9 + t), __ldg(dw_w + c * 9 + 9 + t));
  ull bia2 = pk(__ldg(dw_b + c), __ldg(dw_b + c + 1));

  const __half* rowp[3];
#pragma unroll
  for (int r = 0; r < 3; r++) rowp[r] = sh + ((wo + r) * 64) * 32 + 2 * cp;

  ull xm[3], x0[3];
#pragma unroll
  for (int r = 0; r < 3; r++) {
    xm[r] = (nst > 0) ? ld2h(rowp[r] + ((nst - 1) << 5)) : 0ull;
    x0[r] = ld2h(rowp[r] + (nst << 5));
  }
  __half* outp = g_c + ((size_t)gb * 64 + nst) * C3 + c;
#pragma unroll 4
  for (int n = nst; n < nst + 16; n++) {
    ull xp[3];
#pragma unroll
    for (int r = 0; r < 3; r++)
      xp[r] = (n + 1 < 64) ? ld2h(rowp[r] + ((n + 1) << 5)) : 0ull;
    ull s0 = mul2(xm[0], w2[0]);
    fma2(s0, x0[0], w2[1]); fma2(s0, xp[0], w2[2]);
    ull s1 = mul2(xm[1], w2[3]);
    fma2(s1, x0[1], w2[4]); fma2(s1, xp[1], w2[5]);
    ull s2 = mul2(xm[2], w2[6]);
    fma2(s2, x0[2], w2[7]); fma2(s2, xp[2], w2[8]);
    float2 sv = upk(add2(add2(s0, s1), add2(s2, bia2)));
    *reinterpret_cast<__half2*>(outp) = __floats2half2_rn(sv.x, sv.y);
    outp += C3;
#pragma unroll
    for (int r = 0; r < 3; r++) { xm[r] = x0[r]; x0[r] = xp[r]; }
  }
}

// ---------------------------------------------------------------------------
// Window attention per head-pair: grid (2048, 3), 256 threads.
// Phase 1: fp16 m16n8k16 QK^T. smem (words): sQ 2x16x72 = 2304,
// sK 2x2x4x136 = 2176, sV(reuse) 64x72 = 4608, sS 2x64x68 = 8704.
// Total (4608 + 8704) * 4 = 53248 B.
// ---------------------------------------------------------------------------
#define QP2 72
#define VP 72
#define SSP 68
#define SKW (4 * 136)
#define SK_OFF 2304
#define SS_OFF 4608
#define ATT_SMEM ((SS_OFF + 2 * 64 * SSP) * 4)

__global__ __launch_bounds__(256, 3) void attn_kernel(
    const float* __restrict__ mask, const float* __restrict__ rpb,
    const int* __restrict__ rel_idx) {
  extern __shared__ float sm[];
  uint32_t* sQ = reinterpret_cast<uint32_t*>(sm);
  uint32_t* sK = reinterpret_cast<uint32_t*>(sm) + SK_OFF;
  float* sS = sm + SS_OFF;
  float* sV = sm;  // overwrites sQ/sK after phase 1

  const int tid = threadIdx.x;
  const int b = blockIdx.x;
  const int h2 = blockIdx.y;
  const __half* win = g_c + (size_t)b * 64 * C3 + h2 * 64;

  // ---- phase 0: Q, K (fp16) -> packed-pair smem ---------------------------
#pragma unroll
  for (int rep = 0; rep < 4; rep++) {
    int i = tid + rep * 256;           // 0..1023
    int qk = i >> 9;
    int j = i & 511;
    int row = j >> 3;
    int f = j & 7;                     // chunk of 8 halves
    int h = f >> 2;
    uint4 v = *reinterpret_cast<const uint4*>(
        win + (size_t)row * C3 + qk * 192 + f * 8);
    uint32_t wv[4] = {v.x, v.y, v.z, v.w};
    if (qk == 0) {
      int p0 = (f & 3) * 4;
      int perm = (row & ~15) + 2 * (row & 7) + ((row >> 3) & 1);
      uint32_t* dst = sQ + h * (16 * QP2) + p0 * QP2 + perm;
#pragma unroll
      for (int e = 0; e < 4; e++) dst[e * QP2] = wv[e];
    } else {
      int fq = f & 3;
      int kt = fq >> 1, sel = fq & 1;
      uint32_t* dst = sK + h * (2 * SKW) + kt * SKW + 2 * row + sel;
#pragma unroll
      for (int e = 0; e < 4; e++) dst[e * 136] = wv[e];
    }
  }
  __syncthreads();

  // ---- phase 1: S = (QK^T)*scale + bias + mask ----------------------------
  {
    const int w = tid >> 5, lane = tid & 31;
    const int h = w >> 2, R = (w & 3) << 4;
    const int g = lane >> 2, tg = lane & 3;

    float acc[8][4];
#pragma unroll
    for (int nt = 0; nt < 8; nt++)
#pragma unroll
      for (int r = 0; r < 4; r++) acc[nt][r] = 0.f;

    const uint32_t* qb = sQ + h * (16 * QP2) + R + 2 * g;
    const uint32_t* kb0 = sK + h * (2 * SKW);
#pragma unroll
    for (int kt = 0; kt < 2; kt++) {
      uint32_t af[4];
      {
        const uint32_t* ap = qb + (8 * kt + tg) * QP2;
        ull v01 = *reinterpret_cast<const ull*>(ap);
        ull v23 = *reinterpret_cast<const ull*>(ap + 4 * QP2);
        af[0] = (uint32_t)v01; af[1] = (uint32_t)(v01 >> 32);
        af[2] = (uint32_t)v23; af[3] = (uint32_t)(v23 >> 32);
      }
#pragma unroll
      for (int nt = 0; nt < 8; nt++) {
        const uint32_t* bp = kb0 + kt * SKW + tg * 136 + 2 * (nt * 8 + g);
        ull v = *reinterpret_cast<const ull*>(bp);
        uint32_t bf[2] = {(uint32_t)v, (uint32_t)(v >> 32)};
        MMA16(acc[nt], af, bf);
      }
    }

    const int n0 = R + g, n1 = n0 + 8;
    const int gh = 2 * h2 + h;
    const float* mbase = mask + (size_t)(b & 63) * 4096;
#pragma unroll
    for (int nt = 0; nt < 8; nt++) {
      int m0 = nt * 8 + 2 * tg;
      int2 r0 = *reinterpret_cast<const int2*>(rel_idx + n0 * 64 + m0);
      int2 r1 = *reinterpret_cast<const int2*>(rel_idx + n1 * 64 + m0);
      float2 k0 = *reinterpret_cast<const float2*>(mbase + n0 * 64 + m0);
      float2 k1 = *reinterpret_cast<const float2*>(mbase + n1 * 64 + m0);
      float2 o0, o1;
      o0.x = fmaf(acc[nt][0], SCALE_F, __ldg(rpb + r0.x * 6 + gh) + k0.x);
      o0.y = fmaf(acc[nt][1], SCALE_F, __ldg(rpb + r0.y * 6 + gh) + k0.y);
      o1.x = fmaf(acc[nt][2], SCALE_F, __ldg(rpb + r1.x * 6 + gh) + k1.x);
      o1.y = fmaf(acc[nt][3], SCALE_F, __ldg(rpb + r1.y * 6 + gh) + k1.y);
      *reinterpret_cast<float2*>(sS + (h * 64 + n0) * SSP + m0) = o0;
      *reinterpret_cast<float2*>(sS + (h * 64 + n1) * SSP + m0) = o1;
    }
  }
  __syncthreads();

  // ---- load V (fp16) -> f32 smem (sQ/sK dead) -----------------------------
#pragma unroll
  for (int rep = 0; rep < 2; rep++) {
    int i = tid + rep * 256;
    int row = i >> 3;
    int f = i & 7;
    const __half* src = win + (size_t)row * C3 + 384 + f * 8;
    float* dst = sV + row * VP + f * 8;
#pragma unroll
    for (int e = 0; e < 4; e++) {
      __half2 h = *reinterpret_cast<const __half2*>(src + 2 * e);
      float2 fv = __half22float2(h);
      dst[2 * e] = fv.x;
      dst[2 * e + 1] = fv.y;
    }
  }
  __syncthreads();

  // ---- phase 2: softmax + PV ----------------------------------------------
  const int h = tid >> 7;
  const int n = (tid >> 1) & 63;
  const int dh = tid & 1;
  const int dof = h * 32 + dh * 16;

  const float* srow = sS + (h * 64 + n) * SSP;

  float rmax = -1e30f, rsum = 0.f;
  ull acc2[8];
#pragma unroll
  for (int d = 0; d < 8; d++) acc2[d] = 0ull;

#pragma unroll
  for (int mt = 0; mt < 64; mt += 16) {
    float s[16];
#pragma unroll
    for (int jj = 0; jj < 4; jj++) {
      float4 v = *reinterpret_cast<const float4*>(srow + mt + jj * 4);
      s[jj * 4 + 0] = v.x; s[jj * 4 + 1] = v.y;
      s[jj * 4 + 2] = v.z; s[jj * 4 + 3] = v.w;
    }
    float tmax = rmax;
#pragma unroll
    for (int j = 0; j < 16; j++) tmax = fmaxf(tmax, s[j]);
    float corr = __expf(rmax - tmax);
    rsum *= corr;
    ull corr2 = pk(corr, corr);
#pragma unroll
    for (int d = 0; d < 8; d++) acc2[d] = mul2(acc2[d], corr2);
#pragma unroll
    for (int j = 0; j < 16; j++) {
      float p = __expf(s[j] - tmax);
      rsum += p;
      ull p2 = pk(p, p);
      const ulonglong2* tv =
          reinterpret_cast<const ulonglong2*>(sV + (mt + j) * VP + dof);
#pragma unroll
      for (int d4 = 0; d4 < 4; d4++) {
        ulonglong2 vv = tv[d4];
        fma2(acc2[2 * d4], p2, vv.x);
        fma2(acc2[2 * d4 + 1], p2, vv.y);
      }
    }
    rmax = tmax;
  }
  float inv = 1.f / rsum;

  // write fp16 tiled A-layout for proj GEMM
  const int n_global = b * 64 + n;
  const int mtile = n_global >> 7, mrow = n_global & 127;
  const int perm = (mrow & ~15) + 2 * (mrow & 7) + ((mrow >> 3) & 1);
  const int ktile = (h2 * 64 + dof) >> 4;
  uint32_t* dst = g_ap + ((size_t)(mtile * NKT + ktile) * 8) * AP2 + perm;
#pragma unroll
  for (int d = 0; d < 8; d++) {
    float2 v = upk(acc2[d]);
    dst[d * AP2] = pkh(v.x * inv, v.y * inv);
  }
}

// ---------------------------------------------------------------------------
extern "C" void kernel_launch(void* const* d_in, const int* in_sizes, int n_in,
                              void* d_out, int out_size) {
  const float* x      = (const float*)d_in[0];
  const float* mask   = (const float*)d_in[1];
  const float* qkv_w  = (const float*)d_in[2];
  const float* qkv_b  = (const float*)d_in[3];
  const float* dw_w   = (const float*)d_in[4];
  const float* dw_b   = (const float*)d_in[5];
  const float* rpb    = (const float*)d_in[6];
  const int*   rel    = (const int*)d_in[7];
  const float* proj_w = (const float*)d_in[8];
  const float* proj_b = (const float*)d_in[9];
  float* out = (float*)d_out;

  __half* gt_ptr;
  uint32_t *gax, *gap, *gbq, *gbp;
  cudaGetSymbolAddress((void**)&gt_ptr, g_t);
  cudaGetSymbolAddress((void**)&gax, g_ax);
  cudaGetSymbolAddress((void**)&gap, g_ap);
  cudaGetSymbolAddress((void**)&gbq, g_bq);
  cudaGetSymbolAddress((void**)&gbp, g_bp);

  // 0) operand prep (fp16 pack + tile permute)
  prep_a_kernel<<<dim3(48, 1024), 128>>>(x, gax);
  prep_w_kernel<<<dim3(48, 3), 192>>>(qkv_w, gbq);
  prep_w_kernel<<<dim3(48, 1), 192>>>(proj_w, gbp);

  // 1) QKV GEMM -> fp16 g_t
  hgemm<__half><<<dim3(3, 1024), 192>>>(gax, gbq, qkv_b, gt_ptr, C3);

  // 2) depthwise conv (fp16 in/out)
  const int conv_smem = 10 * 64 * CW * 2;
  cudaFuncSetAttribute(conv_kernel,
                       cudaFuncAttributeMaxDynamicSharedMemorySize, conv_smem);
  dim3 g2(C3 / CW, B_TOT / WB);
  conv_kernel<<<g2, 512, conv_smem>>>(dw_w, dw_b);

  // 3) window attention (per head-pair) -> g_ap fp16 tiled
  cudaFuncSetAttribute(attn_kernel,
                       cudaFuncAttributeMaxDynamicSharedMemorySize, ATT_SMEM);
  attn_kernel<<<dim3(B_TOT, 3), 256, ATT_SMEM>>>(mask, rpb, rel);

  // 4) projection GEMM -> fp32 out
  hgemm<float><<<dim3(1, 1024), 192>>>(gap, gbp, proj_b, out, C_DIM);
}

// round 11
// speedup vs baseline: 3.3793x; 1.1579x over previous
#include <cuda_runtime.h>
#include <cuda_fp16.h>
#include <cstdint>

#define B_TOT 2048
#define N_WIN 64
#define C_DIM 192
#define KDIM 192
#define C3 576
#define HEADS 6
#define HDIM 32
#define SCALE_F 0.17677669529663687f

// fp16 GEMM tile geometry (each 32-bit word packs a k-pair of halves)
#define AP2 136
#define BP2 392
#define AT2_WORDS (8 * AP2)
#define BT2_WORDS (4 * BP2)
#define NKT 12

// scratch
__device__ __align__(16) __half g_t[(size_t)B_TOT * N_WIN * C3];
__device__ __align__(16) __half g_c[(size_t)B_TOT * N_WIN * C3];
__device__ __align__(16) uint32_t g_ax[(size_t)1024 * NKT * AT2_WORDS];
__device__ __align__(16) uint32_t g_ap[(size_t)1024 * NKT * AT2_WORDS];
__device__ __align__(16) uint32_t g_bq[3 * NKT * BT2_WORDS];
__device__ __align__(16) uint32_t g_bp[1 * NKT * BT2_WORDS];

// ------------------------------- helpers ----------------------------------
typedef unsigned long long ull;

__device__ __forceinline__ uint32_t pkh(float x, float y) {
  __half2 h = __floats2half2_rn(x, y);
  return *reinterpret_cast<uint32_t*>(&h);
}
__device__ __forceinline__ ull pk(float x, float y) {
  ull r;
  asm("mov.b64 %0, {%1, %2};" : "=l"(r) : "f"(x), "f"(y));
  return r;
}
__device__ __forceinline__ float2 upk(ull v) {
  float2 r;
  asm("mov.b64 {%0, %1}, %2;" : "=f"(r.x), "=f"(r.y) : "l"(v));
  return r;
}
__device__ __forceinline__ void fma2(ull& d, ull a, ull b) {
  asm("fma.rn.f32x2 %0, %1, %2, %3;" : "=l"(d) : "l"(a), "l"(b), "l"(d));
}
__device__ __forceinline__ ull mul2(ull a, ull b) {
  ull d;
  asm("mul.rn.f32x2 %0, %1, %2;" : "=l"(d) : "l"(a), "l"(b));
  return d;
}
__device__ __forceinline__ ull add2(ull a, ull b) {
  ull d;
  asm("add.rn.f32x2 %0, %1, %2;" : "=l"(d) : "l"(a), "l"(b));
  return d;
}
__device__ __forceinline__ ull ld2h(const __half* p) {
  __half2 h = *reinterpret_cast<const __half2*>(p);
  float2 f = __half22float2(h);
  return pk(f.x, f.y);
}
__device__ __forceinline__ void cp16(uint32_t s, const void* g) {
  asm volatile("cp.async.cg.shared.global [%0], [%1], 16;" ::"r"(s), "l"(g));
}
__device__ __forceinline__ void cp_commit() {
  asm volatile("cp.async.commit_group;");
}
template <int N>
__device__ __forceinline__ void cp_wait() {
  asm volatile("cp.async.wait_group %0;" ::"n"(N));
}
__device__ __forceinline__ uint32_t sptr(const void* p) {
  return (uint32_t)__cvta_generic_to_shared(p);
}
__device__ __forceinline__ void ldm_x4(uint32_t* r, uint32_t addr) {
  asm volatile(
      "ldmatrix.sync.aligned.m8n8.x4.shared.b16 {%0,%1,%2,%3}, [%4];"
      : "=r"(r[0]), "=r"(r[1]), "=r"(r[2]), "=r"(r[3]) : "r"(addr));
}
__device__ __forceinline__ void ldm_x4_t(uint32_t* r, uint32_t addr) {
  asm volatile(
      "ldmatrix.sync.aligned.m8n8.x4.trans.shared.b16 {%0,%1,%2,%3}, [%4];"
      : "=r"(r[0]), "=r"(r[1]), "=r"(r[2]), "=r"(r[3]) : "r"(addr));
}
#define MMA16(d, a, b)                                                       \
  asm volatile(                                                              \
      "mma.sync.aligned.m16n8k16.row.col.f32.f16.f16.f32 "                   \
      "{%0,%1,%2,%3}, {%4,%5,%6,%7}, {%8,%9}, {%0,%1,%2,%3};"                \
      : "+f"(d[0]), "+f"(d[1]), "+f"(d[2]), "+f"(d[3])                       \
      : "r"(a[0]), "r"(a[1]), "r"(a[2]), "r"(a[3]), "r"(b[0]), "r"(b[1]))

// ---------------------------------------------------------------------------
// Prep kernels (unchanged)
// ---------------------------------------------------------------------------
__global__ __launch_bounds__(128) void prep_a_kernel(
    const float* __restrict__ src, uint32_t* __restrict__ dst) {
  const int m = threadIdx.x;
  const int mtile = blockIdx.y;
  const int k0 = blockIdx.x * 4;
  float4 v = *reinterpret_cast<const float4*>(
      src + ((size_t)mtile * 128 + m) * KDIM + k0);
  const int ktile = k0 >> 4;
  const int pl = (k0 >> 1) & 7;
  const int perm = (m & ~15) + 2 * (m & 7) + ((m >> 3) & 1);
  uint32_t* d = dst + ((size_t)(mtile * NKT + ktile) * 8 + pl) * AP2 + perm;
  d[0] = pkh(v.x, v.y);
  d[AP2] = pkh(v.z, v.w);
}

__global__ __launch_bounds__(192) void prep_w_kernel(
    const float* __restrict__ src, uint32_t* __restrict__ dst) {
  const int nl = threadIdx.x;
  const int ntile = blockIdx.y;
  const int k0 = blockIdx.x * 4;
  float4 v = *reinterpret_cast<const float4*>(
      src + ((size_t)ntile * 192 + nl) * KDIM + k0);
  const int ktile = k0 >> 4;
  const int pl = (k0 >> 1) & 7;
  const int pgrp = pl & 3, sel = pl >> 2;
  uint32_t* d = dst + ((size_t)(ntile * NKT + ktile) * 4 + pgrp) * BP2 +
                2 * nl + sel;
  d[0] = pkh(v.x, v.y);
  d[BP2] = pkh(v.z, v.w);
}

// ---------------------------------------------------------------------------
// fp16 GEMM (unchanged)
// ---------------------------------------------------------------------------
template <typename OutT>
__global__ __launch_bounds__(192) void hgemm(
    const uint32_t* __restrict__ At, const uint32_t* __restrict__ Bt,
    const float* __restrict__ bias, OutT* __restrict__ out, int Ncols) {
  __shared__ __align__(16) uint32_t Ab[2][AT2_WORDS];
  __shared__ __align__(16) uint32_t Bb[2][BT2_WORDS];

  const int tid = threadIdx.x;
  const int wid = tid >> 5, lane = tid & 31;
  const int wm = (wid & 1) * 64;
  const int wn = (wid >> 1) * 64;
  const int g = lane >> 2, tg = lane & 3;
  const int m0 = blockIdx.y * 128;
  const int n0 = blockIdx.x * 192;

  const uint32_t* gA = At + (size_t)blockIdx.y * NKT * AT2_WORDS;
  const uint32_t* gB = Bt + (size_t)blockIdx.x * NKT * BT2_WORDS;

  float acc[4][8][4];
#pragma unroll
  for (int mt = 0; mt < 4; mt++)
#pragma unroll
    for (int nt = 0; nt < 8; nt++)
#pragma unroll
      for (int r = 0; r < 4; r++) acc[mt][nt][r] = 0.f;

  auto copy_tile = [&](int kt, int buf) {
    const uint32_t* a = gA + (size_t)kt * AT2_WORDS;
    const uint32_t* bsrc = gB + (size_t)kt * BT2_WORDS;
    uint32_t sa = sptr(&Ab[buf][0]);
    uint32_t sb = sptr(&Bb[buf][0]);
    for (int i = tid * 4; i < AT2_WORDS; i += 192 * 4) cp16(sa + i * 4, a + i);
    for (int i = tid * 4; i < BT2_WORDS; i += 192 * 4) cp16(sb + i * 4, bsrc + i);
  };

  auto mma_tile = [&](int buf) {
    const uint32_t* Asb = Ab[buf];
    const uint32_t* Bsb = Bb[buf];
    uint32_t af[4][4], bf[8][2];
#pragma unroll
    for (int mt = 0; mt < 4; mt++) {
      const uint32_t* ap = Asb + tg * AP2 + wm + mt * 16 + 2 * g;
      ull v01 = *reinterpret_cast<const ull*>(ap);
      ull v23 = *reinterpret_cast<const ull*>(ap + 4 * AP2);
      af[mt][0] = (uint32_t)v01; af[mt][1] = (uint32_t)(v01 >> 32);
      af[mt][2] = (uint32_t)v23; af[mt][3] = (uint32_t)(v23 >> 32);
    }
#pragma unroll
    for (int nt = 0; nt < 8; nt++) {
      const uint32_t* bp = Bsb + tg * BP2 + 2 * (wn + nt * 8 + g);
      ull v = *reinterpret_cast<const ull*>(bp);
      bf[nt][0] = (uint32_t)v; bf[nt][1] = (uint32_t)(v >> 32);
    }
#pragma unroll
    for (int mt = 0; mt < 4; mt++)
#pragma unroll
      for (int nt = 0; nt < 8; nt++) MMA16(acc[mt][nt], af[mt], bf[nt]);
  };

  copy_tile(0, 0);
  cp_commit();

#pragma unroll 1
  for (int kt = 0; kt < NKT; kt += 2) {
    copy_tile(kt + 1, 1);
    cp_commit();
    cp_wait<1>();
    __syncthreads();
    mma_tile(0);
    __syncthreads();
    if (kt + 2 < NKT) {
      copy_tile(kt + 2, 0);
      cp_commit();
      cp_wait<1>();
    } else {
      cp_wait<0>();
    }
    __syncthreads();
    mma_tile(1);
    __syncthreads();
  }

#pragma unroll
  for (int mt = 0; mt < 4; mt++) {
#pragma unroll
    for (int nt = 0; nt < 8; nt++) {
      int row = m0 + wm + mt * 16 + g;
      int col = n0 + wn + nt * 8 + 2 * tg;
      float2 bv = *reinterpret_cast<const float2*>(bias + col);
      float x0 = acc[mt][nt][0] + bv.x, y0 = acc[mt][nt][1] + bv.y;
      float x1 = acc[mt][nt][2] + bv.x, y1 = acc[mt][nt][3] + bv.y;
      if constexpr (sizeof(OutT) == 2) {
        *reinterpret_cast<__half2*>(out + (size_t)row * Ncols + col) =
            __floats2half2_rn(x0, y0);
        *reinterpret_cast<__half2*>(out + (size_t)(row + 8) * Ncols + col) =
            __floats2half2_rn(x1, y1);
      } else {
        *reinterpret_cast<float2*>(out + (size_t)row * Ncols + col) =
            make_float2(x0, y0);
        *reinterpret_cast<float2*>(out + (size_t)(row + 8) * Ncols + col) =
            make_float2(x1, y1);
      }
    }
  }
}

// ---------------------------------------------------------------------------
// Depthwise 3x3 conv (unchanged)
// ---------------------------------------------------------------------------
#define CW 32
#define WB 8

__global__ __launch_bounds__(512, 2) void conv_kernel(
    const float* __restrict__ dw_w, const float* __restrict__ dw_b) {
  extern __shared__ __half sh[];
  const int tid = threadIdx.x;
  const int c0 = blockIdx.x * CW;
  const int b0 = blockIdx.y * WB;

#pragma unroll
  for (int rep = 0; rep < 5; rep++) {
    int i = tid + rep * 512;
    int w = i >> 8;
    int n = (i >> 2) & 63;
    int f = i & 3;
    int gw = b0 - 1 + w;
    uint4 v = make_uint4(0, 0, 0, 0);
    if ((unsigned)gw < (unsigned)B_TOT)
      v = *reinterpret_cast<const uint4*>(
          g_t + ((size_t)gw * 64 + n) * C3 + c0 + f * 8);
    *reinterpret_cast<uint4*>(sh + (w * 64 + n) * 32 + f * 8) = v;
  }
  __syncthreads();

  const int cp = tid & 15;
  const int wo = (tid >> 4) & 7;
  const int nh = tid >> 7;
  const int nst = nh << 4;
  const int gb = b0 + wo;
  const int c = c0 + 2 * cp;

  ull w2[9];
#pragma unroll
  for (int t = 0; t < 9; t++)
    w2[t] = pk(__ldg(dw_w + c * 9 + t), __ldg(dw_w + c * 9 + 9 + t));
  ull bia2 = pk(__ldg(dw_b + c), __ldg(dw_b + c + 1));

  const __half* rowp[3];
#pragma unroll
  for (int r = 0; r < 3; r++) rowp[r] = sh + ((wo + r) * 64) * 32 + 2 * cp;

  ull xm[3], x0[3];
#pragma unroll
  for (int r = 0; r < 3; r++) {
    xm[r] = (nst > 0) ? ld2h(rowp[r] + ((nst - 1) << 5)) : 0ull;
    x0[r] = ld2h(rowp[r] + (nst << 5));
  }
  __half* outp = g_c + ((size_t)gb * 64 + nst) * C3 + c;
#pragma unroll 4
  for (int n = nst; n < nst + 16; n++) {
    ull xp[3];
#pragma unroll
    for (int r = 0; r < 3; r++)
      xp[r] = (n + 1 < 64) ? ld2h(rowp[r] + ((n + 1) << 5)) : 0ull;
    ull s0 = mul2(xm[0], w2[0]);
    fma2(s0, x0[0], w2[1]); fma2(s0, xp[0], w2[2]);
    ull s1 = mul2(xm[1], w2[3]);
    fma2(s1, x0[1], w2[4]); fma2(s1, xp[1], w2[5]);
    ull s2 = mul2(xm[2], w2[6]);
    fma2(s2, x0[2], w2[7]); fma2(s2, xp[2], w2[8]);
    float2 sv = upk(add2(add2(s0, s1), add2(s2, bia2)));
    *reinterpret_cast<__half2*>(outp) = __floats2half2_rn(sv.x, sv.y);
    outp += C3;
#pragma unroll
    for (int r = 0; r < 3; r++) { xm[r] = x0[r]; x0[r] = xp[r]; }
  }
}

// ---------------------------------------------------------------------------
// Window attention per head-pair: grid (2048, 3), 256 threads, 3 CTAs/SM.
// Phase 1: fp16 MMA QK^T -> fp32 sS. Softmax: normalized P written fp16
// in-place over sS rows. PV: ldmatrix + fp16 MMA. V staged as raw fp16.
// ---------------------------------------------------------------------------
#define QP2 72
#define SSP 68
#define VPH 72          // V pitch in halves
#define SKW (4 * 136)
#define SK_OFF 2304
#define SS_OFF 4608
#define ATT_SMEM ((SS_OFF + 2 * 64 * SSP) * 4)

__global__ __launch_bounds__(256, 3) void attn_kernel(
    const float* __restrict__ mask, const float* __restrict__ rpb,
    const int* __restrict__ rel_idx) {
  extern __shared__ float sm[];
  uint32_t* sQ = reinterpret_cast<uint32_t*>(sm);
  uint32_t* sK = reinterpret_cast<uint32_t*>(sm) + SK_OFF;
  float* sS = sm + SS_OFF;
  __half* sP = reinterpret_cast<__half*>(sS);   // fp16 P, in-place (pitch 136)
  __half* sVh = reinterpret_cast<__half*>(sm);  // V fp16, overlays sQ/sK

  const int tid = threadIdx.x;
  const int b = blockIdx.x;
  const int h2 = blockIdx.y;
  const __half* win = g_c + (size_t)b * 64 * C3 + h2 * 64;

  // ---- phase 0: Q, K (fp16) -> packed-pair smem ---------------------------
#pragma unroll
  for (int rep = 0; rep < 4; rep++) {
    int i = tid + rep * 256;
    int qk = i >> 9;
    int j = i & 511;
    int row = j >> 3;
    int f = j & 7;
    int h = f >> 2;
    uint4 v = *reinterpret_cast<const uint4*>(
        win + (size_t)row * C3 + qk * 192 + f * 8);
    uint32_t wv[4] = {v.x, v.y, v.z, v.w};
    if (qk == 0) {
      int p0 = (f & 3) * 4;
      int perm = (row & ~15) + 2 * (row & 7) + ((row >> 3) & 1);
      uint32_t* dst = sQ + h * (16 * QP2) + p0 * QP2 + perm;
#pragma unroll
      for (int e = 0; e < 4; e++) dst[e * QP2] = wv[e];
    } else {
      int fq = f & 3;
      int kt = fq >> 1, sel = fq & 1;
      uint32_t* dst = sK + h * (2 * SKW) + kt * SKW + 2 * row + sel;
#pragma unroll
      for (int e = 0; e < 4; e++) dst[e * 136] = wv[e];
    }
  }
  __syncthreads();

  // ---- phase 1: S = (QK^T)*scale + bias + mask -> sS (fp32) ---------------
  {
    const int w = tid >> 5, lane = tid & 31;
    const int h = w >> 2, R = (w & 3) << 4;
    const int g = lane >> 2, tg = lane & 3;

    float acc[8][4];
#pragma unroll
    for (int nt = 0; nt < 8; nt++)
#pragma unroll
      for (int r = 0; r < 4; r++) acc[nt][r] = 0.f;

    const uint32_t* qb = sQ + h * (16 * QP2) + R + 2 * g;
    const uint32_t* kb0 = sK + h * (2 * SKW);
#pragma unroll
    for (int kt = 0; kt < 2; kt++) {
      uint32_t af[4];
      {
        const uint32_t* ap = qb + (8 * kt + tg) * QP2;
        ull v01 = *reinterpret_cast<const ull*>(ap);
        ull v23 = *reinterpret_cast<const ull*>(ap + 4 * QP2);
        af[0] = (uint32_t)v01; af[1] = (uint32_t)(v01 >> 32);
        af[2] = (uint32_t)v23; af[3] = (uint32_t)(v23 >> 32);
      }
#pragma unroll
      for (int nt = 0; nt < 8; nt++) {
        const uint32_t* bp = kb0 + kt * SKW + tg * 136 + 2 * (nt * 8 + g);
        ull v = *reinterpret_cast<const ull*>(bp);
        uint32_t bf[2] = {(uint32_t)v, (uint32_t)(v >> 32)};
        MMA16(acc[nt], af, bf);
      }
    }

    const int n0 = R + g, n1 = n0 + 8;
    const int gh = 2 * h2 + h;
    const float* mbase = mask + (size_t)(b & 63) * 4096;
#pragma unroll
    for (int nt = 0; nt < 8; nt++) {
      int m0 = nt * 8 + 2 * tg;
      int2 r0 = *reinterpret_cast<const int2*>(rel_idx + n0 * 64 + m0);
      int2 r1 = *reinterpret_cast<const int2*>(rel_idx + n1 * 64 + m0);
      float2 k0 = *reinterpret_cast<const float2*>(mbase + n0 * 64 + m0);
      float2 k1 = *reinterpret_cast<const float2*>(mbase + n1 * 64 + m0);
      float2 o0, o1;
      o0.x = fmaf(acc[nt][0], SCALE_F, __ldg(rpb + r0.x * 6 + gh) + k0.x);
      o0.y = fmaf(acc[nt][1], SCALE_F, __ldg(rpb + r0.y * 6 + gh) + k0.y);
      o1.x = fmaf(acc[nt][2], SCALE_F, __ldg(rpb + r1.x * 6 + gh) + k1.x);
      o1.y = fmaf(acc[nt][3], SCALE_F, __ldg(rpb + r1.y * 6 + gh) + k1.y);
      *reinterpret_cast<float2*>(sS + (h * 64 + n0) * SSP + m0) = o0;
      *reinterpret_cast<float2*>(sS + (h * 64 + n1) * SSP + m0) = o1;
    }
  }
  __syncthreads();

  // ---- phase 2a: stage FULL V (64 halves/row; 2 reps of 256) --------------
#pragma unroll
  for (int rep = 0; rep < 2; rep++) {
    int i = tid + rep * 256;     // 0..511
    int row = i >> 3;            // 0..63
    int f = i & 7;               // 8 chunks x 8 halves = 64 halves
    uint4 v = *reinterpret_cast<const uint4*>(
        win + (size_t)row * C3 + 384 + f * 8);
    *reinterpret_cast<uint4*>(sVh + row * VPH + f * 8) = v;
  }

  // ---- phase 2b: full-row softmax, normalized P -> fp16 in place ----------
  {
    const int h = tid >> 7;
    const int r = (tid >> 1) & 63;
    const int half = tid & 1;
    float* srow = sS + (h * 64 + r) * SSP + half * 32;

    float s[32];
#pragma unroll
    for (int jj = 0; jj < 8; jj++) {
      float4 v = *reinterpret_cast<const float4*>(srow + jj * 4);
      s[jj * 4 + 0] = v.x; s[jj * 4 + 1] = v.y;
      s[jj * 4 + 2] = v.z; s[jj * 4 + 3] = v.w;
    }

    float mx = -1e30f;
#pragma unroll
    for (int j = 0; j < 32; j++) mx = fmaxf(mx, s[j]);
    mx = fmaxf(mx, __shfl_xor_sync(0xffffffffu, mx, 1));
    float sum = 0.f;
#pragma unroll
    for (int j = 0; j < 32; j++) {
      s[j] = __expf(s[j] - mx);
      sum += s[j];
    }
    sum += __shfl_xor_sync(0xffffffffu, sum, 1);
    float inv = 1.f / sum;

    uint32_t* prow = reinterpret_cast<uint32_t*>(
        sP + (h * 64 + r) * (2 * SSP)) + half * 16;
#pragma unroll
    for (int j = 0; j < 16; j++)
      prow[j] = pkh(s[2 * j] * inv, s[2 * j + 1] * inv);
  }
  __syncthreads();

  // ---- phase 3: out = P @ V via ldmatrix + fp16 MMA -----------------------
  {
    const int w = tid >> 5, lane = tid & 31;
    const int h = w >> 2, R = (w & 3) << 4;
    const int g = lane >> 2, tg = lane & 3;

    float acc[4][4];
#pragma unroll
    for (int nt = 0; nt < 4; nt++)
#pragma unroll
      for (int r = 0; r < 4; r++) acc[nt][r] = 0.f;

    const int arow = R + (lane & 7) + (((lane >> 3) & 1) << 3);
    const int akoff = ((lane >> 4) & 1) << 3;
    const int vkrow = lane & 15;
    const int vnoff = h * 32 + (((lane >> 4) & 1) << 3);

#pragma unroll
    for (int kt = 0; kt < 4; kt++) {
      uint32_t a[4];
      ldm_x4(a, sptr(sP + (h * 64 + arow) * (2 * SSP) + kt * 16 + akoff));
#pragma unroll
      for (int dh = 0; dh < 2; dh++) {
        uint32_t bm[4];
        ldm_x4_t(bm, sptr(sVh + (kt * 16 + vkrow) * VPH + vnoff + dh * 16));
        MMA16(acc[dh * 2], a, (bm));
        uint32_t* b2 = bm + 2;
        MMA16(acc[dh * 2 + 1], a, b2);
      }
    }

    // epilogue: write fp16 tiled A-layout for proj GEMM
    const int row0 = R + g;
#pragma unroll
    for (int nt = 0; nt < 4; nt++) {
      int c = h * 32 + nt * 8 + 2 * tg;
      int gk = h2 * 64 + c;
      int ktile = gk >> 4;
      int p = (gk >> 1) & 7;
#pragma unroll
      for (int rr = 0; rr < 2; rr++) {
        int n_global = b * 64 + row0 + rr * 8;
        int mtile = n_global >> 7, mrow = n_global & 127;
        int perm = (mrow & ~15) + 2 * (mrow & 7) + ((mrow >> 3) & 1);
        g_ap[((size_t)(mtile * NKT + ktile) * 8 + p) * AP2 + perm] =
            pkh(acc[nt][rr * 2], acc[nt][rr * 2 + 1]);
      }
    }
  }
}

// ---------------------------------------------------------------------------
extern "C" void kernel_launch(void* const* d_in, const int* in_sizes, int n_in,
                              void* d_out, int out_size) {
  const float* x      = (const float*)d_in[0];
  const float* mask   = (const float*)d_in[1];
  const float* qkv_w  = (const float*)d_in[2];
  const float* qkv_b  = (const float*)d_in[3];
  const float* dw_w   = (const float*)d_in[4];
  const float* dw_b   = (const float*)d_in[5];
  const float* rpb    = (const float*)d_in[6];
  const int*   rel    = (const int*)d_in[7];
  const float* proj_w = (const float*)d_in[8];
  const float* proj_b = (const float*)d_in[9];
  float* out = (float*)d_out;

  __half* gt_ptr;
  uint32_t *gax, *gap, *gbq, *gbp;
  cudaGetSymbolAddress((void**)&gt_ptr, g_t);
  cudaGetSymbolAddress((void**)&gax, g_ax);
  cudaGetSymbolAddress((void**)&gap, g_ap);
  cudaGetSymbolAddress((void**)&gbq, g_bq);
  cudaGetSymbolAddress((void**)&gbp, g_bp);

  // 0) operand prep
  prep_a_kernel<<<dim3(48, 1024), 128>>>(x, gax);
  prep_w_kernel<<<dim3(48, 3), 192>>>(qkv_w, gbq);
  prep_w_kernel<<<dim3(48, 1), 192>>>(proj_w, gbp);

  // 1) QKV GEMM -> fp16 g_t
  hgemm<__half><<<dim3(3, 1024), 192>>>(gax, gbq, qkv_b, gt_ptr, C3);

  // 2) depthwise conv (fp16 in/out)
  const int conv_smem = 10 * 64 * CW * 2;
  cudaFuncSetAttribute(conv_kernel,
                       cudaFuncAttributeMaxDynamicSharedMemorySize, conv_smem);
  dim3 g2(C3 / CW, B_TOT / WB);
  conv_kernel<<<g2, 512, conv_smem>>>(dw_w, dw_b);

  // 3) window attention (per head-pair) -> g_ap fp16 tiled
  cudaFuncSetAttribute(attn_kernel,
                       cudaFuncAttributeMaxDynamicSharedMemorySize, ATT_SMEM);
  attn_kernel<<<dim3(B_TOT, 3), 256, ATT_SMEM>>>(mask, rpb, rel);

  // 4) projection GEMM -> fp32 out
  hgemm<float><<<dim3(1, 1024), 192>>>(gap, gbp, proj_b, out, C_DIM);
}

// round 12
// speedup vs baseline: 3.4706x; 1.0270x over previous
#include <cuda_runtime.h>
#include <cuda_fp16.h>
#include <cstdint>

#define B_TOT 2048
#define N_WIN 64
#define C_DIM 192
#define KDIM 192
#define C3 576
#define HEADS 6
#define HDIM 32
#define SCALE_F 0.17677669529663687f

// fp16 GEMM tile geometry (each 32-bit word packs a k-pair of halves)
#define AP2 136
#define BP2 392
#define AT2_WORDS (8 * AP2)
#define BT2_WORDS (4 * BP2)
#define NKT 12
#define STAGES 3

// scratch
__device__ __align__(16) __half g_t[(size_t)B_TOT * N_WIN * C3];
__device__ __align__(16) __half g_c[(size_t)B_TOT * N_WIN * C3];
__device__ __align__(16) uint32_t g_ax[(size_t)1024 * NKT * AT2_WORDS];
__device__ __align__(16) uint32_t g_ap[(size_t)1024 * NKT * AT2_WORDS];
__device__ __align__(16) uint32_t g_bq[3 * NKT * BT2_WORDS];
__device__ __align__(16) uint32_t g_bp[1 * NKT * BT2_WORDS];
__device__ __align__(16) __half g_cb[64 * HEADS * 4096];  // bias+mask table

// ------------------------------- helpers ----------------------------------
typedef unsigned long long ull;

__device__ __forceinline__ uint32_t pkh(float x, float y) {
  __half2 h = __floats2half2_rn(x, y);
  return *reinterpret_cast<uint32_t*>(&h);
}
__device__ __forceinline__ ull pk(float x, float y) {
  ull r;
  asm("mov.b64 %0, {%1, %2};" : "=l"(r) : "f"(x), "f"(y));
  return r;
}
__device__ __forceinline__ float2 upk(ull v) {
  float2 r;
  asm("mov.b64 {%0, %1}, %2;" : "=f"(r.x), "=f"(r.y) : "l"(v));
  return r;
}
__device__ __forceinline__ void fma2(ull& d, ull a, ull b) {
  asm("fma.rn.f32x2 %0, %1, %2, %3;" : "=l"(d) : "l"(a), "l"(b), "l"(d));
}
__device__ __forceinline__ ull mul2(ull a, ull b) {
  ull d;
  asm("mul.rn.f32x2 %0, %1, %2;" : "=l"(d) : "l"(a), "l"(b));
  return d;
}
__device__ __forceinline__ ull add2(ull a, ull b) {
  ull d;
  asm("add.rn.f32x2 %0, %1, %2;" : "=l"(d) : "l"(a), "l"(b));
  return d;
}
__device__ __forceinline__ ull ld2h(const __half* p) {
  __half2 h = *reinterpret_cast<const __half2*>(p);
  float2 f = __half22float2(h);
  return pk(f.x, f.y);
}
__device__ __forceinline__ void cp16(uint32_t s, const void* g) {
  asm volatile("cp.async.cg.shared.global [%0], [%1], 16;" ::"r"(s), "l"(g));
}
__device__ __forceinline__ void cp_commit() {
  asm volatile("cp.async.commit_group;");
}
template <int N>
__device__ __forceinline__ void cp_wait() {
  asm volatile("cp.async.wait_group %0;" ::"n"(N));
}
__device__ __forceinline__ uint32_t sptr(const void* p) {
  return (uint32_t)__cvta_generic_to_shared(p);
}
__device__ __forceinline__ void ldm_x4(uint32_t* r, uint32_t addr) {
  asm volatile(
      "ldmatrix.sync.aligned.m8n8.x4.shared.b16 {%0,%1,%2,%3}, [%4];"
      : "=r"(r[0]), "=r"(r[1]), "=r"(r[2]), "=r"(r[3]) : "r"(addr));
}
__device__ __forceinline__ void ldm_x4_t(uint32_t* r, uint32_t addr) {
  asm volatile(
      "ldmatrix.sync.aligned.m8n8.x4.trans.shared.b16 {%0,%1,%2,%3}, [%4];"
      : "=r"(r[0]), "=r"(r[1]), "=r"(r[2]), "=r"(r[3]) : "r"(addr));
}
#define MMA16(d, a, b)                                                       \
  asm volatile(                                                              \
      "mma.sync.aligned.m16n8k16.row.col.f32.f16.f16.f32 "                   \
      "{%0,%1,%2,%3}, {%4,%5,%6,%7}, {%8,%9}, {%0,%1,%2,%3};"                \
      : "+f"(d[0]), "+f"(d[1]), "+f"(d[2]), "+f"(d[3])                       \
      : "r"(a[0]), "r"(a[1]), "r"(a[2]), "r"(a[3]), "r"(b[0]), "r"(b[1]))

// ---------------------------------------------------------------------------
// Prep kernels
// ---------------------------------------------------------------------------
__global__ __launch_bounds__(128) void prep_a_kernel(
    const float* __restrict__ src, uint32_t* __restrict__ dst) {
  const int m = threadIdx.x;
  const int mtile = blockIdx.y;
  const int k0 = blockIdx.x * 4;
  float4 v = *reinterpret_cast<const float4*>(
      src + ((size_t)mtile * 128 + m) * KDIM + k0);
  const int ktile = k0 >> 4;
  const int pl = (k0 >> 1) & 7;
  const int perm = (m & ~15) + 2 * (m & 7) + ((m >> 3) & 1);
  uint32_t* d = dst + ((size_t)(mtile * NKT + ktile) * 8 + pl) * AP2 + perm;
  d[0] = pkh(v.x, v.y);
  d[AP2] = pkh(v.z, v.w);
}

__global__ __launch_bounds__(192) void prep_w_kernel(
    const float* __restrict__ src, uint32_t* __restrict__ dst) {
  const int nl = threadIdx.x;
  const int ntile = blockIdx.y;
  const int k0 = blockIdx.x * 4;
  float4 v = *reinterpret_cast<const float4*>(
      src + ((size_t)ntile * 192 + nl) * KDIM + k0);
  const int ktile = k0 >> 4;
  const int pl = (k0 >> 1) & 7;
  const int pgrp = pl & 3, sel = pl >> 2;
  uint32_t* d = dst + ((size_t)(ntile * NKT + ktile) * 4 + pgrp) * BP2 +
                2 * nl + sel;
  d[0] = pkh(v.x, v.y);
  d[BP2] = pkh(v.z, v.w);
}

// combined bias: g_cb[w][h][n][m] = rpb[rel[n][m]][h] + mask[w][n][m]
__global__ __launch_bounds__(256) void bias_prep_kernel(
    const float* __restrict__ mask, const float* __restrict__ rpb,
    const int* __restrict__ rel) {
  const int wi = blockIdx.x, h = blockIdx.y;
  const float* mrow = mask + (size_t)wi * 4096;
  __half* dst = g_cb + (((size_t)wi * HEADS + h) << 12);
  for (int i = threadIdx.x; i < 4096; i += 256)
    dst[i] = __float2half(__ldg(rpb + __ldg(rel + i) * 6 + h) + mrow[i]);
}

// ---------------------------------------------------------------------------
// fp16 GEMM: 3-stage cp.async pipeline, one __syncthreads per k-tile.
// ---------------------------------------------------------------------------
template <typename OutT>
__global__ __launch_bounds__(192) void hgemm(
    const uint32_t* __restrict__ At, const uint32_t* __restrict__ Bt,
    const float* __restrict__ bias, OutT* __restrict__ out, int Ncols) {
  __shared__ __align__(16) uint32_t Ab[STAGES][AT2_WORDS];
  __shared__ __align__(16) uint32_t Bb[STAGES][BT2_WORDS];

  const int tid = threadIdx.x;
  const int wid = tid >> 5, lane = tid & 31;
  const int wm = (wid & 1) * 64;
  const int wn = (wid >> 1) * 64;
  const int g = lane >> 2, tg = lane & 3;
  const int m0 = blockIdx.y * 128;
  const int n0 = blockIdx.x * 192;

  const uint32_t* gA = At + (size_t)blockIdx.y * NKT * AT2_WORDS;
  const uint32_t* gB = Bt + (size_t)blockIdx.x * NKT * BT2_WORDS;

  float acc[4][8][4];
#pragma unroll
  for (int mt = 0; mt < 4; mt++)
#pragma unroll
    for (int nt = 0; nt < 8; nt++)
#pragma unroll
      for (int r = 0; r < 4; r++) acc[mt][nt][r] = 0.f;

  auto copy_tile = [&](int kt, int buf) {
    const uint32_t* a = gA + (size_t)kt * AT2_WORDS;
    const uint32_t* bsrc = gB + (size_t)kt * BT2_WORDS;
    uint32_t sa = sptr(&Ab[buf][0]);
    uint32_t sb = sptr(&Bb[buf][0]);
    for (int i = tid * 4; i < AT2_WORDS; i += 192 * 4) cp16(sa + i * 4, a + i);
    for (int i = tid * 4; i < BT2_WORDS; i += 192 * 4) cp16(sb + i * 4, bsrc + i);
  };

  auto mma_tile = [&](int buf) {
    const uint32_t* Asb = Ab[buf];
    const uint32_t* Bsb = Bb[buf];
    uint32_t af[4][4], bf[8][2];
#pragma unroll
    for (int mt = 0; mt < 4; mt++) {
      const uint32_t* ap = Asb + tg * AP2 + wm + mt * 16 + 2 * g;
      ull v01 = *reinterpret_cast<const ull*>(ap);
      ull v23 = *reinterpret_cast<const ull*>(ap + 4 * AP2);
      af[mt][0] = (uint32_t)v01; af[mt][1] = (uint32_t)(v01 >> 32);
      af[mt][2] = (uint32_t)v23; af[mt][3] = (uint32_t)(v23 >> 32);
    }
#pragma unroll
    for (int nt = 0; nt < 8; nt++) {
      const uint32_t* bp = Bsb + tg * BP2 + 2 * (wn + nt * 8 + g);
      ull v = *reinterpret_cast<const ull*>(bp);
      bf[nt][0] = (uint32_t)v; bf[nt][1] = (uint32_t)(v >> 32);
    }
#pragma unroll
    for (int mt = 0; mt < 4; mt++)
#pragma unroll
      for (int nt = 0; nt < 8; nt++) MMA16(acc[mt][nt], af[mt], bf[nt]);
  };

  // prologue: tiles 0, 1 in flight
  copy_tile(0, 0);
  cp_commit();
  copy_tile(1, 1);
  cp_commit();

#pragma unroll 1
  for (int kt = 0; kt < NKT; kt++) {
    if (kt < NKT - 1) {
      cp_wait<1>();   // tile kt complete (kt+1 may still be in flight)
    } else {
      cp_wait<0>();
    }
    __syncthreads();  // everyone done with tile kt-1 -> its buffer is free
    if (kt + 2 < NKT) {
      copy_tile(kt + 2, (kt + 2) % STAGES);
      cp_commit();
    }
    mma_tile(kt % STAGES);
  }

#pragma unroll
  for (int mt = 0; mt < 4; mt++) {
#pragma unroll
    for (int nt = 0; nt < 8; nt++) {
      int row = m0 + wm + mt * 16 + g;
      int col = n0 + wn + nt * 8 + 2 * tg;
      float2 bv = *reinterpret_cast<const float2*>(bias + col);
      float x0 = acc[mt][nt][0] + bv.x, y0 = acc[mt][nt][1] + bv.y;
      float x1 = acc[mt][nt][2] + bv.x, y1 = acc[mt][nt][3] + bv.y;
      if constexpr (sizeof(OutT) == 2) {
        *reinterpret_cast<__half2*>(out + (size_t)row * Ncols + col) =
            __floats2half2_rn(x0, y0);
        *reinterpret_cast<__half2*>(out + (size_t)(row + 8) * Ncols + col) =
            __floats2half2_rn(x1, y1);
      } else {
        *reinterpret_cast<float2*>(out + (size_t)row * Ncols + col) =
            make_float2(x0, y0);
        *reinterpret_cast<float2*>(out + (size_t)(row + 8) * Ncols + col) =
            make_float2(x1, y1);
      }
    }
  }
}

// ---------------------------------------------------------------------------
// Depthwise 3x3 conv (unchanged)
// ---------------------------------------------------------------------------
#define CW 32
#define WB 8

__global__ __launch_bounds__(512, 2) void conv_kernel(
    const float* __restrict__ dw_w, const float* __restrict__ dw_b) {
  extern __shared__ __half sh[];
  const int tid = threadIdx.x;
  const int c0 = blockIdx.x * CW;
  const int b0 = blockIdx.y * WB;

#pragma unroll
  for (int rep = 0; rep < 5; rep++) {
    int i = tid + rep * 512;
    int w = i >> 8;
    int n = (i >> 2) & 63;
    int f = i & 3;
    int gw = b0 - 1 + w;
    uint4 v = make_uint4(0, 0, 0, 0);
    if ((unsigned)gw < (unsigned)B_TOT)
      v = *reinterpret_cast<const uint4*>(
          g_t + ((size_t)gw * 64 + n) * C3 + c0 + f * 8);
    *reinterpret_cast<uint4*>(sh + (w * 64 + n) * 32 + f * 8) = v;
  }
  __syncthreads();

  const int cp = tid & 15;
  const int wo = (tid >> 4) & 7;
  const int nh = tid >> 7;
  const int nst = nh << 4;
  const int gb = b0 + wo;
  const int c = c0 + 2 * cp;

  ull w2[9];
#pragma unroll
  for (int t = 0; t < 9; t++)
    w2[t] = pk(__ldg(dw_w + c * 9 + t), __ldg(dw_w + c * 9 + 9 + t));
  ull bia2 = pk(__ldg(dw_b + c), __ldg(dw_b + c + 1));

  const __half* rowp[3];
#pragma unroll
  for (int r = 0; r < 3; r++) rowp[r] = sh + ((wo + r) * 64) * 32 + 2 * cp;

  ull xm[3], x0[3];
#pragma unroll
  for (int r = 0; r < 3; r++) {
    xm[r] = (nst > 0) ? ld2h(rowp[r] + ((nst - 1) << 5)) : 0ull;
    x0[r] = ld2h(rowp[r] + (nst << 5));
  }
  __half* outp = g_c + ((size_t)gb * 64 + nst) * C3 + c;
#pragma unroll 4
  for (int n = nst; n < nst + 16; n++) {
    ull xp[3];
#pragma unroll
    for (int r = 0; r < 3; r++)
      xp[r] = (n + 1 < 64) ? ld2h(rowp[r] + ((n + 1) << 5)) : 0ull;
    ull s0 = mul2(xm[0], w2[0]);
    fma2(s0, x0[0], w2[1]); fma2(s0, xp[0], w2[2]);
    ull s1 = mul2(xm[1], w2[3]);
    fma2(s1, x0[1], w2[4]); fma2(s1, xp[1], w2[5]);
    ull s2 = mul2(xm[2], w2[6]);
    fma2(s2, x0[2], w2[7]); fma2(s2, xp[2], w2[8]);
    float2 sv = upk(add2(add2(s0, s1), add2(s2, bia2)));
    *reinterpret_cast<__half2*>(outp) = __floats2half2_rn(sv.x, sv.y);
    outp += C3;
#pragma unroll
    for (int r = 0; r < 3; r++) { xm[r] = x0[r]; x0[r] = xp[r]; }
  }
}

// ---------------------------------------------------------------------------
// Window attention per head-pair (round 11 structure; epilogue uses g_cb)
// ---------------------------------------------------------------------------
#define QP2 72
#define SSP 68
#define VPH 72
#define SKW (4 * 136)
#define SK_OFF 2304
#define SS_OFF 4608
#define ATT_SMEM ((SS_OFF + 2 * 64 * SSP) * 4)

__global__ __launch_bounds__(256, 3) void attn_kernel() {
  extern __shared__ float sm[];
  uint32_t* sQ = reinterpret_cast<uint32_t*>(sm);
  uint32_t* sK = reinterpret_cast<uint32_t*>(sm) + SK_OFF;
  float* sS = sm + SS_OFF;
  __half* sP = reinterpret_cast<__half*>(sS);
  __half* sVh = reinterpret_cast<__half*>(sm);

  const int tid = threadIdx.x;
  const int b = blockIdx.x;
  const int h2 = blockIdx.y;
  const __half* win = g_c + (size_t)b * 64 * C3 + h2 * 64;

  // ---- phase 0: Q, K -> packed-pair smem ----------------------------------
#pragma unroll
  for (int rep = 0; rep < 4; rep++) {
    int i = tid + rep * 256;
    int qk = i >> 9;
    int j = i & 511;
    int row = j >> 3;
    int f = j & 7;
    int h = f >> 2;
    uint4 v = *reinterpret_cast<const uint4*>(
        win + (size_t)row * C3 + qk * 192 + f * 8);
    uint32_t wv[4] = {v.x, v.y, v.z, v.w};
    if (qk == 0) {
      int p0 = (f & 3) * 4;
      int perm = (row & ~15) + 2 * (row & 7) + ((row >> 3) & 1);
      uint32_t* dst = sQ + h * (16 * QP2) + p0 * QP2 + perm;
#pragma unroll
      for (int e = 0; e < 4; e++) dst[e * QP2] = wv[e];
    } else {
      int fq = f & 3;
      int kt = fq >> 1, sel = fq & 1;
      uint32_t* dst = sK + h * (2 * SKW) + kt * SKW + 2 * row + sel;
#pragma unroll
      for (int e = 0; e < 4; e++) dst[e * 136] = wv[e];
    }
  }
  __syncthreads();

  // ---- phase 1: S = (QK^T)*scale + combined(bias+mask) -> sS --------------
  {
    const int w = tid >> 5, lane = tid & 31;
    const int h = w >> 2, R = (w & 3) << 4;
    const int g = lane >> 2, tg = lane & 3;

    float acc[8][4];
#pragma unroll
    for (int nt = 0; nt < 8; nt++)
#pragma unroll
      for (int r = 0; r < 4; r++) acc[nt][r] = 0.f;

    const uint32_t* qb = sQ + h * (16 * QP2) + R + 2 * g;
    const uint32_t* kb0 = sK + h * (2 * SKW);
#pragma unroll
    for (int kt = 0; kt < 2; kt++) {
      uint32_t af[4];
      {
        const uint32_t* ap = qb + (8 * kt + tg) * QP2;
        ull v01 = *reinterpret_cast<const ull*>(ap);
        ull v23 = *reinterpret_cast<const ull*>(ap + 4 * QP2);
        af[0] = (uint32_t)v01; af[1] = (uint32_t)(v01 >> 32);
        af[2] = (uint32_t)v23; af[3] = (uint32_t)(v23 >> 32);
      }
#pragma unroll
      for (int nt = 0; nt < 8; nt++) {
        const uint32_t* bp = kb0 + kt * SKW + tg * 136 + 2 * (nt * 8 + g);
        ull v = *reinterpret_cast<const ull*>(bp);
        uint32_t bf[2] = {(uint32_t)v, (uint32_t)(v >> 32)};
        MMA16(acc[nt], af, bf);
      }
    }

    const int n0 = R + g, n1 = n0 + 8;
    const int gh = 2 * h2 + h;
    const __half* cmb = g_cb + (((size_t)(b & 63) * HEADS + gh) << 12);
#pragma unroll
    for (int nt = 0; nt < 8; nt++) {
      int m0 = nt * 8 + 2 * tg;
      float2 k0 = __half22float2(
          *reinterpret_cast<const __half2*>(cmb + n0 * 64 + m0));
      float2 k1 = __half22float2(
          *reinterpret_cast<const __half2*>(cmb + n1 * 64 + m0));
      float2 o0, o1;
      o0.x = fmaf(acc[nt][0], SCALE_F, k0.x);
      o0.y = fmaf(acc[nt][1], SCALE_F, k0.y);
      o1.x = fmaf(acc[nt][2], SCALE_F, k1.x);
      o1.y = fmaf(acc[nt][3], SCALE_F, k1.y);
      *reinterpret_cast<float2*>(sS + (h * 64 + n0) * SSP + m0) = o0;
      *reinterpret_cast<float2*>(sS + (h * 64 + n1) * SSP + m0) = o1;
    }
  }
  __syncthreads();

  // ---- phase 2a: stage full V (fp16 raw) -----------------------------------
#pragma unroll
  for (int rep = 0; rep < 2; rep++) {
    int i = tid + rep * 256;
    int row = i >> 3;
    int f = i & 7;
    uint4 v = *reinterpret_cast<const uint4*>(
        win + (size_t)row * C3 + 384 + f * 8);
    *reinterpret_cast<uint4*>(sVh + row * VPH + f * 8) = v;
  }

  // ---- phase 2b: full-row softmax, normalized P -> fp16 in place ----------
  {
    const int h = tid >> 7;
    const int r = (tid >> 1) & 63;
    const int half = tid & 1;
    float* srow = sS + (h * 64 + r) * SSP + half * 32;

    float s[32];
#pragma unroll
    for (int jj = 0; jj < 8; jj++) {
      float4 v = *reinterpret_cast<const float4*>(srow + jj * 4);
      s[jj * 4 + 0] = v.x; s[jj * 4 + 1] = v.y;
      s[jj * 4 + 2] = v.z; s[jj * 4 + 3] = v.w;
    }

    float mx = -1e30f;
#pragma unroll
    for (int j = 0; j < 32; j++) mx = fmaxf(mx, s[j]);
    mx = fmaxf(mx, __shfl_xor_sync(0xffffffffu, mx, 1));
    float sum = 0.f;
#pragma unroll
    for (int j = 0; j < 32; j++) {
      s[j] = __expf(s[j] - mx);
      sum += s[j];
    }
    sum += __shfl_xor_sync(0xffffffffu, sum, 1);
    float inv = 1.f / sum;

    uint32_t* prow = reinterpret_cast<uint32_t*>(
        sP + (h * 64 + r) * (2 * SSP)) + half * 16;
#pragma unroll
    for (int j = 0; j < 16; j++)
      prow[j] = pkh(s[2 * j] * inv, s[2 * j + 1] * inv);
  }
  __syncthreads();

  // ---- phase 3: out = P @ V via ldmatrix + fp16 MMA -----------------------
  {
    const int w = tid >> 5, lane = tid & 31;
    const int h = w >> 2, R = (w & 3) << 4;
    const int g = lane >> 2, tg = lane & 3;

    float acc[4][4];
#pragma unroll
    for (int nt = 0; nt < 4; nt++)
#pragma unroll
      for (int r = 0; r < 4; r++) acc[nt][r] = 0.f;

    const int arow = R + (lane & 7) + (((lane >> 3) & 1) << 3);
    const int akoff = ((lane >> 4) & 1) << 3;
    const int vkrow = lane & 15;
    const int vnoff = h * 32 + (((lane >> 4) & 1) << 3);

#pragma unroll
    for (int kt = 0; kt < 4; kt++) {
      uint32_t a[4];
      ldm_x4(a, sptr(sP + (h * 64 + arow) * (2 * SSP) + kt * 16 + akoff));
#pragma unroll
      for (int dh = 0; dh < 2; dh++) {
        uint32_t bm[4];
        ldm_x4_t(bm, sptr(sVh + (kt * 16 + vkrow) * VPH + vnoff + dh * 16));
        MMA16(acc[dh * 2], a, (bm));
        uint32_t* b2 = bm + 2;
        MMA16(acc[dh * 2 + 1], a, b2);
      }
    }

    const int row0 = R + g;
#pragma unroll
    for (int nt = 0; nt < 4; nt++) {
      int c = h * 32 + nt * 8 + 2 * tg;
      int gk = h2 * 64 + c;
      int ktile = gk >> 4;
      int p = (gk >> 1) & 7;
#pragma unroll
      for (int rr = 0; rr < 2; rr++) {
        int n_global = b * 64 + row0 + rr * 8;
        int mtile = n_global >> 7, mrow = n_global & 127;
        int perm = (mrow & ~15) + 2 * (mrow & 7) + ((mrow >> 3) & 1);
        g_ap[((size_t)(mtile * NKT + ktile) * 8 + p) * AP2 + perm] =
            pkh(acc[nt][rr * 2], acc[nt][rr * 2 + 1]);
      }
    }
  }
}

// ---------------------------------------------------------------------------
extern "C" void kernel_launch(void* const* d_in, const int* in_sizes, int n_in,
                              void* d_out, int out_size) {
  const float* x      = (const float*)d_in[0];
  const float* mask   = (const float*)d_in[1];
  const float* qkv_w  = (const float*)d_in[2];
  const float* qkv_b  = (const float*)d_in[3];
  const float* dw_w   = (const float*)d_in[4];
  const float* dw_b   = (const float*)d_in[5];
  const float* rpb    = (const float*)d_in[6];
  const int*   rel    = (const int*)d_in[7];
  const float* proj_w = (const float*)d_in[8];
  const float* proj_b = (const float*)d_in[9];
  float* out = (float*)d_out;

  __half* gt_ptr;
  uint32_t *gax, *gap, *gbq, *gbp;
  cudaGetSymbolAddress((void**)&gt_ptr, g_t);
  cudaGetSymbolAddress((void**)&gax, g_ax);
  cudaGetSymbolAddress((void**)&gap, g_ap);
  cudaGetSymbolAddress((void**)&gbq, g_bq);
  cudaGetSymbolAddress((void**)&gbp, g_bp);

  // 0) operand + bias-table prep
  prep_a_kernel<<<dim3(48, 1024), 128>>>(x, gax);
  prep_w_kernel<<<dim3(48, 3), 192>>>(qkv_w, gbq);
  prep_w_kernel<<<dim3(48, 1), 192>>>(proj_w, gbp);
  bias_prep_kernel<<<dim3(64, HEADS), 256>>>(mask, rpb, rel);

  // 1) QKV GEMM -> fp16 g_t
  hgemm<__half><<<dim3(3, 1024), 192>>>(gax, gbq, qkv_b, gt_ptr, C3);

  // 2) depthwise conv (fp16 in/out)
  const int conv_smem = 10 * 64 * CW * 2;
  cudaFuncSetAttribute(conv_kernel,
                       cudaFuncAttributeMaxDynamicSharedMemorySize, conv_smem);
  dim3 g2(C3 / CW, B_TOT / WB);
  conv_kernel<<<g2, 512, conv_smem>>>(dw_w, dw_b);

  // 3) window attention (per head-pair) -> g_ap fp16 tiled
  cudaFuncSetAttribute(attn_kernel,
                       cudaFuncAttributeMaxDynamicSharedMemorySize, ATT_SMEM);
  attn_kernel<<<dim3(B_TOT, 3), 256, ATT_SMEM>>>();

  // 4) projection GEMM -> fp32 out
  hgemm<float><<<dim3(1, 1024), 192>>>(gap, gbp, proj_b, out, C_DIM);
}